// round 6
// baseline (speedup 1.0000x reference)
#include <cuda_runtime.h>
#include <cuda_bf16.h>
#include <cstdint>
#include <math.h>

#define B_   2
#define T_   2048
#define C_   1024
#define NH_  16
#define HS_  64
#define WIN_ 256

// ---------------------------------------------------------------------------
// Scratch (__device__ globals; no allocation allowed)
// ---------------------------------------------------------------------------
__device__ __nv_bfloat16 g_qkvh[(size_t)B_ * T_ * 3 * C_];   // split qkv hi
__device__ __nv_bfloat16 g_qkvl[(size_t)B_ * T_ * 3 * C_];   // split qkv lo
__device__ __nv_bfloat16 g_xh[(size_t)B_ * T_ * C_];
__device__ __nv_bfloat16 g_xl[(size_t)B_ * T_ * C_];
__device__ __nv_bfloat16 g_yh[(size_t)B_ * T_ * C_];
__device__ __nv_bfloat16 g_yl[(size_t)B_ * T_ * C_];
__device__ __nv_bfloat16 g_wah[(size_t)3 * C_ * C_];         // W_attn^T [3C, C]
__device__ __nv_bfloat16 g_wal[(size_t)3 * C_ * C_];
__device__ __nv_bfloat16 g_wph[(size_t)C_ * C_];             // W_proj^T [C, C]
__device__ __nv_bfloat16 g_wpl[(size_t)C_ * C_];

// ---------------------------------------------------------------------------
// mma.sync / ldmatrix / cp.async helpers
// ---------------------------------------------------------------------------
__device__ __forceinline__ uint32_t smem_to_u32(const void* smem_ptr) {
    uint32_t addr;
    asm("{ .reg .u64 tmp; cvta.to.shared.u64 tmp, %1; cvt.u32.u64 %0, tmp; }"
        : "=r"(addr) : "l"(smem_ptr));
    return addr;
}
__device__ __forceinline__ void cp16(uint32_t saddr, const void* g) {
    asm volatile("cp.async.cg.shared.global [%0], [%1], 16;" :: "r"(saddr), "l"(g));
}
__device__ __forceinline__ void cp_commit() {
    asm volatile("cp.async.commit_group;" ::: "memory");
}
template <int N>
__device__ __forceinline__ void cp_wait() {
    asm volatile("cp.async.wait_group %0;" :: "n"(N) : "memory");
}
__device__ __forceinline__ void ldm4(uint32_t* r, uint32_t addr) {
    asm volatile("ldmatrix.sync.aligned.m8n8.x4.shared.b16 {%0,%1,%2,%3}, [%4];"
        : "=r"(r[0]), "=r"(r[1]), "=r"(r[2]), "=r"(r[3]) : "r"(addr));
}
__device__ __forceinline__ void ldm4t(uint32_t* r, uint32_t addr) {
    asm volatile("ldmatrix.sync.aligned.m8n8.x4.trans.shared.b16 {%0,%1,%2,%3}, [%4];"
        : "=r"(r[0]), "=r"(r[1]), "=r"(r[2]), "=r"(r[3]) : "r"(addr));
}
__device__ __forceinline__ void mma_bf16(float* c, const uint32_t* a, const uint32_t* b) {
    asm volatile("mma.sync.aligned.m16n8k16.row.col.f32.bf16.bf16.f32 "
        "{%0,%1,%2,%3}, {%4,%5,%6,%7}, {%8,%9}, {%0,%1,%2,%3};"
        : "+f"(c[0]), "+f"(c[1]), "+f"(c[2]), "+f"(c[3])
        : "r"(a[0]), "r"(a[1]), "r"(a[2]), "r"(a[3]), "r"(b[0]), "r"(b[1]));
}
__device__ __forceinline__ uint32_t pack_bf16(float lo, float hi) {
    __nv_bfloat162 t = __floats2bfloat162_rn(lo, hi);
    return *reinterpret_cast<uint32_t*>(&t);
}
__device__ __forceinline__ void store_split_pair(__nv_bfloat16* Ch, __nv_bfloat16* Cl,
                                                 size_t idx, float v0, float v1) {
    __nv_bfloat162 h = __floats2bfloat162_rn(v0, v1);
    __nv_bfloat162 l = __floats2bfloat162_rn(v0 - __bfloat162float(h.x),
                                             v1 - __bfloat162float(h.y));
    *reinterpret_cast<__nv_bfloat162*>(Ch + idx) = h;
    *reinterpret_cast<__nv_bfloat162*>(Cl + idx) = l;
}

// ---------------------------------------------------------------------------
// Split-precision conversion kernels
// ---------------------------------------------------------------------------
__global__ __launch_bounds__(256) void split_convert(const float* __restrict__ in,
                                                     __nv_bfloat16* __restrict__ oh,
                                                     __nv_bfloat16* __restrict__ ol,
                                                     int n2)
{
    int i = blockIdx.x * blockDim.x + threadIdx.x;
    if (i >= n2) return;
    float2 v = reinterpret_cast<const float2*>(in)[i];
    __nv_bfloat16 hx = __float2bfloat16(v.x);
    __nv_bfloat16 hy = __float2bfloat16(v.y);
    __nv_bfloat162 th; th.x = hx; th.y = hy;
    __nv_bfloat162 tl;
    tl.x = __float2bfloat16(v.x - __bfloat162float(hx));
    tl.y = __float2bfloat16(v.y - __bfloat162float(hy));
    reinterpret_cast<__nv_bfloat162*>(oh)[i] = th;
    reinterpret_cast<__nv_bfloat162*>(ol)[i] = tl;
}

// in: [K,N] fp32 row-major -> out hi/lo: [N,K] bf16 (transposed, K-major)
__global__ __launch_bounds__(256) void transpose_split(const float* __restrict__ in,
                                                       __nv_bfloat16* __restrict__ oh,
                                                       __nv_bfloat16* __restrict__ ol,
                                                       int K, int N)
{
    __shared__ float t[32][33];
    const int nt = blockIdx.x * 32;
    const int kt = blockIdx.y * 32;
    const int tx = threadIdx.x & 31;
    const int ty = threadIdx.x >> 5;
#pragma unroll
    for (int j = 0; j < 4; j++) {
        int k = kt + ty + j * 8;
        t[ty + j * 8][tx] = in[(size_t)k * N + nt + tx];
    }
    __syncthreads();
#pragma unroll
    for (int j = 0; j < 4; j++) {
        int n = nt + ty + j * 8;
        int k = kt + tx;
        float v = t[tx][ty + j * 8];
        __nv_bfloat16 h = __float2bfloat16(v);
        oh[(size_t)n * K + k] = h;
        ol[(size_t)n * K + k] = __float2bfloat16(v - __bfloat162float(h));
    }
}

// ---------------------------------------------------------------------------
// Split-bf16 GEMM (HMMA), round-3 geometry + single sync per chunk.
// CTA 128x128, BK=32, 8 warps (2M x 4N), warp tile 64x32, 2-stage cp.async,
// 2 CTAs/SM. C = (Ah+Al)@(Bh+Bl)^T, 3-product, fp32 accum.
// SPLIT_OUT=1 -> bf16 hi/lo output, else fp32.
// ---------------------------------------------------------------------------
#define BM 128
#define BN 128
#define BKC 32
#define LDA 40
#define TILE_BYTES (128 * LDA * 2)           // 10240
#define OFF_AH 0
#define OFF_AL (TILE_BYTES)
#define OFF_BH (2 * TILE_BYTES)
#define OFF_BL (3 * TILE_BYTES)
#define STAGE_BYTES (4 * TILE_BYTES)         // 40960
#define GEMM_SMEM (2 * STAGE_BYTES)          // 81920

template <int SPLIT_OUT>
__global__ __launch_bounds__(256, 2) void gemm_mma(
    const __nv_bfloat16* __restrict__ Ah, const __nv_bfloat16* __restrict__ Al,
    const __nv_bfloat16* __restrict__ Bh, const __nv_bfloat16* __restrict__ Bl,
    float* __restrict__ C, __nv_bfloat16* __restrict__ Ch,
    __nv_bfloat16* __restrict__ Cl, int M, int N, int K)
{
    extern __shared__ char smem[];
    const uint32_t sbase = smem_to_u32(smem);

    const int tid  = threadIdx.x;
    const int lane = tid & 31;
    const int wid  = tid >> 5;
    const int warpRow = wid & 1;
    const int warpCol = wid >> 1;
    const int m0 = blockIdx.y * BM;
    const int n0 = blockIdx.x * BN;
    const int NC = K / BKC;

    const int v0 = tid, v1 = tid + 256;
    const int r0 = v0 >> 2, s0 = v0 & 3;
    const int r1 = v1 >> 2, s1 = v1 & 3;
    const uint32_t so0 = (uint32_t)(r0 * LDA + s0 * 8) * 2;
    const uint32_t so1 = (uint32_t)(r1 * LDA + s1 * 8) * 2;

    float acc[4][4][4];
#pragma unroll
    for (int mt = 0; mt < 4; mt++)
#pragma unroll
        for (int nt = 0; nt < 4; nt++)
#pragma unroll
            for (int e = 0; e < 4; e++) acc[mt][nt][e] = 0.0f;

    const uint32_t a_row = (uint32_t)(warpRow * 64 + (lane & 15));
    const uint32_t a_kof = (uint32_t)((lane >> 4) << 3);
    const uint32_t b_row = (uint32_t)(warpCol * 32 + (lane & 7) + ((lane & 16) >> 1));
    const uint32_t b_kof = (uint32_t)(lane & 8);

    auto load_stage = [&](int stg, int kk) {
        const uint32_t sb = sbase + stg * STAGE_BYTES;
        const size_t ga0 = (size_t)(m0 + r0) * K + kk + s0 * 8;
        const size_t ga1 = (size_t)(m0 + r1) * K + kk + s1 * 8;
        const size_t gb0 = (size_t)(n0 + r0) * K + kk + s0 * 8;
        const size_t gb1 = (size_t)(n0 + r1) * K + kk + s1 * 8;
        cp16(sb + OFF_AH + so0, Ah + ga0);
        cp16(sb + OFF_AH + so1, Ah + ga1);
        cp16(sb + OFF_AL + so0, Al + ga0);
        cp16(sb + OFF_AL + so1, Al + ga1);
        cp16(sb + OFF_BH + so0, Bh + gb0);
        cp16(sb + OFF_BH + so1, Bh + gb1);
        cp16(sb + OFF_BL + so0, Bl + gb0);
        cp16(sb + OFF_BL + so1, Bl + gb1);
        cp_commit();
    };

    load_stage(0, 0);

    for (int c = 0; c < NC; c++) {
        // Single barrier per chunk: guarantees every warp finished computing
        // chunk c-1 (which used buffer (c+1)&1) before we overwrite it below.
        __syncthreads();
        if (c + 1 < NC) load_stage((c + 1) & 1, (c + 1) * BKC);
        else            cp_commit();   // empty group keeps wait<1> semantics
        cp_wait<1>();                  // stage c resident (only c+1 pending)

        const uint32_t sb = sbase + (c & 1) * STAGE_BYTES;

#pragma unroll
        for (int ks = 0; ks < 2; ks++) {
            const uint32_t akc = (uint32_t)(ks * 16) + a_kof;
            const uint32_t bkc = (uint32_t)(ks * 16) + b_kof;

            uint32_t fAh[4][4], fAl[4][4];
#pragma unroll
            for (int mt = 0; mt < 4; mt++) {
                const uint32_t off = ((a_row + mt * 16) * LDA + akc) * 2;
                ldm4(fAh[mt], sb + OFF_AH + off);
                ldm4(fAl[mt], sb + OFF_AL + off);
            }
            uint32_t fBh[2][4], fBl[2][4];
#pragma unroll
            for (int g = 0; g < 2; g++) {
                const uint32_t off = ((b_row + g * 16) * LDA + bkc) * 2;
                ldm4(fBh[g], sb + OFF_BH + off);
                ldm4(fBl[g], sb + OFF_BL + off);
            }

#pragma unroll
            for (int mt = 0; mt < 4; mt++) {
#pragma unroll
                for (int nt = 0; nt < 4; nt++) {
                    const uint32_t* bh = &fBh[nt >> 1][(nt & 1) * 2];
                    const uint32_t* bl = &fBl[nt >> 1][(nt & 1) * 2];
                    mma_bf16(acc[mt][nt], fAh[mt], bh);
                    mma_bf16(acc[mt][nt], fAh[mt], bl);
                    mma_bf16(acc[mt][nt], fAl[mt], bh);
                }
            }
        }
    }

    const int erow = m0 + warpRow * 64 + (lane >> 2);
    const int ecol = n0 + warpCol * 32 + (lane & 3) * 2;
#pragma unroll
    for (int mt = 0; mt < 4; mt++) {
#pragma unroll
        for (int nt = 0; nt < 4; nt++) {
            const size_t i0 = (size_t)(erow + mt * 16) * N + ecol + nt * 8;
            const size_t i1 = (size_t)(erow + mt * 16 + 8) * N + ecol + nt * 8;
            if (SPLIT_OUT) {
                store_split_pair(Ch, Cl, i0, acc[mt][nt][0], acc[mt][nt][1]);
                store_split_pair(Ch, Cl, i1, acc[mt][nt][2], acc[mt][nt][3]);
            } else {
                *reinterpret_cast<float2*>(C + i0) = make_float2(acc[mt][nt][0], acc[mt][nt][1]);
                *reinterpret_cast<float2*>(C + i1) = make_float2(acc[mt][nt][2], acc[mt][nt][3]);
            }
        }
    }
}

// ---------------------------------------------------------------------------
// Tensor-core SWA flash attention; consumes pre-split qkv hi/lo, emits split y.
// (unchanged from round 5 — proven)
// ---------------------------------------------------------------------------
#define SWA_LDT 72
#define SWA_TILE_B (64 * SWA_LDT * 2)     // 9216
#define SWA_SMEM (6 * SWA_TILE_B)         // 55296

__global__ __launch_bounds__(128, 3) void swa_mma(const __nv_bfloat16* __restrict__ qh,
                                                  const __nv_bfloat16* __restrict__ ql,
                                                  __nv_bfloat16* __restrict__ yh,
                                                  __nv_bfloat16* __restrict__ yl)
{
    extern __shared__ char sm[];
    const uint32_t sb = smem_to_u32(sm);
    const uint32_t QH = sb;
    const uint32_t QL = sb + 1 * SWA_TILE_B;
    const uint32_t KH = sb + 2 * SWA_TILE_B;
    const uint32_t KL = sb + 3 * SWA_TILE_B;
    const uint32_t VH = sb + 4 * SWA_TILE_B;
    const uint32_t VL = sb + 5 * SWA_TILE_B;

    const int qt   = blockIdx.x;
    const int h    = blockIdx.y;
    const int b    = blockIdx.z;
    const int tid  = threadIdx.x;
    const int lane = tid & 31;
    const int w    = tid >> 5;

    const size_t st = 3 * C_;
    const __nv_bfloat16* baseh = qh + (size_t)b * T_ * st + (size_t)h * HS_;
    const __nv_bfloat16* basel = ql + (size_t)b * T_ * st + (size_t)h * HS_;

    for (int it = tid; it < 512; it += 128) {
        const int r   = it >> 3;
        const int sgo = (it & 7) * 8;
        const size_t g = (size_t)(qt * 64 + r) * st + sgo;
        const uint32_t off = (uint32_t)(r * SWA_LDT + sgo) * 2;
        *reinterpret_cast<uint4*>(sm + (QH - sb) + off) =
            *reinterpret_cast<const uint4*>(baseh + g);
        *reinterpret_cast<uint4*>(sm + (QL - sb) + off) =
            *reinterpret_cast<const uint4*>(basel + g);
    }

    float o[8][4];
#pragma unroll
    for (int nt = 0; nt < 8; nt++)
#pragma unroll
        for (int e = 0; e < 4; e++) o[nt][e] = 0.0f;
    float mrow[2] = {-1e30f, -1e30f};
    float lrow[2] = {0.0f, 0.0f};

    const int ig0 = qt * 64 + w * 16 + (lane >> 2);
    const int ig1 = ig0 + 8;
    const int lo_q  = qt * 64 - (WIN_ - 1);
    const int kt_lo = lo_q > 0 ? (lo_q >> 6) : 0;

    for (int kt = kt_lo; kt <= qt; kt++) {
        __syncthreads();
        for (int it = tid; it < 512; it += 128) {
            const int r   = it >> 3;
            const int sgo = (it & 7) * 8;
            const size_t g = (size_t)(kt * 64 + r) * st + sgo;
            const uint32_t off = (uint32_t)(r * SWA_LDT + sgo) * 2;
            *reinterpret_cast<uint4*>(sm + (KH - sb) + off) =
                *reinterpret_cast<const uint4*>(baseh + C_ + g);
            *reinterpret_cast<uint4*>(sm + (KL - sb) + off) =
                *reinterpret_cast<const uint4*>(basel + C_ + g);
            *reinterpret_cast<uint4*>(sm + (VH - sb) + off) =
                *reinterpret_cast<const uint4*>(baseh + 2 * C_ + g);
            *reinterpret_cast<uint4*>(sm + (VL - sb) + off) =
                *reinterpret_cast<const uint4*>(basel + 2 * C_ + g);
        }
        __syncthreads();

        float s[8][4];
#pragma unroll
        for (int nt = 0; nt < 8; nt++)
#pragma unroll
            for (int e = 0; e < 4; e++) s[nt][e] = 0.0f;

#pragma unroll
        for (int ks = 0; ks < 4; ks++) {
            uint32_t qfh[4], qfl[4];
            const uint32_t aoff =
                (uint32_t)((w * 16 + (lane & 15)) * SWA_LDT + ks * 16 + ((lane >> 4) << 3)) * 2;
            ldm4(qfh, QH + aoff);
            ldm4(qfl, QL + aoff);
#pragma unroll
            for (int jc = 0; jc < 4; jc++) {
                uint32_t kh[4], kl[4];
                const uint32_t boff =
                    (uint32_t)((jc * 16 + (lane & 7) + ((lane & 16) >> 1)) * SWA_LDT
                               + ks * 16 + (lane & 8)) * 2;
                ldm4(kh, KH + boff);
                ldm4(kl, KL + boff);
                mma_bf16(s[jc * 2],     qfh, kh);
                mma_bf16(s[jc * 2],     qfh, kl);
                mma_bf16(s[jc * 2],     qfl, kh);
                mma_bf16(s[jc * 2 + 1], qfh, kh + 2);
                mma_bf16(s[jc * 2 + 1], qfh, kl + 2);
                mma_bf16(s[jc * 2 + 1], qfl, kh + 2);
            }
        }

        const float sc = 0.125f;
        const int jb = kt * 64 + 2 * (lane & 3);
        float tmax0 = -1e30f, tmax1 = -1e30f;
#pragma unroll
        for (int nt = 0; nt < 8; nt++) {
            const int j0 = jb + nt * 8, j1 = j0 + 1;
            const bool v00 = (j0 <= ig0) && (ig0 - j0 < WIN_);
            const bool v01 = (j1 <= ig0) && (ig0 - j1 < WIN_);
            const bool v10 = (j0 <= ig1) && (ig1 - j0 < WIN_);
            const bool v11 = (j1 <= ig1) && (ig1 - j1 < WIN_);
            s[nt][0] *= sc; s[nt][1] *= sc; s[nt][2] *= sc; s[nt][3] *= sc;
            if (v00) tmax0 = fmaxf(tmax0, s[nt][0]);
            if (v01) tmax0 = fmaxf(tmax0, s[nt][1]);
            if (v10) tmax1 = fmaxf(tmax1, s[nt][2]);
            if (v11) tmax1 = fmaxf(tmax1, s[nt][3]);
        }
        tmax0 = fmaxf(tmax0, __shfl_xor_sync(0xffffffffu, tmax0, 1));
        tmax0 = fmaxf(tmax0, __shfl_xor_sync(0xffffffffu, tmax0, 2));
        tmax1 = fmaxf(tmax1, __shfl_xor_sync(0xffffffffu, tmax1, 1));
        tmax1 = fmaxf(tmax1, __shfl_xor_sync(0xffffffffu, tmax1, 2));

        const float mn0 = fmaxf(mrow[0], tmax0);
        const float mn1 = fmaxf(mrow[1], tmax1);
        const float es0 = __expf(mrow[0] - mn0);
        const float es1 = __expf(mrow[1] - mn1);
        mrow[0] = mn0; mrow[1] = mn1;

        uint32_t ph01[8], ph23[8], pl01[8], pl23[8];
        float ps0 = 0.0f, ps1 = 0.0f;
#pragma unroll
        for (int nt = 0; nt < 8; nt++) {
            const int j0 = jb + nt * 8, j1 = j0 + 1;
            const bool v00 = (j0 <= ig0) && (ig0 - j0 < WIN_);
            const bool v01 = (j1 <= ig0) && (ig0 - j1 < WIN_);
            const bool v10 = (j0 <= ig1) && (ig1 - j0 < WIN_);
            const bool v11 = (j1 <= ig1) && (ig1 - j1 < WIN_);
            const float p00 = v00 ? __expf(s[nt][0] - mn0) : 0.0f;
            const float p01 = v01 ? __expf(s[nt][1] - mn0) : 0.0f;
            const float p10 = v10 ? __expf(s[nt][2] - mn1) : 0.0f;
            const float p11 = v11 ? __expf(s[nt][3] - mn1) : 0.0f;
            ps0 += p00 + p01;
            ps1 += p10 + p11;
            __nv_bfloat162 h01 = __floats2bfloat162_rn(p00, p01);
            __nv_bfloat162 h23 = __floats2bfloat162_rn(p10, p11);
            ph01[nt] = *reinterpret_cast<uint32_t*>(&h01);
            ph23[nt] = *reinterpret_cast<uint32_t*>(&h23);
            pl01[nt] = pack_bf16(p00 - __bfloat162float(h01.x),
                                 p01 - __bfloat162float(h01.y));
            pl23[nt] = pack_bf16(p10 - __bfloat162float(h23.x),
                                 p11 - __bfloat162float(h23.y));
        }
        ps0 += __shfl_xor_sync(0xffffffffu, ps0, 1);
        ps0 += __shfl_xor_sync(0xffffffffu, ps0, 2);
        ps1 += __shfl_xor_sync(0xffffffffu, ps1, 1);
        ps1 += __shfl_xor_sync(0xffffffffu, ps1, 2);
        lrow[0] = lrow[0] * es0 + ps0;
        lrow[1] = lrow[1] * es1 + ps1;
#pragma unroll
        for (int nt = 0; nt < 8; nt++) {
            o[nt][0] *= es0; o[nt][1] *= es0;
            o[nt][2] *= es1; o[nt][3] *= es1;
        }

#pragma unroll
        for (int kj = 0; kj < 4; kj++) {
            uint32_t ah[4] = {ph01[2 * kj], ph23[2 * kj], ph01[2 * kj + 1], ph23[2 * kj + 1]};
            uint32_t al[4] = {pl01[2 * kj], pl23[2 * kj], pl01[2 * kj + 1], pl23[2 * kj + 1]};
#pragma unroll
            for (int dc = 0; dc < 4; dc++) {
                uint32_t vh[4], vl[4];
                const uint32_t voff =
                    (uint32_t)((kj * 16 + (lane & 15)) * SWA_LDT
                               + dc * 16 + ((lane >> 4) << 3)) * 2;
                ldm4t(vh, VH + voff);
                ldm4t(vl, VL + voff);
                mma_bf16(o[dc * 2],     ah, vh);
                mma_bf16(o[dc * 2],     ah, vl);
                mma_bf16(o[dc * 2],     al, vh);
                mma_bf16(o[dc * 2 + 1], ah, vh + 2);
                mma_bf16(o[dc * 2 + 1], ah, vl + 2);
                mma_bf16(o[dc * 2 + 1], al, vh + 2);
            }
        }
    }

    const float inv0 = 1.0f / lrow[0];
    const float inv1 = 1.0f / lrow[1];
    const size_t row0 = (size_t)b * T_ + qt * 64 + w * 16 + (lane >> 2);
    const int    colb = h * HS_ + 2 * (lane & 3);
#pragma unroll
    for (int nt = 0; nt < 8; nt++) {
        store_split_pair(yh, yl, row0 * C_ + colb + nt * 8,
                         o[nt][0] * inv0, o[nt][1] * inv0);
        store_split_pair(yh, yl, (row0 + 8) * C_ + colb + nt * 8,
                         o[nt][2] * inv1, o[nt][3] * inv1);
    }
}

// ---------------------------------------------------------------------------
extern "C" void kernel_launch(void* const* d_in, const int* in_sizes, int n_in,
                              void* d_out, int out_size)
{
    const float* x      = (const float*)d_in[0];
    const float* W_attn = (const float*)d_in[1];
    const float* W_proj = (const float*)d_in[2];
    float* out = (float*)d_out;

    __nv_bfloat16 *qkvh, *qkvl, *xh, *xl, *yh, *yl, *wah, *wal, *wph, *wpl;
    cudaGetSymbolAddress((void**)&qkvh, g_qkvh);
    cudaGetSymbolAddress((void**)&qkvl, g_qkvl);
    cudaGetSymbolAddress((void**)&xh,  g_xh);
    cudaGetSymbolAddress((void**)&xl,  g_xl);
    cudaGetSymbolAddress((void**)&yh,  g_yh);
    cudaGetSymbolAddress((void**)&yl,  g_yl);
    cudaGetSymbolAddress((void**)&wah, g_wah);
    cudaGetSymbolAddress((void**)&wal, g_wal);
    cudaGetSymbolAddress((void**)&wph, g_wph);
    cudaGetSymbolAddress((void**)&wpl, g_wpl);

    cudaFuncSetAttribute(gemm_mma<0>, cudaFuncAttributeMaxDynamicSharedMemorySize,
                         GEMM_SMEM);
    cudaFuncSetAttribute(gemm_mma<1>, cudaFuncAttributeMaxDynamicSharedMemorySize,
                         GEMM_SMEM);
    cudaFuncSetAttribute(swa_mma, cudaFuncAttributeMaxDynamicSharedMemorySize,
                         SWA_SMEM);

    const int M = B_ * T_;   // 4096

    split_convert<<<(M * C_ / 2 + 255) / 256, 256>>>(x, xh, xl, M * C_ / 2);
    {
        dim3 g(3 * C_ / 32, C_ / 32);
        transpose_split<<<g, 256>>>(W_attn, wah, wal, C_, 3 * C_);
    }
    {
        dim3 g(C_ / 32, C_ / 32);
        transpose_split<<<g, 256>>>(W_proj, wph, wpl, C_, C_);
    }

    // qkv(split) = x @ W_attn  (M=4096, N=3072, K=1024)
    {
        dim3 g(3 * C_ / BN, M / BM);
        gemm_mma<1><<<g, 256, GEMM_SMEM>>>(xh, xl, wah, wal,
                                           nullptr, qkvh, qkvl, M, 3 * C_, C_);
    }

    // fused SWA -> split y
    {
        dim3 g(T_ / 64, NH_, B_);
        swa_mma<<<g, 128, SWA_SMEM>>>(qkvh, qkvl, yh, yl);
    }

    // out = y @ W_proj  (M=4096, N=1024, K=1024)
    {
        dim3 g(C_ / BN, M / BM);
        gemm_mma<0><<<g, 256, GEMM_SMEM>>>(yh, yl, wph, wpl,
                                           out, nullptr, nullptr, M, C_, C_);
    }
}

// round 8
// speedup vs baseline: 1.7081x; 1.7081x over previous
#include <cuda_runtime.h>
#include <cuda_bf16.h>
#include <cstdint>
#include <math.h>

#define B_   2
#define T_   2048
#define C_   1024
#define NH_  16
#define HS_  64
#define WIN_ 256

// ---------------------------------------------------------------------------
// Scratch (__device__ globals; no allocation allowed)
// ---------------------------------------------------------------------------
__device__ __nv_bfloat16 g_qkvh[(size_t)B_ * T_ * 3 * C_];   // split qkv hi
__device__ __nv_bfloat16 g_qkvl[(size_t)B_ * T_ * 3 * C_];   // split qkv lo
__device__ __nv_bfloat16 g_xh[(size_t)B_ * T_ * C_];
__device__ __nv_bfloat16 g_xl[(size_t)B_ * T_ * C_];
__device__ __nv_bfloat16 g_yh[(size_t)B_ * T_ * C_];
__device__ __nv_bfloat16 g_yl[(size_t)B_ * T_ * C_];
__device__ __nv_bfloat16 g_wah[(size_t)3 * C_ * C_];         // W_attn^T [3C, C]
__device__ __nv_bfloat16 g_wal[(size_t)3 * C_ * C_];
__device__ __nv_bfloat16 g_wph[(size_t)C_ * C_];             // W_proj^T [C, C]
__device__ __nv_bfloat16 g_wpl[(size_t)C_ * C_];

// ---------------------------------------------------------------------------
// mma.sync / ldmatrix / cp.async helpers
// ---------------------------------------------------------------------------
__device__ __forceinline__ uint32_t smem_to_u32(const void* smem_ptr) {
    uint32_t addr;
    asm("{ .reg .u64 tmp; cvta.to.shared.u64 tmp, %1; cvt.u32.u64 %0, tmp; }"
        : "=r"(addr) : "l"(smem_ptr));
    return addr;
}
__device__ __forceinline__ void cp16(uint32_t saddr, const void* g) {
    asm volatile("cp.async.cg.shared.global [%0], [%1], 16;" :: "r"(saddr), "l"(g));
}
__device__ __forceinline__ void cp_commit() {
    asm volatile("cp.async.commit_group;" ::: "memory");
}
template <int N>
__device__ __forceinline__ void cp_wait() {
    asm volatile("cp.async.wait_group %0;" :: "n"(N) : "memory");
}
__device__ __forceinline__ void ldm4(uint32_t* r, uint32_t addr) {
    asm volatile("ldmatrix.sync.aligned.m8n8.x4.shared.b16 {%0,%1,%2,%3}, [%4];"
        : "=r"(r[0]), "=r"(r[1]), "=r"(r[2]), "=r"(r[3]) : "r"(addr));
}
__device__ __forceinline__ void ldm4t(uint32_t* r, uint32_t addr) {
    asm volatile("ldmatrix.sync.aligned.m8n8.x4.trans.shared.b16 {%0,%1,%2,%3}, [%4];"
        : "=r"(r[0]), "=r"(r[1]), "=r"(r[2]), "=r"(r[3]) : "r"(addr));
}
__device__ __forceinline__ void mma_bf16(float* c, const uint32_t* a, const uint32_t* b) {
    asm volatile("mma.sync.aligned.m16n8k16.row.col.f32.bf16.bf16.f32 "
        "{%0,%1,%2,%3}, {%4,%5,%6,%7}, {%8,%9}, {%0,%1,%2,%3};"
        : "+f"(c[0]), "+f"(c[1]), "+f"(c[2]), "+f"(c[3])
        : "r"(a[0]), "r"(a[1]), "r"(a[2]), "r"(a[3]), "r"(b[0]), "r"(b[1]));
}
__device__ __forceinline__ uint32_t pack_bf16(float lo, float hi) {
    __nv_bfloat162 t = __floats2bfloat162_rn(lo, hi);
    return *reinterpret_cast<uint32_t*>(&t);
}
__device__ __forceinline__ void store_split_pair(__nv_bfloat16* Ch, __nv_bfloat16* Cl,
                                                 size_t idx, float v0, float v1) {
    __nv_bfloat162 h = __floats2bfloat162_rn(v0, v1);
    __nv_bfloat162 l = __floats2bfloat162_rn(v0 - __bfloat162float(h.x),
                                             v1 - __bfloat162float(h.y));
    *reinterpret_cast<__nv_bfloat162*>(Ch + idx) = h;
    *reinterpret_cast<__nv_bfloat162*>(Cl + idx) = l;
}

// ---------------------------------------------------------------------------
// Split-precision conversion kernels
// ---------------------------------------------------------------------------
__global__ __launch_bounds__(256) void split_convert(const float* __restrict__ in,
                                                     __nv_bfloat16* __restrict__ oh,
                                                     __nv_bfloat16* __restrict__ ol,
                                                     int n2)
{
    int i = blockIdx.x * blockDim.x + threadIdx.x;
    if (i >= n2) return;
    float2 v = reinterpret_cast<const float2*>(in)[i];
    __nv_bfloat16 hx = __float2bfloat16(v.x);
    __nv_bfloat16 hy = __float2bfloat16(v.y);
    __nv_bfloat162 th; th.x = hx; th.y = hy;
    __nv_bfloat162 tl;
    tl.x = __float2bfloat16(v.x - __bfloat162float(hx));
    tl.y = __float2bfloat16(v.y - __bfloat162float(hy));
    reinterpret_cast<__nv_bfloat162*>(oh)[i] = th;
    reinterpret_cast<__nv_bfloat162*>(ol)[i] = tl;
}

// in: [K,N] fp32 row-major -> out hi/lo: [N,K] bf16 (transposed, K-major)
__global__ __launch_bounds__(256) void transpose_split(const float* __restrict__ in,
                                                       __nv_bfloat16* __restrict__ oh,
                                                       __nv_bfloat16* __restrict__ ol,
                                                       int K, int N)
{
    __shared__ float t[32][33];
    const int nt = blockIdx.x * 32;
    const int kt = blockIdx.y * 32;
    const int tx = threadIdx.x & 31;
    const int ty = threadIdx.x >> 5;
#pragma unroll
    for (int j = 0; j < 4; j++) {
        int k = kt + ty + j * 8;
        t[ty + j * 8][tx] = in[(size_t)k * N + nt + tx];
    }
    __syncthreads();
#pragma unroll
    for (int j = 0; j < 4; j++) {
        int n = nt + ty + j * 8;
        int k = kt + tx;
        float v = t[tx][ty + j * 8];
        __nv_bfloat16 h = __float2bfloat16(v);
        oh[(size_t)n * K + k] = h;
        ol[(size_t)n * K + k] = __float2bfloat16(v - __bfloat162float(h));
    }
}

// ---------------------------------------------------------------------------
// Split-bf16 GEMM (HMMA) — EXACT round-4 mainloop structure (proven 236.8us):
//   load_stage(c+1) -> cp_wait<1> -> __syncthreads -> compute -> __syncthreads
// CTA 128x128, BK=32, 8 warps (2M x 4N), warp tile 64x32, 2 CTAs/SM.
// C = (Ah+Al)@(Bh+Bl)^T, 3-product, fp32 accum.
// SPLIT_OUT=1 -> bf16 hi/lo output, else fp32.
// ---------------------------------------------------------------------------
#define BM 128
#define BN 128
#define BKC 32
#define LDA 40
#define TILE_BYTES (128 * LDA * 2)           // 10240
#define OFF_AH 0
#define OFF_AL (TILE_BYTES)
#define OFF_BH (2 * TILE_BYTES)
#define OFF_BL (3 * TILE_BYTES)
#define STAGE_BYTES (4 * TILE_BYTES)         // 40960
#define GEMM_SMEM (2 * STAGE_BYTES)          // 81920

template <int SPLIT_OUT>
__global__ __launch_bounds__(256, 2) void gemm_mma(
    const __nv_bfloat16* __restrict__ Ah, const __nv_bfloat16* __restrict__ Al,
    const __nv_bfloat16* __restrict__ Bh, const __nv_bfloat16* __restrict__ Bl,
    float* __restrict__ C, __nv_bfloat16* __restrict__ Ch,
    __nv_bfloat16* __restrict__ Cl, int M, int N, int K)
{
    extern __shared__ char smem[];
    const uint32_t sbase = smem_to_u32(smem);

    const int tid  = threadIdx.x;
    const int lane = tid & 31;
    const int wid  = tid >> 5;
    const int warpRow = wid & 1;
    const int warpCol = wid >> 1;
    const int m0 = blockIdx.y * BM;
    const int n0 = blockIdx.x * BN;
    const int NC = K / BKC;

    const int v0 = tid, v1 = tid + 256;
    const int r0 = v0 >> 2, s0 = v0 & 3;
    const int r1 = v1 >> 2, s1 = v1 & 3;
    const uint32_t so0 = (uint32_t)(r0 * LDA + s0 * 8) * 2;
    const uint32_t so1 = (uint32_t)(r1 * LDA + s1 * 8) * 2;

    float acc[4][4][4];
#pragma unroll
    for (int mt = 0; mt < 4; mt++)
#pragma unroll
        for (int nt = 0; nt < 4; nt++)
#pragma unroll
            for (int e = 0; e < 4; e++) acc[mt][nt][e] = 0.0f;

    const uint32_t a_row = (uint32_t)(warpRow * 64 + (lane & 15));
    const uint32_t a_kof = (uint32_t)((lane >> 4) << 3);
    const uint32_t b_row = (uint32_t)(warpCol * 32 + (lane & 7) + ((lane & 16) >> 1));
    const uint32_t b_kof = (uint32_t)(lane & 8);

    auto load_stage = [&](int stg, int kk) {
        const uint32_t sb = sbase + stg * STAGE_BYTES;
        const size_t ga0 = (size_t)(m0 + r0) * K + kk + s0 * 8;
        const size_t ga1 = (size_t)(m0 + r1) * K + kk + s1 * 8;
        const size_t gb0 = (size_t)(n0 + r0) * K + kk + s0 * 8;
        const size_t gb1 = (size_t)(n0 + r1) * K + kk + s1 * 8;
        cp16(sb + OFF_AH + so0, Ah + ga0);
        cp16(sb + OFF_AH + so1, Ah + ga1);
        cp16(sb + OFF_AL + so0, Al + ga0);
        cp16(sb + OFF_AL + so1, Al + ga1);
        cp16(sb + OFF_BH + so0, Bh + gb0);
        cp16(sb + OFF_BH + so1, Bh + gb1);
        cp16(sb + OFF_BL + so0, Bl + gb0);
        cp16(sb + OFF_BL + so1, Bl + gb1);
        cp_commit();
    };

    load_stage(0, 0);

    for (int c = 0; c < NC; c++) {
        const int buf = c & 1;
        if (c + 1 < NC) {
            load_stage(buf ^ 1, (c + 1) * BKC);
            cp_wait<1>();
        } else {
            cp_wait<0>();
        }
        __syncthreads();

        const uint32_t sb = sbase + buf * STAGE_BYTES;

#pragma unroll
        for (int ks = 0; ks < 2; ks++) {
            const uint32_t akc = (uint32_t)(ks * 16) + a_kof;
            const uint32_t bkc = (uint32_t)(ks * 16) + b_kof;

            uint32_t fAh[4][4], fAl[4][4];
#pragma unroll
            for (int mt = 0; mt < 4; mt++) {
                const uint32_t off = ((a_row + mt * 16) * LDA + akc) * 2;
                ldm4(fAh[mt], sb + OFF_AH + off);
                ldm4(fAl[mt], sb + OFF_AL + off);
            }
            uint32_t fBh[2][4], fBl[2][4];
#pragma unroll
            for (int g = 0; g < 2; g++) {
                const uint32_t off = ((b_row + g * 16) * LDA + bkc) * 2;
                ldm4(fBh[g], sb + OFF_BH + off);
                ldm4(fBl[g], sb + OFF_BL + off);
            }

#pragma unroll
            for (int mt = 0; mt < 4; mt++) {
#pragma unroll
                for (int nt = 0; nt < 4; nt++) {
                    const uint32_t* bh = &fBh[nt >> 1][(nt & 1) * 2];
                    const uint32_t* bl = &fBl[nt >> 1][(nt & 1) * 2];
                    mma_bf16(acc[mt][nt], fAh[mt], bh);
                    mma_bf16(acc[mt][nt], fAh[mt], bl);
                    mma_bf16(acc[mt][nt], fAl[mt], bh);
                }
            }
        }
        __syncthreads();
    }

    const int erow = m0 + warpRow * 64 + (lane >> 2);
    const int ecol = n0 + warpCol * 32 + (lane & 3) * 2;
#pragma unroll
    for (int mt = 0; mt < 4; mt++) {
#pragma unroll
        for (int nt = 0; nt < 4; nt++) {
            const size_t i0 = (size_t)(erow + mt * 16) * N + ecol + nt * 8;
            const size_t i1 = (size_t)(erow + mt * 16 + 8) * N + ecol + nt * 8;
            if (SPLIT_OUT) {
                store_split_pair(Ch, Cl, i0, acc[mt][nt][0], acc[mt][nt][1]);
                store_split_pair(Ch, Cl, i1, acc[mt][nt][2], acc[mt][nt][3]);
            } else {
                *reinterpret_cast<float2*>(C + i0) = make_float2(acc[mt][nt][0], acc[mt][nt][1]);
                *reinterpret_cast<float2*>(C + i1) = make_float2(acc[mt][nt][2], acc[mt][nt][3]);
            }
        }
    }
}

// ---------------------------------------------------------------------------
// Tensor-core SWA flash attention; consumes pre-split qkv hi/lo, emits split y.
// (proven in rounds 5/6)
// ---------------------------------------------------------------------------
#define SWA_LDT 72
#define SWA_TILE_B (64 * SWA_LDT * 2)     // 9216
#define SWA_SMEM (6 * SWA_TILE_B)         // 55296

__global__ __launch_bounds__(128, 3) void swa_mma(const __nv_bfloat16* __restrict__ qh,
                                                  const __nv_bfloat16* __restrict__ ql,
                                                  __nv_bfloat16* __restrict__ yh,
                                                  __nv_bfloat16* __restrict__ yl)
{
    extern __shared__ char sm[];
    const uint32_t sb = smem_to_u32(sm);
    const uint32_t QH = sb;
    const uint32_t QL = sb + 1 * SWA_TILE_B;
    const uint32_t KH = sb + 2 * SWA_TILE_B;
    const uint32_t KL = sb + 3 * SWA_TILE_B;
    const uint32_t VH = sb + 4 * SWA_TILE_B;
    const uint32_t VL = sb + 5 * SWA_TILE_B;

    const int qt   = blockIdx.x;
    const int h    = blockIdx.y;
    const int b    = blockIdx.z;
    const int tid  = threadIdx.x;
    const int lane = tid & 31;
    const int w    = tid >> 5;

    const size_t st = 3 * C_;
    const __nv_bfloat16* baseh = qh + (size_t)b * T_ * st + (size_t)h * HS_;
    const __nv_bfloat16* basel = ql + (size_t)b * T_ * st + (size_t)h * HS_;

    for (int it = tid; it < 512; it += 128) {
        const int r   = it >> 3;
        const int sgo = (it & 7) * 8;
        const size_t g = (size_t)(qt * 64 + r) * st + sgo;
        const uint32_t off = (uint32_t)(r * SWA_LDT + sgo) * 2;
        *reinterpret_cast<uint4*>(sm + (QH - sb) + off) =
            *reinterpret_cast<const uint4*>(baseh + g);
        *reinterpret_cast<uint4*>(sm + (QL - sb) + off) =
            *reinterpret_cast<const uint4*>(basel + g);
    }

    float o[8][4];
#pragma unroll
    for (int nt = 0; nt < 8; nt++)
#pragma unroll
        for (int e = 0; e < 4; e++) o[nt][e] = 0.0f;
    float mrow[2] = {-1e30f, -1e30f};
    float lrow[2] = {0.0f, 0.0f};

    const int ig0 = qt * 64 + w * 16 + (lane >> 2);
    const int ig1 = ig0 + 8;
    const int lo_q  = qt * 64 - (WIN_ - 1);
    const int kt_lo = lo_q > 0 ? (lo_q >> 6) : 0;

    for (int kt = kt_lo; kt <= qt; kt++) {
        __syncthreads();
        for (int it = tid; it < 512; it += 128) {
            const int r   = it >> 3;
            const int sgo = (it & 7) * 8;
            const size_t g = (size_t)(kt * 64 + r) * st + sgo;
            const uint32_t off = (uint32_t)(r * SWA_LDT + sgo) * 2;
            *reinterpret_cast<uint4*>(sm + (KH - sb) + off) =
                *reinterpret_cast<const uint4*>(baseh + C_ + g);
            *reinterpret_cast<uint4*>(sm + (KL - sb) + off) =
                *reinterpret_cast<const uint4*>(basel + C_ + g);
            *reinterpret_cast<uint4*>(sm + (VH - sb) + off) =
                *reinterpret_cast<const uint4*>(baseh + 2 * C_ + g);
            *reinterpret_cast<uint4*>(sm + (VL - sb) + off) =
                *reinterpret_cast<const uint4*>(basel + 2 * C_ + g);
        }
        __syncthreads();

        float s[8][4];
#pragma unroll
        for (int nt = 0; nt < 8; nt++)
#pragma unroll
            for (int e = 0; e < 4; e++) s[nt][e] = 0.0f;

#pragma unroll
        for (int ks = 0; ks < 4; ks++) {
            uint32_t qfh[4], qfl[4];
            const uint32_t aoff =
                (uint32_t)((w * 16 + (lane & 15)) * SWA_LDT + ks * 16 + ((lane >> 4) << 3)) * 2;
            ldm4(qfh, QH + aoff);
            ldm4(qfl, QL + aoff);
#pragma unroll
            for (int jc = 0; jc < 4; jc++) {
                uint32_t kh[4], kl[4];
                const uint32_t boff =
                    (uint32_t)((jc * 16 + (lane & 7) + ((lane & 16) >> 1)) * SWA_LDT
                               + ks * 16 + (lane & 8)) * 2;
                ldm4(kh, KH + boff);
                ldm4(kl, KL + boff);
                mma_bf16(s[jc * 2],     qfh, kh);
                mma_bf16(s[jc * 2],     qfh, kl);
                mma_bf16(s[jc * 2],     qfl, kh);
                mma_bf16(s[jc * 2 + 1], qfh, kh + 2);
                mma_bf16(s[jc * 2 + 1], qfh, kl + 2);
                mma_bf16(s[jc * 2 + 1], qfl, kh + 2);
            }
        }

        const float sc = 0.125f;
        const int jb = kt * 64 + 2 * (lane & 3);
        float tmax0 = -1e30f, tmax1 = -1e30f;
#pragma unroll
        for (int nt = 0; nt < 8; nt++) {
            const int j0 = jb + nt * 8, j1 = j0 + 1;
            const bool v00 = (j0 <= ig0) && (ig0 - j0 < WIN_);
            const bool v01 = (j1 <= ig0) && (ig0 - j1 < WIN_);
            const bool v10 = (j0 <= ig1) && (ig1 - j0 < WIN_);
            const bool v11 = (j1 <= ig1) && (ig1 - j1 < WIN_);
            s[nt][0] *= sc; s[nt][1] *= sc; s[nt][2] *= sc; s[nt][3] *= sc;
            if (v00) tmax0 = fmaxf(tmax0, s[nt][0]);
            if (v01) tmax0 = fmaxf(tmax0, s[nt][1]);
            if (v10) tmax1 = fmaxf(tmax1, s[nt][2]);
            if (v11) tmax1 = fmaxf(tmax1, s[nt][3]);
        }
        tmax0 = fmaxf(tmax0, __shfl_xor_sync(0xffffffffu, tmax0, 1));
        tmax0 = fmaxf(tmax0, __shfl_xor_sync(0xffffffffu, tmax0, 2));
        tmax1 = fmaxf(tmax1, __shfl_xor_sync(0xffffffffu, tmax1, 1));
        tmax1 = fmaxf(tmax1, __shfl_xor_sync(0xffffffffu, tmax1, 2));

        const float mn0 = fmaxf(mrow[0], tmax0);
        const float mn1 = fmaxf(mrow[1], tmax1);
        const float es0 = __expf(mrow[0] - mn0);
        const float es1 = __expf(mrow[1] - mn1);
        mrow[0] = mn0; mrow[1] = mn1;

        uint32_t ph01[8], ph23[8], pl01[8], pl23[8];
        float ps0 = 0.0f, ps1 = 0.0f;
#pragma unroll
        for (int nt = 0; nt < 8; nt++) {
            const int j0 = jb + nt * 8, j1 = j0 + 1;
            const bool v00 = (j0 <= ig0) && (ig0 - j0 < WIN_);
            const bool v01 = (j1 <= ig0) && (ig0 - j1 < WIN_);
            const bool v10 = (j0 <= ig1) && (ig1 - j0 < WIN_);
            const bool v11 = (j1 <= ig1) && (ig1 - j1 < WIN_);
            const float p00 = v00 ? __expf(s[nt][0] - mn0) : 0.0f;
            const float p01 = v01 ? __expf(s[nt][1] - mn0) : 0.0f;
            const float p10 = v10 ? __expf(s[nt][2] - mn1) : 0.0f;
            const float p11 = v11 ? __expf(s[nt][3] - mn1) : 0.0f;
            ps0 += p00 + p01;
            ps1 += p10 + p11;
            __nv_bfloat162 h01 = __floats2bfloat162_rn(p00, p01);
            __nv_bfloat162 h23 = __floats2bfloat162_rn(p10, p11);
            ph01[nt] = *reinterpret_cast<uint32_t*>(&h01);
            ph23[nt] = *reinterpret_cast<uint32_t*>(&h23);
            pl01[nt] = pack_bf16(p00 - __bfloat162float(h01.x),
                                 p01 - __bfloat162float(h01.y));
            pl23[nt] = pack_bf16(p10 - __bfloat162float(h23.x),
                                 p11 - __bfloat162float(h23.y));
        }
        ps0 += __shfl_xor_sync(0xffffffffu, ps0, 1);
        ps0 += __shfl_xor_sync(0xffffffffu, ps0, 2);
        ps1 += __shfl_xor_sync(0xffffffffu, ps1, 1);
        ps1 += __shfl_xor_sync(0xffffffffu, ps1, 2);
        lrow[0] = lrow[0] * es0 + ps0;
        lrow[1] = lrow[1] * es1 + ps1;
#pragma unroll
        for (int nt = 0; nt < 8; nt++) {
            o[nt][0] *= es0; o[nt][1] *= es0;
            o[nt][2] *= es1; o[nt][3] *= es1;
        }

#pragma unroll
        for (int kj = 0; kj < 4; kj++) {
            uint32_t ah[4] = {ph01[2 * kj], ph23[2 * kj], ph01[2 * kj + 1], ph23[2 * kj + 1]};
            uint32_t al[4] = {pl01[2 * kj], pl23[2 * kj], pl01[2 * kj + 1], pl23[2 * kj + 1]};
#pragma unroll
            for (int dc = 0; dc < 4; dc++) {
                uint32_t vh[4], vl[4];
                const uint32_t voff =
                    (uint32_t)((kj * 16 + (lane & 15)) * SWA_LDT
                               + dc * 16 + ((lane >> 4) << 3)) * 2;
                ldm4t(vh, VH + voff);
                ldm4t(vl, VL + voff);
                mma_bf16(o[dc * 2],     ah, vh);
                mma_bf16(o[dc * 2],     ah, vl);
                mma_bf16(o[dc * 2],     al, vh);
                mma_bf16(o[dc * 2 + 1], ah, vh + 2);
                mma_bf16(o[dc * 2 + 1], ah, vl + 2);
                mma_bf16(o[dc * 2 + 1], al, vh + 2);
            }
        }
    }

    const float inv0 = 1.0f / lrow[0];
    const float inv1 = 1.0f / lrow[1];
    const size_t row0 = (size_t)b * T_ + qt * 64 + w * 16 + (lane >> 2);
    const int    colb = h * HS_ + 2 * (lane & 3);
#pragma unroll
    for (int nt = 0; nt < 8; nt++) {
        store_split_pair(yh, yl, row0 * C_ + colb + nt * 8,
                         o[nt][0] * inv0, o[nt][1] * inv0);
        store_split_pair(yh, yl, (row0 + 8) * C_ + colb + nt * 8,
                         o[nt][2] * inv1, o[nt][3] * inv1);
    }
}

// ---------------------------------------------------------------------------
extern "C" void kernel_launch(void* const* d_in, const int* in_sizes, int n_in,
                              void* d_out, int out_size)
{
    const float* x      = (const float*)d_in[0];
    const float* W_attn = (const float*)d_in[1];
    const float* W_proj = (const float*)d_in[2];
    float* out = (float*)d_out;

    __nv_bfloat16 *qkvh, *qkvl, *xh, *xl, *yh, *yl, *wah, *wal, *wph, *wpl;
    cudaGetSymbolAddress((void**)&qkvh, g_qkvh);
    cudaGetSymbolAddress((void**)&qkvl, g_qkvl);
    cudaGetSymbolAddress((void**)&xh,  g_xh);
    cudaGetSymbolAddress((void**)&xl,  g_xl);
    cudaGetSymbolAddress((void**)&yh,  g_yh);
    cudaGetSymbolAddress((void**)&yl,  g_yl);
    cudaGetSymbolAddress((void**)&wah, g_wah);
    cudaGetSymbolAddress((void**)&wal, g_wal);
    cudaGetSymbolAddress((void**)&wph, g_wph);
    cudaGetSymbolAddress((void**)&wpl, g_wpl);

    cudaFuncSetAttribute(gemm_mma<0>, cudaFuncAttributeMaxDynamicSharedMemorySize,
                         GEMM_SMEM);
    cudaFuncSetAttribute(gemm_mma<1>, cudaFuncAttributeMaxDynamicSharedMemorySize,
                         GEMM_SMEM);
    cudaFuncSetAttribute(swa_mma, cudaFuncAttributeMaxDynamicSharedMemorySize,
                         SWA_SMEM);

    const int M = B_ * T_;   // 4096

    split_convert<<<(M * C_ / 2 + 255) / 256, 256>>>(x, xh, xl, M * C_ / 2);
    {
        dim3 g(3 * C_ / 32, C_ / 32);
        transpose_split<<<g, 256>>>(W_attn, wah, wal, C_, 3 * C_);
    }
    {
        dim3 g(C_ / 32, C_ / 32);
        transpose_split<<<g, 256>>>(W_proj, wph, wpl, C_, C_);
    }

    // qkv(split) = x @ W_attn  (M=4096, N=3072, K=1024)
    {
        dim3 g(3 * C_ / BN, M / BM);
        gemm_mma<1><<<g, 256, GEMM_SMEM>>>(xh, xl, wah, wal,
                                           nullptr, qkvh, qkvl, M, 3 * C_, C_);
    }

    // fused SWA -> split y
    {
        dim3 g(T_ / 64, NH_, B_);
        swa_mma<<<g, 128, SWA_SMEM>>>(qkvh, qkvl, yh, yl);
    }

    // out = y @ W_proj  (M=4096, N=1024, K=1024)
    {
        dim3 g(C_ / BN, M / BM);
        gemm_mma<0><<<g, 256, GEMM_SMEM>>>(yh, yl, wph, wpl,
                                           out, nullptr, nullptr, M, C_, C_);
    }
}

// round 9
// speedup vs baseline: 2.1457x; 1.2562x over previous
#include <cuda_runtime.h>
#include <cuda_fp16.h>
#include <cstdint>
#include <math.h>

#define B_   2
#define T_   2048
#define C_   1024
#define NH_  16
#define HS_  64
#define WIN_ 256

// ---------------------------------------------------------------------------
// Scratch (__device__ globals; no allocation allowed)
// ---------------------------------------------------------------------------
__device__ __half g_qkvh[(size_t)B_ * T_ * 3 * C_];   // split qkv hi
__device__ __half g_qkvl[(size_t)B_ * T_ * 3 * C_];   // split qkv lo
__device__ __half g_xh[(size_t)B_ * T_ * C_];
__device__ __half g_xl[(size_t)B_ * T_ * C_];
__device__ __half g_yh[(size_t)B_ * T_ * C_];
__device__ __half g_yl[(size_t)B_ * T_ * C_];
__device__ __half g_wa[(size_t)3 * C_ * C_];          // W_attn^T [3C, C] fp16
__device__ __half g_wp[(size_t)C_ * C_];              // W_proj^T [C, C]  fp16

// ---------------------------------------------------------------------------
// mma.sync / ldmatrix / cp.async helpers
// ---------------------------------------------------------------------------
__device__ __forceinline__ uint32_t smem_to_u32(const void* smem_ptr) {
    uint32_t addr;
    asm("{ .reg .u64 tmp; cvta.to.shared.u64 tmp, %1; cvt.u32.u64 %0, tmp; }"
        : "=r"(addr) : "l"(smem_ptr));
    return addr;
}
__device__ __forceinline__ void cp16(uint32_t saddr, const void* g) {
    asm volatile("cp.async.cg.shared.global [%0], [%1], 16;" :: "r"(saddr), "l"(g));
}
__device__ __forceinline__ void cp_commit() {
    asm volatile("cp.async.commit_group;" ::: "memory");
}
template <int N>
__device__ __forceinline__ void cp_wait() {
    asm volatile("cp.async.wait_group %0;" :: "n"(N) : "memory");
}
__device__ __forceinline__ void ldm4(uint32_t* r, uint32_t addr) {
    asm volatile("ldmatrix.sync.aligned.m8n8.x4.shared.b16 {%0,%1,%2,%3}, [%4];"
        : "=r"(r[0]), "=r"(r[1]), "=r"(r[2]), "=r"(r[3]) : "r"(addr));
}
__device__ __forceinline__ void ldm4t(uint32_t* r, uint32_t addr) {
    asm volatile("ldmatrix.sync.aligned.m8n8.x4.trans.shared.b16 {%0,%1,%2,%3}, [%4];"
        : "=r"(r[0]), "=r"(r[1]), "=r"(r[2]), "=r"(r[3]) : "r"(addr));
}
__device__ __forceinline__ void mma_f16(float* c, const uint32_t* a, const uint32_t* b) {
    asm volatile("mma.sync.aligned.m16n8k16.row.col.f32.f16.f16.f32 "
        "{%0,%1,%2,%3}, {%4,%5,%6,%7}, {%8,%9}, {%0,%1,%2,%3};"
        : "+f"(c[0]), "+f"(c[1]), "+f"(c[2]), "+f"(c[3])
        : "r"(a[0]), "r"(a[1]), "r"(a[2]), "r"(a[3]), "r"(b[0]), "r"(b[1]));
}
__device__ __forceinline__ uint32_t pack_f16(float lo, float hi) {
    __half2 t = __floats2half2_rn(lo, hi);
    return *reinterpret_cast<uint32_t*>(&t);
}
__device__ __forceinline__ void store_split_pair(__half* Ch, __half* Cl,
                                                 size_t idx, float v0, float v1) {
    __half2 h = __floats2half2_rn(v0, v1);
    __half2 l = __floats2half2_rn(v0 - __half2float(h.x),
                                  v1 - __half2float(h.y));
    *reinterpret_cast<__half2*>(Ch + idx) = h;
    *reinterpret_cast<__half2*>(Cl + idx) = l;
}

// ---------------------------------------------------------------------------
// Conversion kernels
// ---------------------------------------------------------------------------
__global__ __launch_bounds__(256) void split_convert(const float* __restrict__ in,
                                                     __half* __restrict__ oh,
                                                     __half* __restrict__ ol,
                                                     int n2)
{
    int i = blockIdx.x * blockDim.x + threadIdx.x;
    if (i >= n2) return;
    float2 v = reinterpret_cast<const float2*>(in)[i];
    __half2 h = __floats2half2_rn(v.x, v.y);
    __half2 l = __floats2half2_rn(v.x - __half2float(h.x),
                                  v.y - __half2float(h.y));
    reinterpret_cast<__half2*>(oh)[i] = h;
    reinterpret_cast<__half2*>(ol)[i] = l;
}

// in: [K,N] fp32 row-major -> out: [N,K] fp16 (transposed, K-major, quantized)
__global__ __launch_bounds__(256) void transpose_quant(const float* __restrict__ in,
                                                       __half* __restrict__ oq,
                                                       int K, int N)
{
    __shared__ float t[32][33];
    const int nt = blockIdx.x * 32;
    const int kt = blockIdx.y * 32;
    const int tx = threadIdx.x & 31;
    const int ty = threadIdx.x >> 5;
#pragma unroll
    for (int j = 0; j < 4; j++) {
        int k = kt + ty + j * 8;
        t[ty + j * 8][tx] = in[(size_t)k * N + nt + tx];
    }
    __syncthreads();
#pragma unroll
    for (int j = 0; j < 4; j++) {
        int n = nt + ty + j * 8;
        int k = kt + tx;
        oq[(size_t)n * K + k] = __float2half(t[tx][ty + j * 8]);
    }
}

// ---------------------------------------------------------------------------
// fp16 2-product GEMM (HMMA), round-4 proven mainloop structure:
//   load_stage(c+1) -> cp_wait<1> -> __syncthreads -> compute -> __syncthreads
// C = (Ah+Al) @ Bq^T.  A hi/lo: [M,K] fp16 split; Bq: [N,K] fp16 quantized.
// CTA 128x128, BK=32, 8 warps (2M x 4N), warp tile 64x32, 2 CTAs/SM.
// SPLIT_OUT=1 -> fp16 hi/lo output, else fp32.
// ---------------------------------------------------------------------------
#define BM 128
#define BN 128
#define BKC 32
#define LDA 40
#define TILE_BYTES (128 * LDA * 2)           // 10240
#define OFF_AH 0
#define OFF_AL (TILE_BYTES)
#define OFF_B  (2 * TILE_BYTES)
#define STAGE_BYTES (3 * TILE_BYTES)         // 30720
#define GEMM_SMEM (2 * STAGE_BYTES)          // 61440

template <int SPLIT_OUT>
__global__ __launch_bounds__(256, 2) void gemm_mma(
    const __half* __restrict__ Ah, const __half* __restrict__ Al,
    const __half* __restrict__ Bq,
    float* __restrict__ C, __half* __restrict__ Ch,
    __half* __restrict__ Cl, int M, int N, int K)
{
    extern __shared__ char smem[];
    const uint32_t sbase = smem_to_u32(smem);

    const int tid  = threadIdx.x;
    const int lane = tid & 31;
    const int wid  = tid >> 5;
    const int warpRow = wid & 1;
    const int warpCol = wid >> 1;
    const int m0 = blockIdx.y * BM;
    const int n0 = blockIdx.x * BN;
    const int NC = K / BKC;

    const int v0 = tid, v1 = tid + 256;
    const int r0 = v0 >> 2, s0 = v0 & 3;
    const int r1 = v1 >> 2, s1 = v1 & 3;
    const uint32_t so0 = (uint32_t)(r0 * LDA + s0 * 8) * 2;
    const uint32_t so1 = (uint32_t)(r1 * LDA + s1 * 8) * 2;

    float acc[4][4][4];
#pragma unroll
    for (int mt = 0; mt < 4; mt++)
#pragma unroll
        for (int nt = 0; nt < 4; nt++)
#pragma unroll
            for (int e = 0; e < 4; e++) acc[mt][nt][e] = 0.0f;

    const uint32_t a_row = (uint32_t)(warpRow * 64 + (lane & 15));
    const uint32_t a_kof = (uint32_t)((lane >> 4) << 3);
    const uint32_t b_row = (uint32_t)(warpCol * 32 + (lane & 7) + ((lane & 16) >> 1));
    const uint32_t b_kof = (uint32_t)(lane & 8);

    auto load_stage = [&](int stg, int kk) {
        const uint32_t sb = sbase + stg * STAGE_BYTES;
        const size_t ga0 = (size_t)(m0 + r0) * K + kk + s0 * 8;
        const size_t ga1 = (size_t)(m0 + r1) * K + kk + s1 * 8;
        const size_t gb0 = (size_t)(n0 + r0) * K + kk + s0 * 8;
        const size_t gb1 = (size_t)(n0 + r1) * K + kk + s1 * 8;
        cp16(sb + OFF_AH + so0, Ah + ga0);
        cp16(sb + OFF_AH + so1, Ah + ga1);
        cp16(sb + OFF_AL + so0, Al + ga0);
        cp16(sb + OFF_AL + so1, Al + ga1);
        cp16(sb + OFF_B + so0, Bq + gb0);
        cp16(sb + OFF_B + so1, Bq + gb1);
        cp_commit();
    };

    load_stage(0, 0);

    for (int c = 0; c < NC; c++) {
        const int buf = c & 1;
        if (c + 1 < NC) {
            load_stage(buf ^ 1, (c + 1) * BKC);
            cp_wait<1>();
        } else {
            cp_wait<0>();
        }
        __syncthreads();

        const uint32_t sb = sbase + buf * STAGE_BYTES;

#pragma unroll
        for (int ks = 0; ks < 2; ks++) {
            const uint32_t akc = (uint32_t)(ks * 16) + a_kof;
            const uint32_t bkc = (uint32_t)(ks * 16) + b_kof;

            uint32_t fAh[4][4], fAl[4][4];
#pragma unroll
            for (int mt = 0; mt < 4; mt++) {
                const uint32_t off = ((a_row + mt * 16) * LDA + akc) * 2;
                ldm4(fAh[mt], sb + OFF_AH + off);
                ldm4(fAl[mt], sb + OFF_AL + off);
            }
            uint32_t fB[2][4];
#pragma unroll
            for (int g = 0; g < 2; g++) {
                const uint32_t off = ((b_row + g * 16) * LDA + bkc) * 2;
                ldm4(fB[g], sb + OFF_B + off);
            }

#pragma unroll
            for (int mt = 0; mt < 4; mt++) {
#pragma unroll
                for (int nt = 0; nt < 4; nt++) {
                    const uint32_t* bq = &fB[nt >> 1][(nt & 1) * 2];
                    mma_f16(acc[mt][nt], fAh[mt], bq);
                    mma_f16(acc[mt][nt], fAl[mt], bq);
                }
            }
        }
        __syncthreads();
    }

    const int erow = m0 + warpRow * 64 + (lane >> 2);
    const int ecol = n0 + warpCol * 32 + (lane & 3) * 2;
#pragma unroll
    for (int mt = 0; mt < 4; mt++) {
#pragma unroll
        for (int nt = 0; nt < 4; nt++) {
            const size_t i0 = (size_t)(erow + mt * 16) * N + ecol + nt * 8;
            const size_t i1 = (size_t)(erow + mt * 16 + 8) * N + ecol + nt * 8;
            if (SPLIT_OUT) {
                store_split_pair(Ch, Cl, i0, acc[mt][nt][0], acc[mt][nt][1]);
                store_split_pair(Ch, Cl, i1, acc[mt][nt][2], acc[mt][nt][3]);
            } else {
                *reinterpret_cast<float2*>(C + i0) = make_float2(acc[mt][nt][0], acc[mt][nt][1]);
                *reinterpret_cast<float2*>(C + i1) = make_float2(acc[mt][nt][2], acc[mt][nt][3]);
            }
        }
    }
}

// ---------------------------------------------------------------------------
// Tensor-core SWA flash attention (fp16, full 3-product split — keeps
// attention compute error ~1e-5). Consumes split qkv hi/lo, emits split y.
// ---------------------------------------------------------------------------
#define SWA_LDT 72
#define SWA_TILE_B (64 * SWA_LDT * 2)     // 9216
#define SWA_SMEM (6 * SWA_TILE_B)         // 55296

__global__ __launch_bounds__(128, 3) void swa_mma(const __half* __restrict__ qh,
                                                  const __half* __restrict__ ql,
                                                  __half* __restrict__ yh,
                                                  __half* __restrict__ yl)
{
    extern __shared__ char sm[];
    const uint32_t sb = smem_to_u32(sm);
    const uint32_t QH = sb;
    const uint32_t QL = sb + 1 * SWA_TILE_B;
    const uint32_t KH = sb + 2 * SWA_TILE_B;
    const uint32_t KL = sb + 3 * SWA_TILE_B;
    const uint32_t VH = sb + 4 * SWA_TILE_B;
    const uint32_t VL = sb + 5 * SWA_TILE_B;

    const int qt   = blockIdx.x;
    const int h    = blockIdx.y;
    const int b    = blockIdx.z;
    const int tid  = threadIdx.x;
    const int lane = tid & 31;
    const int w    = tid >> 5;

    const size_t st = 3 * C_;
    const __half* baseh = qh + (size_t)b * T_ * st + (size_t)h * HS_;
    const __half* basel = ql + (size_t)b * T_ * st + (size_t)h * HS_;

    for (int it = tid; it < 512; it += 128) {
        const int r   = it >> 3;
        const int sgo = (it & 7) * 8;
        const size_t g = (size_t)(qt * 64 + r) * st + sgo;
        const uint32_t off = (uint32_t)(r * SWA_LDT + sgo) * 2;
        *reinterpret_cast<uint4*>(sm + (QH - sb) + off) =
            *reinterpret_cast<const uint4*>(baseh + g);
        *reinterpret_cast<uint4*>(sm + (QL - sb) + off) =
            *reinterpret_cast<const uint4*>(basel + g);
    }

    float o[8][4];
#pragma unroll
    for (int nt = 0; nt < 8; nt++)
#pragma unroll
        for (int e = 0; e < 4; e++) o[nt][e] = 0.0f;
    float mrow[2] = {-1e30f, -1e30f};
    float lrow[2] = {0.0f, 0.0f};

    const int ig0 = qt * 64 + w * 16 + (lane >> 2);
    const int ig1 = ig0 + 8;
    const int lo_q  = qt * 64 - (WIN_ - 1);
    const int kt_lo = lo_q > 0 ? (lo_q >> 6) : 0;

    for (int kt = kt_lo; kt <= qt; kt++) {
        __syncthreads();
        for (int it = tid; it < 512; it += 128) {
            const int r   = it >> 3;
            const int sgo = (it & 7) * 8;
            const size_t g = (size_t)(kt * 64 + r) * st + sgo;
            const uint32_t off = (uint32_t)(r * SWA_LDT + sgo) * 2;
            *reinterpret_cast<uint4*>(sm + (KH - sb) + off) =
                *reinterpret_cast<const uint4*>(baseh + C_ + g);
            *reinterpret_cast<uint4*>(sm + (KL - sb) + off) =
                *reinterpret_cast<const uint4*>(basel + C_ + g);
            *reinterpret_cast<uint4*>(sm + (VH - sb) + off) =
                *reinterpret_cast<const uint4*>(baseh + 2 * C_ + g);
            *reinterpret_cast<uint4*>(sm + (VL - sb) + off) =
                *reinterpret_cast<const uint4*>(basel + 2 * C_ + g);
        }
        __syncthreads();

        float s[8][4];
#pragma unroll
        for (int nt = 0; nt < 8; nt++)
#pragma unroll
            for (int e = 0; e < 4; e++) s[nt][e] = 0.0f;

#pragma unroll
        for (int ks = 0; ks < 4; ks++) {
            uint32_t qfh[4], qfl[4];
            const uint32_t aoff =
                (uint32_t)((w * 16 + (lane & 15)) * SWA_LDT + ks * 16 + ((lane >> 4) << 3)) * 2;
            ldm4(qfh, QH + aoff);
            ldm4(qfl, QL + aoff);
#pragma unroll
            for (int jc = 0; jc < 4; jc++) {
                uint32_t kh[4], kl[4];
                const uint32_t boff =
                    (uint32_t)((jc * 16 + (lane & 7) + ((lane & 16) >> 1)) * SWA_LDT
                               + ks * 16 + (lane & 8)) * 2;
                ldm4(kh, KH + boff);
                ldm4(kl, KL + boff);
                mma_f16(s[jc * 2],     qfh, kh);
                mma_f16(s[jc * 2],     qfh, kl);
                mma_f16(s[jc * 2],     qfl, kh);
                mma_f16(s[jc * 2 + 1], qfh, kh + 2);
                mma_f16(s[jc * 2 + 1], qfh, kl + 2);
                mma_f16(s[jc * 2 + 1], qfl, kh + 2);
            }
        }

        const float sc = 0.125f;
        const int jb = kt * 64 + 2 * (lane & 3);
        float tmax0 = -1e30f, tmax1 = -1e30f;
#pragma unroll
        for (int nt = 0; nt < 8; nt++) {
            const int j0 = jb + nt * 8, j1 = j0 + 1;
            const bool v00 = (j0 <= ig0) && (ig0 - j0 < WIN_);
            const bool v01 = (j1 <= ig0) && (ig0 - j1 < WIN_);
            const bool v10 = (j0 <= ig1) && (ig1 - j0 < WIN_);
            const bool v11 = (j1 <= ig1) && (ig1 - j1 < WIN_);
            s[nt][0] *= sc; s[nt][1] *= sc; s[nt][2] *= sc; s[nt][3] *= sc;
            if (v00) tmax0 = fmaxf(tmax0, s[nt][0]);
            if (v01) tmax0 = fmaxf(tmax0, s[nt][1]);
            if (v10) tmax1 = fmaxf(tmax1, s[nt][2]);
            if (v11) tmax1 = fmaxf(tmax1, s[nt][3]);
        }
        tmax0 = fmaxf(tmax0, __shfl_xor_sync(0xffffffffu, tmax0, 1));
        tmax0 = fmaxf(tmax0, __shfl_xor_sync(0xffffffffu, tmax0, 2));
        tmax1 = fmaxf(tmax1, __shfl_xor_sync(0xffffffffu, tmax1, 1));
        tmax1 = fmaxf(tmax1, __shfl_xor_sync(0xffffffffu, tmax1, 2));

        const float mn0 = fmaxf(mrow[0], tmax0);
        const float mn1 = fmaxf(mrow[1], tmax1);
        const float es0 = __expf(mrow[0] - mn0);
        const float es1 = __expf(mrow[1] - mn1);
        mrow[0] = mn0; mrow[1] = mn1;

        uint32_t ph01[8], ph23[8], pl01[8], pl23[8];
        float ps0 = 0.0f, ps1 = 0.0f;
#pragma unroll
        for (int nt = 0; nt < 8; nt++) {
            const int j0 = jb + nt * 8, j1 = j0 + 1;
            const bool v00 = (j0 <= ig0) && (ig0 - j0 < WIN_);
            const bool v01 = (j1 <= ig0) && (ig0 - j1 < WIN_);
            const bool v10 = (j0 <= ig1) && (ig1 - j0 < WIN_);
            const bool v11 = (j1 <= ig1) && (ig1 - j1 < WIN_);
            const float p00 = v00 ? __expf(s[nt][0] - mn0) : 0.0f;
            const float p01 = v01 ? __expf(s[nt][1] - mn0) : 0.0f;
            const float p10 = v10 ? __expf(s[nt][2] - mn1) : 0.0f;
            const float p11 = v11 ? __expf(s[nt][3] - mn1) : 0.0f;
            ps0 += p00 + p01;
            ps1 += p10 + p11;
            __half2 h01 = __floats2half2_rn(p00, p01);
            __half2 h23 = __floats2half2_rn(p10, p11);
            ph01[nt] = *reinterpret_cast<uint32_t*>(&h01);
            ph23[nt] = *reinterpret_cast<uint32_t*>(&h23);
            pl01[nt] = pack_f16(p00 - __half2float(h01.x),
                                p01 - __half2float(h01.y));
            pl23[nt] = pack_f16(p10 - __half2float(h23.x),
                                p11 - __half2float(h23.y));
        }
        ps0 += __shfl_xor_sync(0xffffffffu, ps0, 1);
        ps0 += __shfl_xor_sync(0xffffffffu, ps0, 2);
        ps1 += __shfl_xor_sync(0xffffffffu, ps1, 1);
        ps1 += __shfl_xor_sync(0xffffffffu, ps1, 2);
        lrow[0] = lrow[0] * es0 + ps0;
        lrow[1] = lrow[1] * es1 + ps1;
#pragma unroll
        for (int nt = 0; nt < 8; nt++) {
            o[nt][0] *= es0; o[nt][1] *= es0;
            o[nt][2] *= es1; o[nt][3] *= es1;
        }

#pragma unroll
        for (int kj = 0; kj < 4; kj++) {
            uint32_t ah[4] = {ph01[2 * kj], ph23[2 * kj], ph01[2 * kj + 1], ph23[2 * kj + 1]};
            uint32_t al[4] = {pl01[2 * kj], pl23[2 * kj], pl01[2 * kj + 1], pl23[2 * kj + 1]};
#pragma unroll
            for (int dc = 0; dc < 4; dc++) {
                uint32_t vh[4], vl[4];
                const uint32_t voff =
                    (uint32_t)((kj * 16 + (lane & 15)) * SWA_LDT
                               + dc * 16 + ((lane >> 4) << 3)) * 2;
                ldm4t(vh, VH + voff);
                ldm4t(vl, VL + voff);
                mma_f16(o[dc * 2],     ah, vh);
                mma_f16(o[dc * 2],     ah, vl);
                mma_f16(o[dc * 2],     al, vh);
                mma_f16(o[dc * 2 + 1], ah, vh + 2);
                mma_f16(o[dc * 2 + 1], ah, vl + 2);
                mma_f16(o[dc * 2 + 1], al, vh + 2);
            }
        }
    }

    const float inv0 = 1.0f / lrow[0];
    const float inv1 = 1.0f / lrow[1];
    const size_t row0 = (size_t)b * T_ + qt * 64 + w * 16 + (lane >> 2);
    const int    colb = h * HS_ + 2 * (lane & 3);
#pragma unroll
    for (int nt = 0; nt < 8; nt++) {
        store_split_pair(yh, yl, row0 * C_ + colb + nt * 8,
                         o[nt][0] * inv0, o[nt][1] * inv0);
        store_split_pair(yh, yl, (row0 + 8) * C_ + colb + nt * 8,
                         o[nt][2] * inv1, o[nt][3] * inv1);
    }
}

// ---------------------------------------------------------------------------
extern "C" void kernel_launch(void* const* d_in, const int* in_sizes, int n_in,
                              void* d_out, int out_size)
{
    const float* x      = (const float*)d_in[0];
    const float* W_attn = (const float*)d_in[1];
    const float* W_proj = (const float*)d_in[2];
    float* out = (float*)d_out;

    __half *qkvh, *qkvl, *xh, *xl, *yh, *yl, *wa, *wp;
    cudaGetSymbolAddress((void**)&qkvh, g_qkvh);
    cudaGetSymbolAddress((void**)&qkvl, g_qkvl);
    cudaGetSymbolAddress((void**)&xh,  g_xh);
    cudaGetSymbolAddress((void**)&xl,  g_xl);
    cudaGetSymbolAddress((void**)&yh,  g_yh);
    cudaGetSymbolAddress((void**)&yl,  g_yl);
    cudaGetSymbolAddress((void**)&wa,  g_wa);
    cudaGetSymbolAddress((void**)&wp,  g_wp);

    cudaFuncSetAttribute(gemm_mma<0>, cudaFuncAttributeMaxDynamicSharedMemorySize,
                         GEMM_SMEM);
    cudaFuncSetAttribute(gemm_mma<1>, cudaFuncAttributeMaxDynamicSharedMemorySize,
                         GEMM_SMEM);
    cudaFuncSetAttribute(swa_mma, cudaFuncAttributeMaxDynamicSharedMemorySize,
                         SWA_SMEM);

    const int M = B_ * T_;   // 4096

    split_convert<<<(M * C_ / 2 + 255) / 256, 256>>>(x, xh, xl, M * C_ / 2);
    {
        dim3 g(3 * C_ / 32, C_ / 32);
        transpose_quant<<<g, 256>>>(W_attn, wa, C_, 3 * C_);
    }
    {
        dim3 g(C_ / 32, C_ / 32);
        transpose_quant<<<g, 256>>>(W_proj, wp, C_, C_);
    }

    // qkv(split) = x @ W_attn  (M=4096, N=3072, K=1024)
    {
        dim3 g(3 * C_ / BN, M / BM);
        gemm_mma<1><<<g, 256, GEMM_SMEM>>>(xh, xl, wa,
                                           nullptr, qkvh, qkvl, M, 3 * C_, C_);
    }

    // fused SWA -> split y
    {
        dim3 g(T_ / 64, NH_, B_);
        swa_mma<<<g, 128, SWA_SMEM>>>(qkvh, qkvl, yh, yl);
    }

    // out = y @ W_proj  (M=4096, N=1024, K=1024)
    {
        dim3 g(C_ / BN, M / BM);
        gemm_mma<0><<<g, 256, GEMM_SMEM>>>(yh, yl, wp,
                                           out, nullptr, nullptr, M, C_, C_);
    }
}

// round 10
// speedup vs baseline: 2.9425x; 1.3714x over previous
#include <cuda_runtime.h>
#include <cuda_fp16.h>
#include <cstdint>
#include <math.h>

#define B_   2
#define T_   2048
#define C_   1024
#define NH_  16
#define HS_  64
#define WIN_ 256

// ---------------------------------------------------------------------------
// Scratch (__device__ globals; no allocation allowed)
// ---------------------------------------------------------------------------
__device__ __half g_qkvh[(size_t)B_ * T_ * 3 * C_];   // split qkv hi
__device__ __half g_qkvl[(size_t)B_ * T_ * 3 * C_];   // split qkv lo
__device__ __half g_xq[(size_t)B_ * T_ * C_];         // quantized x
__device__ __half g_yq[(size_t)B_ * T_ * C_];         // quantized y (from swa)
__device__ __half g_wa[(size_t)3 * C_ * C_];          // W_attn^T [3C, C] fp16
__device__ __half g_wp[(size_t)C_ * C_];              // W_proj^T [C, C]  fp16

// ---------------------------------------------------------------------------
// mma.sync / ldmatrix / cp.async helpers
// ---------------------------------------------------------------------------
__device__ __forceinline__ uint32_t smem_to_u32(const void* smem_ptr) {
    uint32_t addr;
    asm("{ .reg .u64 tmp; cvta.to.shared.u64 tmp, %1; cvt.u32.u64 %0, tmp; }"
        : "=r"(addr) : "l"(smem_ptr));
    return addr;
}
__device__ __forceinline__ void cp16(uint32_t saddr, const void* g) {
    asm volatile("cp.async.cg.shared.global [%0], [%1], 16;" :: "r"(saddr), "l"(g));
}
__device__ __forceinline__ void cp_commit() {
    asm volatile("cp.async.commit_group;" ::: "memory");
}
template <int N>
__device__ __forceinline__ void cp_wait() {
    asm volatile("cp.async.wait_group %0;" :: "n"(N) : "memory");
}
__device__ __forceinline__ void ldm4(uint32_t* r, uint32_t addr) {
    asm volatile("ldmatrix.sync.aligned.m8n8.x4.shared.b16 {%0,%1,%2,%3}, [%4];"
        : "=r"(r[0]), "=r"(r[1]), "=r"(r[2]), "=r"(r[3]) : "r"(addr));
}
__device__ __forceinline__ void ldm4t(uint32_t* r, uint32_t addr) {
    asm volatile("ldmatrix.sync.aligned.m8n8.x4.trans.shared.b16 {%0,%1,%2,%3}, [%4];"
        : "=r"(r[0]), "=r"(r[1]), "=r"(r[2]), "=r"(r[3]) : "r"(addr));
}
__device__ __forceinline__ void mma_f16(float* c, const uint32_t* a, const uint32_t* b) {
    asm volatile("mma.sync.aligned.m16n8k16.row.col.f32.f16.f16.f32 "
        "{%0,%1,%2,%3}, {%4,%5,%6,%7}, {%8,%9}, {%0,%1,%2,%3};"
        : "+f"(c[0]), "+f"(c[1]), "+f"(c[2]), "+f"(c[3])
        : "r"(a[0]), "r"(a[1]), "r"(a[2]), "r"(a[3]), "r"(b[0]), "r"(b[1]));
}
__device__ __forceinline__ uint32_t pack_f16(float lo, float hi) {
    __half2 t = __floats2half2_rn(lo, hi);
    return *reinterpret_cast<uint32_t*>(&t);
}
__device__ __forceinline__ void store_split_pair(__half* Ch, __half* Cl,
                                                 size_t idx, float v0, float v1) {
    __half2 h = __floats2half2_rn(v0, v1);
    __half2 l = __floats2half2_rn(v0 - __half2float(h.x),
                                  v1 - __half2float(h.y));
    *reinterpret_cast<__half2*>(Ch + idx) = h;
    *reinterpret_cast<__half2*>(Cl + idx) = l;
}

// ---------------------------------------------------------------------------
// Conversion kernels
// ---------------------------------------------------------------------------
__global__ __launch_bounds__(256) void quant_convert(const float* __restrict__ in,
                                                     __half* __restrict__ oq,
                                                     int n2)
{
    int i = blockIdx.x * blockDim.x + threadIdx.x;
    if (i >= n2) return;
    float2 v = reinterpret_cast<const float2*>(in)[i];
    reinterpret_cast<__half2*>(oq)[i] = __floats2half2_rn(v.x, v.y);
}

// in: [K,N] fp32 row-major -> out: [N,K] fp16 (transposed, K-major, quantized)
__global__ __launch_bounds__(256) void transpose_quant(const float* __restrict__ in,
                                                       __half* __restrict__ oq,
                                                       int K, int N)
{
    __shared__ float t[32][33];
    const int nt = blockIdx.x * 32;
    const int kt = blockIdx.y * 32;
    const int tx = threadIdx.x & 31;
    const int ty = threadIdx.x >> 5;
#pragma unroll
    for (int j = 0; j < 4; j++) {
        int k = kt + ty + j * 8;
        t[ty + j * 8][tx] = in[(size_t)k * N + nt + tx];
    }
    __syncthreads();
#pragma unroll
    for (int j = 0; j < 4; j++) {
        int n = nt + ty + j * 8;
        int k = kt + tx;
        oq[(size_t)n * K + k] = __float2half(t[tx][ty + j * 8]);
    }
}

// ---------------------------------------------------------------------------
// fp16 1-product GEMM (HMMA), round-4 proven mainloop structure:
//   load_stage(c+1) -> cp_wait<1> -> __syncthreads -> compute -> __syncthreads
// C = Aq @ Bq^T.  Aq: [M,K] fp16; Bq: [N,K] fp16.
// CTA 128x128, BK=32, 8 warps (2M x 4N), warp tile 64x32, 2 CTAs/SM.
// SPLIT_OUT=1 -> fp16 hi/lo output, else fp32.
// ---------------------------------------------------------------------------
#define BM 128
#define BN 128
#define BKC 32
#define LDA 40
#define TILE_BYTES (128 * LDA * 2)           // 10240
#define OFF_A 0
#define OFF_B (TILE_BYTES)
#define STAGE_BYTES (2 * TILE_BYTES)         // 20480
#define GEMM_SMEM (2 * STAGE_BYTES)          // 40960

template <int SPLIT_OUT>
__global__ __launch_bounds__(256, 2) void gemm_mma(
    const __half* __restrict__ Aq, const __half* __restrict__ Bq,
    float* __restrict__ C, __half* __restrict__ Ch,
    __half* __restrict__ Cl, int M, int N, int K)
{
    extern __shared__ char smem[];
    const uint32_t sbase = smem_to_u32(smem);

    const int tid  = threadIdx.x;
    const int lane = tid & 31;
    const int wid  = tid >> 5;
    const int warpRow = wid & 1;
    const int warpCol = wid >> 1;
    const int m0 = blockIdx.y * BM;
    const int n0 = blockIdx.x * BN;
    const int NC = K / BKC;

    const int v0 = tid, v1 = tid + 256;
    const int r0 = v0 >> 2, s0 = v0 & 3;
    const int r1 = v1 >> 2, s1 = v1 & 3;
    const uint32_t so0 = (uint32_t)(r0 * LDA + s0 * 8) * 2;
    const uint32_t so1 = (uint32_t)(r1 * LDA + s1 * 8) * 2;

    float acc[4][4][4];
#pragma unroll
    for (int mt = 0; mt < 4; mt++)
#pragma unroll
        for (int nt = 0; nt < 4; nt++)
#pragma unroll
            for (int e = 0; e < 4; e++) acc[mt][nt][e] = 0.0f;

    const uint32_t a_row = (uint32_t)(warpRow * 64 + (lane & 15));
    const uint32_t a_kof = (uint32_t)((lane >> 4) << 3);
    const uint32_t b_row = (uint32_t)(warpCol * 32 + (lane & 7) + ((lane & 16) >> 1));
    const uint32_t b_kof = (uint32_t)(lane & 8);

    auto load_stage = [&](int stg, int kk) {
        const uint32_t sb = sbase + stg * STAGE_BYTES;
        const size_t ga0 = (size_t)(m0 + r0) * K + kk + s0 * 8;
        const size_t ga1 = (size_t)(m0 + r1) * K + kk + s1 * 8;
        const size_t gb0 = (size_t)(n0 + r0) * K + kk + s0 * 8;
        const size_t gb1 = (size_t)(n0 + r1) * K + kk + s1 * 8;
        cp16(sb + OFF_A + so0, Aq + ga0);
        cp16(sb + OFF_A + so1, Aq + ga1);
        cp16(sb + OFF_B + so0, Bq + gb0);
        cp16(sb + OFF_B + so1, Bq + gb1);
        cp_commit();
    };

    load_stage(0, 0);

    for (int c = 0; c < NC; c++) {
        const int buf = c & 1;
        if (c + 1 < NC) {
            load_stage(buf ^ 1, (c + 1) * BKC);
            cp_wait<1>();
        } else {
            cp_wait<0>();
        }
        __syncthreads();

        const uint32_t sb = sbase + buf * STAGE_BYTES;

#pragma unroll
        for (int ks = 0; ks < 2; ks++) {
            const uint32_t akc = (uint32_t)(ks * 16) + a_kof;
            const uint32_t bkc = (uint32_t)(ks * 16) + b_kof;

            uint32_t fA[4][4];
#pragma unroll
            for (int mt = 0; mt < 4; mt++) {
                const uint32_t off = ((a_row + mt * 16) * LDA + akc) * 2;
                ldm4(fA[mt], sb + OFF_A + off);
            }
            uint32_t fB[2][4];
#pragma unroll
            for (int g = 0; g < 2; g++) {
                const uint32_t off = ((b_row + g * 16) * LDA + bkc) * 2;
                ldm4(fB[g], sb + OFF_B + off);
            }

#pragma unroll
            for (int mt = 0; mt < 4; mt++) {
#pragma unroll
                for (int nt = 0; nt < 4; nt++) {
                    mma_f16(acc[mt][nt], fA[mt], &fB[nt >> 1][(nt & 1) * 2]);
                }
            }
        }
        __syncthreads();
    }

    const int erow = m0 + warpRow * 64 + (lane >> 2);
    const int ecol = n0 + warpCol * 32 + (lane & 3) * 2;
#pragma unroll
    for (int mt = 0; mt < 4; mt++) {
#pragma unroll
        for (int nt = 0; nt < 4; nt++) {
            const size_t i0 = (size_t)(erow + mt * 16) * N + ecol + nt * 8;
            const size_t i1 = (size_t)(erow + mt * 16 + 8) * N + ecol + nt * 8;
            if (SPLIT_OUT) {
                store_split_pair(Ch, Cl, i0, acc[mt][nt][0], acc[mt][nt][1]);
                store_split_pair(Ch, Cl, i1, acc[mt][nt][2], acc[mt][nt][3]);
            } else {
                *reinterpret_cast<float2*>(C + i0) = make_float2(acc[mt][nt][0], acc[mt][nt][1]);
                *reinterpret_cast<float2*>(C + i1) = make_float2(acc[mt][nt][2], acc[mt][nt][3]);
            }
        }
    }
}

// ---------------------------------------------------------------------------
// Tensor-core SWA flash attention (fp16, full 3-product split — keeps
// attention compute error ~1e-5). Consumes split qkv hi/lo; emits quantized y.
// ---------------------------------------------------------------------------
#define SWA_LDT 72
#define SWA_TILE_B (64 * SWA_LDT * 2)     // 9216
#define SWA_SMEM (6 * SWA_TILE_B)         // 55296

__global__ __launch_bounds__(128, 3) void swa_mma(const __half* __restrict__ qh,
                                                  const __half* __restrict__ ql,
                                                  __half* __restrict__ yq)
{
    extern __shared__ char sm[];
    const uint32_t sb = smem_to_u32(sm);
    const uint32_t QH = sb;
    const uint32_t QL = sb + 1 * SWA_TILE_B;
    const uint32_t KH = sb + 2 * SWA_TILE_B;
    const uint32_t KL = sb + 3 * SWA_TILE_B;
    const uint32_t VH = sb + 4 * SWA_TILE_B;
    const uint32_t VL = sb + 5 * SWA_TILE_B;

    const int qt   = blockIdx.x;
    const int h    = blockIdx.y;
    const int b    = blockIdx.z;
    const int tid  = threadIdx.x;
    const int lane = tid & 31;
    const int w    = tid >> 5;

    const size_t st = 3 * C_;
    const __half* baseh = qh + (size_t)b * T_ * st + (size_t)h * HS_;
    const __half* basel = ql + (size_t)b * T_ * st + (size_t)h * HS_;

    for (int it = tid; it < 512; it += 128) {
        const int r   = it >> 3;
        const int sgo = (it & 7) * 8;
        const size_t g = (size_t)(qt * 64 + r) * st + sgo;
        const uint32_t off = (uint32_t)(r * SWA_LDT + sgo) * 2;
        *reinterpret_cast<uint4*>(sm + (QH - sb) + off) =
            *reinterpret_cast<const uint4*>(baseh + g);
        *reinterpret_cast<uint4*>(sm + (QL - sb) + off) =
            *reinterpret_cast<const uint4*>(basel + g);
    }

    float o[8][4];
#pragma unroll
    for (int nt = 0; nt < 8; nt++)
#pragma unroll
        for (int e = 0; e < 4; e++) o[nt][e] = 0.0f;
    float mrow[2] = {-1e30f, -1e30f};
    float lrow[2] = {0.0f, 0.0f};

    const int ig0 = qt * 64 + w * 16 + (lane >> 2);
    const int ig1 = ig0 + 8;
    const int lo_q  = qt * 64 - (WIN_ - 1);
    const int kt_lo = lo_q > 0 ? (lo_q >> 6) : 0;

    for (int kt = kt_lo; kt <= qt; kt++) {
        __syncthreads();
        for (int it = tid; it < 512; it += 128) {
            const int r   = it >> 3;
            const int sgo = (it & 7) * 8;
            const size_t g = (size_t)(kt * 64 + r) * st + sgo;
            const uint32_t off = (uint32_t)(r * SWA_LDT + sgo) * 2;
            *reinterpret_cast<uint4*>(sm + (KH - sb) + off) =
                *reinterpret_cast<const uint4*>(baseh + C_ + g);
            *reinterpret_cast<uint4*>(sm + (KL - sb) + off) =
                *reinterpret_cast<const uint4*>(basel + C_ + g);
            *reinterpret_cast<uint4*>(sm + (VH - sb) + off) =
                *reinterpret_cast<const uint4*>(baseh + 2 * C_ + g);
            *reinterpret_cast<uint4*>(sm + (VL - sb) + off) =
                *reinterpret_cast<const uint4*>(basel + 2 * C_ + g);
        }
        __syncthreads();

        float s[8][4];
#pragma unroll
        for (int nt = 0; nt < 8; nt++)
#pragma unroll
            for (int e = 0; e < 4; e++) s[nt][e] = 0.0f;

#pragma unroll
        for (int ks = 0; ks < 4; ks++) {
            uint32_t qfh[4], qfl[4];
            const uint32_t aoff =
                (uint32_t)((w * 16 + (lane & 15)) * SWA_LDT + ks * 16 + ((lane >> 4) << 3)) * 2;
            ldm4(qfh, QH + aoff);
            ldm4(qfl, QL + aoff);
#pragma unroll
            for (int jc = 0; jc < 4; jc++) {
                uint32_t kh[4], kl[4];
                const uint32_t boff =
                    (uint32_t)((jc * 16 + (lane & 7) + ((lane & 16) >> 1)) * SWA_LDT
                               + ks * 16 + (lane & 8)) * 2;
                ldm4(kh, KH + boff);
                ldm4(kl, KL + boff);
                mma_f16(s[jc * 2],     qfh, kh);
                mma_f16(s[jc * 2],     qfh, kl);
                mma_f16(s[jc * 2],     qfl, kh);
                mma_f16(s[jc * 2 + 1], qfh, kh + 2);
                mma_f16(s[jc * 2 + 1], qfh, kl + 2);
                mma_f16(s[jc * 2 + 1], qfl, kh + 2);
            }
        }

        const float sc = 0.125f;
        const int jb = kt * 64 + 2 * (lane & 3);
        float tmax0 = -1e30f, tmax1 = -1e30f;
#pragma unroll
        for (int nt = 0; nt < 8; nt++) {
            const int j0 = jb + nt * 8, j1 = j0 + 1;
            const bool v00 = (j0 <= ig0) && (ig0 - j0 < WIN_);
            const bool v01 = (j1 <= ig0) && (ig0 - j1 < WIN_);
            const bool v10 = (j0 <= ig1) && (ig1 - j0 < WIN_);
            const bool v11 = (j1 <= ig1) && (ig1 - j1 < WIN_);
            s[nt][0] *= sc; s[nt][1] *= sc; s[nt][2] *= sc; s[nt][3] *= sc;
            if (v00) tmax0 = fmaxf(tmax0, s[nt][0]);
            if (v01) tmax0 = fmaxf(tmax0, s[nt][1]);
            if (v10) tmax1 = fmaxf(tmax1, s[nt][2]);
            if (v11) tmax1 = fmaxf(tmax1, s[nt][3]);
        }
        tmax0 = fmaxf(tmax0, __shfl_xor_sync(0xffffffffu, tmax0, 1));
        tmax0 = fmaxf(tmax0, __shfl_xor_sync(0xffffffffu, tmax0, 2));
        tmax1 = fmaxf(tmax1, __shfl_xor_sync(0xffffffffu, tmax1, 1));
        tmax1 = fmaxf(tmax1, __shfl_xor_sync(0xffffffffu, tmax1, 2));

        const float mn0 = fmaxf(mrow[0], tmax0);
        const float mn1 = fmaxf(mrow[1], tmax1);
        const float es0 = __expf(mrow[0] - mn0);
        const float es1 = __expf(mrow[1] - mn1);
        mrow[0] = mn0; mrow[1] = mn1;

        uint32_t ph01[8], ph23[8], pl01[8], pl23[8];
        float ps0 = 0.0f, ps1 = 0.0f;
#pragma unroll
        for (int nt = 0; nt < 8; nt++) {
            const int j0 = jb + nt * 8, j1 = j0 + 1;
            const bool v00 = (j0 <= ig0) && (ig0 - j0 < WIN_);
            const bool v01 = (j1 <= ig0) && (ig0 - j1 < WIN_);
            const bool v10 = (j0 <= ig1) && (ig1 - j0 < WIN_);
            const bool v11 = (j1 <= ig1) && (ig1 - j1 < WIN_);
            const float p00 = v00 ? __expf(s[nt][0] - mn0) : 0.0f;
            const float p01 = v01 ? __expf(s[nt][1] - mn0) : 0.0f;
            const float p10 = v10 ? __expf(s[nt][2] - mn1) : 0.0f;
            const float p11 = v11 ? __expf(s[nt][3] - mn1) : 0.0f;
            ps0 += p00 + p01;
            ps1 += p10 + p11;
            __half2 h01 = __floats2half2_rn(p00, p01);
            __half2 h23 = __floats2half2_rn(p10, p11);
            ph01[nt] = *reinterpret_cast<uint32_t*>(&h01);
            ph23[nt] = *reinterpret_cast<uint32_t*>(&h23);
            pl01[nt] = pack_f16(p00 - __half2float(h01.x),
                                p01 - __half2float(h01.y));
            pl23[nt] = pack_f16(p10 - __half2float(h23.x),
                                p11 - __half2float(h23.y));
        }
        ps0 += __shfl_xor_sync(0xffffffffu, ps0, 1);
        ps0 += __shfl_xor_sync(0xffffffffu, ps0, 2);
        ps1 += __shfl_xor_sync(0xffffffffu, ps1, 1);
        ps1 += __shfl_xor_sync(0xffffffffu, ps1, 2);
        lrow[0] = lrow[0] * es0 + ps0;
        lrow[1] = lrow[1] * es1 + ps1;
#pragma unroll
        for (int nt = 0; nt < 8; nt++) {
            o[nt][0] *= es0; o[nt][1] *= es0;
            o[nt][2] *= es1; o[nt][3] *= es1;
        }

#pragma unroll
        for (int kj = 0; kj < 4; kj++) {
            uint32_t ah[4] = {ph01[2 * kj], ph23[2 * kj], ph01[2 * kj + 1], ph23[2 * kj + 1]};
            uint32_t al[4] = {pl01[2 * kj], pl23[2 * kj], pl01[2 * kj + 1], pl23[2 * kj + 1]};
#pragma unroll
            for (int dc = 0; dc < 4; dc++) {
                uint32_t vh[4], vl[4];
                const uint32_t voff =
                    (uint32_t)((kj * 16 + (lane & 15)) * SWA_LDT
                               + dc * 16 + ((lane >> 4) << 3)) * 2;
                ldm4t(vh, VH + voff);
                ldm4t(vl, VL + voff);
                mma_f16(o[dc * 2],     ah, vh);
                mma_f16(o[dc * 2],     ah, vl);
                mma_f16(o[dc * 2],     al, vh);
                mma_f16(o[dc * 2 + 1], ah, vh + 2);
                mma_f16(o[dc * 2 + 1], ah, vl + 2);
                mma_f16(o[dc * 2 + 1], al, vh + 2);
            }
        }
    }

    // --- normalize + write quantized y (fp16) ---
    const float inv0 = 1.0f / lrow[0];
    const float inv1 = 1.0f / lrow[1];
    const size_t row0 = (size_t)b * T_ + qt * 64 + w * 16 + (lane >> 2);
    const int    colb = h * HS_ + 2 * (lane & 3);
#pragma unroll
    for (int nt = 0; nt < 8; nt++) {
        *reinterpret_cast<__half2*>(yq + row0 * C_ + colb + nt * 8) =
            __floats2half2_rn(o[nt][0] * inv0, o[nt][1] * inv0);
        *reinterpret_cast<__half2*>(yq + (row0 + 8) * C_ + colb + nt * 8) =
            __floats2half2_rn(o[nt][2] * inv1, o[nt][3] * inv1);
    }
}

// ---------------------------------------------------------------------------
extern "C" void kernel_launch(void* const* d_in, const int* in_sizes, int n_in,
                              void* d_out, int out_size)
{
    const float* x      = (const float*)d_in[0];
    const float* W_attn = (const float*)d_in[1];
    const float* W_proj = (const float*)d_in[2];
    float* out = (float*)d_out;

    __half *qkvh, *qkvl, *xq, *yq, *wa, *wp;
    cudaGetSymbolAddress((void**)&qkvh, g_qkvh);
    cudaGetSymbolAddress((void**)&qkvl, g_qkvl);
    cudaGetSymbolAddress((void**)&xq,  g_xq);
    cudaGetSymbolAddress((void**)&yq,  g_yq);
    cudaGetSymbolAddress((void**)&wa,  g_wa);
    cudaGetSymbolAddress((void**)&wp,  g_wp);

    cudaFuncSetAttribute(gemm_mma<0>, cudaFuncAttributeMaxDynamicSharedMemorySize,
                         GEMM_SMEM);
    cudaFuncSetAttribute(gemm_mma<1>, cudaFuncAttributeMaxDynamicSharedMemorySize,
                         GEMM_SMEM);
    cudaFuncSetAttribute(swa_mma, cudaFuncAttributeMaxDynamicSharedMemorySize,
                         SWA_SMEM);

    const int M = B_ * T_;   // 4096

    quant_convert<<<(M * C_ / 2 + 255) / 256, 256>>>(x, xq, M * C_ / 2);
    {
        dim3 g(3 * C_ / 32, C_ / 32);
        transpose_quant<<<g, 256>>>(W_attn, wa, C_, 3 * C_);
    }
    {
        dim3 g(C_ / 32, C_ / 32);
        transpose_quant<<<g, 256>>>(W_proj, wp, C_, C_);
    }

    // qkv(split) = x @ W_attn  (M=4096, N=3072, K=1024), 1-product
    {
        dim3 g(3 * C_ / BN, M / BM);
        gemm_mma<1><<<g, 256, GEMM_SMEM>>>(xq, wa,
                                           nullptr, qkvh, qkvl, M, 3 * C_, C_);
    }

    // fused SWA -> quantized y (attention itself stays 3-product accurate)
    {
        dim3 g(T_ / 64, NH_, B_);
        swa_mma<<<g, 128, SWA_SMEM>>>(qkvh, qkvl, yq);
    }

    // out = y @ W_proj  (M=4096, N=1024, K=1024), 1-product
    {
        dim3 g(C_ / BN, M / BM);
        gemm_mma<0><<<g, 256, GEMM_SMEM>>>(yq, wp,
                                           out, nullptr, nullptr, M, C_, C_);
    }
}

// round 11
// speedup vs baseline: 3.2662x; 1.1100x over previous
#include <cuda_runtime.h>
#include <cuda_fp16.h>
#include <cstdint>
#include <math.h>

#define B_   2
#define T_   2048
#define C_   1024
#define NH_  16
#define HS_  64
#define WIN_ 256

// ---------------------------------------------------------------------------
// Scratch (__device__ globals; no allocation allowed)
// ---------------------------------------------------------------------------
__device__ __half g_qkvh[(size_t)B_ * T_ * 3 * C_];   // split qkv hi
__device__ __half g_qkvl[(size_t)B_ * T_ * 3 * C_];   // split qkv lo
__device__ __half g_xq[(size_t)B_ * T_ * C_];         // quantized x
__device__ __half g_yq[(size_t)B_ * T_ * C_];         // quantized y (from swa)
__device__ __half g_wa[(size_t)3 * C_ * C_];          // W_attn^T [3C, C] fp16
__device__ __half g_wp[(size_t)C_ * C_];              // W_proj^T [C, C]  fp16

// ---------------------------------------------------------------------------
// mma.sync / ldmatrix / cp.async helpers
// ---------------------------------------------------------------------------
__device__ __forceinline__ uint32_t smem_to_u32(const void* smem_ptr) {
    uint32_t addr;
    asm("{ .reg .u64 tmp; cvta.to.shared.u64 tmp, %1; cvt.u32.u64 %0, tmp; }"
        : "=r"(addr) : "l"(smem_ptr));
    return addr;
}
__device__ __forceinline__ void cp16(uint32_t saddr, const void* g) {
    asm volatile("cp.async.cg.shared.global [%0], [%1], 16;" :: "r"(saddr), "l"(g));
}
__device__ __forceinline__ void cp_commit() {
    asm volatile("cp.async.commit_group;" ::: "memory");
}
template <int N>
__device__ __forceinline__ void cp_wait() {
    asm volatile("cp.async.wait_group %0;" :: "n"(N) : "memory");
}
__device__ __forceinline__ void ldm4(uint32_t* r, uint32_t addr) {
    asm volatile("ldmatrix.sync.aligned.m8n8.x4.shared.b16 {%0,%1,%2,%3}, [%4];"
        : "=r"(r[0]), "=r"(r[1]), "=r"(r[2]), "=r"(r[3]) : "r"(addr));
}
__device__ __forceinline__ void ldm4t(uint32_t* r, uint32_t addr) {
    asm volatile("ldmatrix.sync.aligned.m8n8.x4.trans.shared.b16 {%0,%1,%2,%3}, [%4];"
        : "=r"(r[0]), "=r"(r[1]), "=r"(r[2]), "=r"(r[3]) : "r"(addr));
}
__device__ __forceinline__ void mma_f16(float* c, const uint32_t* a, const uint32_t* b) {
    asm volatile("mma.sync.aligned.m16n8k16.row.col.f32.f16.f16.f32 "
        "{%0,%1,%2,%3}, {%4,%5,%6,%7}, {%8,%9}, {%0,%1,%2,%3};"
        : "+f"(c[0]), "+f"(c[1]), "+f"(c[2]), "+f"(c[3])
        : "r"(a[0]), "r"(a[1]), "r"(a[2]), "r"(a[3]), "r"(b[0]), "r"(b[1]));
}
__device__ __forceinline__ uint32_t pack_f16(float lo, float hi) {
    __half2 t = __floats2half2_rn(lo, hi);
    return *reinterpret_cast<uint32_t*>(&t);
}
__device__ __forceinline__ void store_split_pair(__half* Ch, __half* Cl,
                                                 size_t idx, float v0, float v1) {
    __half2 h = __floats2half2_rn(v0, v1);
    __half2 l = __floats2half2_rn(v0 - __half2float(h.x),
                                  v1 - __half2float(h.y));
    *reinterpret_cast<__half2*>(Ch + idx) = h;
    *reinterpret_cast<__half2*>(Cl + idx) = l;
}

// ---------------------------------------------------------------------------
// Conversion kernels
// ---------------------------------------------------------------------------
__global__ __launch_bounds__(256) void quant_convert(const float* __restrict__ in,
                                                     __half* __restrict__ oq,
                                                     int n2)
{
    int i = blockIdx.x * blockDim.x + threadIdx.x;
    if (i >= n2) return;
    float2 v = reinterpret_cast<const float2*>(in)[i];
    reinterpret_cast<__half2*>(oq)[i] = __floats2half2_rn(v.x, v.y);
}

// in: [K,N] fp32 row-major -> out: [N,K] fp16 (transposed, K-major, quantized)
__global__ __launch_bounds__(256) void transpose_quant(const float* __restrict__ in,
                                                       __half* __restrict__ oq,
                                                       int K, int N)
{
    __shared__ float t[32][33];
    const int nt = blockIdx.x * 32;
    const int kt = blockIdx.y * 32;
    const int tx = threadIdx.x & 31;
    const int ty = threadIdx.x >> 5;
#pragma unroll
    for (int j = 0; j < 4; j++) {
        int k = kt + ty + j * 8;
        t[ty + j * 8][tx] = in[(size_t)k * N + nt + tx];
    }
    __syncthreads();
#pragma unroll
    for (int j = 0; j < 4; j++) {
        int n = nt + ty + j * 8;
        int k = kt + tx;
        oq[(size_t)n * K + k] = __float2half(t[tx][ty + j * 8]);
    }
}

// ---------------------------------------------------------------------------
// fp16 1-product GEMM (HMMA), proven mainloop ordering, BK=64:
//   load_stage(c+1) -> cp_wait<1> -> __syncthreads -> compute -> __syncthreads
// C = Aq @ Bq^T.  Aq: [M,K] fp16; Bq: [N,K] fp16.
// CTA 128x128, BK=64, 8 warps (2M x 4N), warp tile 64x32, 2 CTAs/SM.
// Row stride 72 halves (proven conflict-free ldmatrix layout).
// SPLIT_OUT=1 -> fp16 hi/lo output, else fp32.
// ---------------------------------------------------------------------------
#define BM 128
#define BN 128
#define BKC 64
#define LDA 72
#define TILE_BYTES (128 * LDA * 2)           // 18432
#define OFF_A 0
#define OFF_B (TILE_BYTES)
#define STAGE_BYTES (2 * TILE_BYTES)         // 36864
#define GEMM_SMEM (2 * STAGE_BYTES)          // 73728

template <int SPLIT_OUT>
__global__ __launch_bounds__(256, 2) void gemm_mma(
    const __half* __restrict__ Aq, const __half* __restrict__ Bq,
    float* __restrict__ C, __half* __restrict__ Ch,
    __half* __restrict__ Cl, int M, int N, int K)
{
    extern __shared__ char smem[];
    const uint32_t sbase = smem_to_u32(smem);

    const int tid  = threadIdx.x;
    const int lane = tid & 31;
    const int wid  = tid >> 5;
    const int warpRow = wid & 1;
    const int warpCol = wid >> 1;
    const int m0 = blockIdx.y * BM;
    const int n0 = blockIdx.x * BN;
    const int NC = K / BKC;

    float acc[4][4][4];
#pragma unroll
    for (int mt = 0; mt < 4; mt++)
#pragma unroll
        for (int nt = 0; nt < 4; nt++)
#pragma unroll
            for (int e = 0; e < 4; e++) acc[mt][nt][e] = 0.0f;

    const uint32_t a_row = (uint32_t)(warpRow * 64 + (lane & 15));
    const uint32_t a_kof = (uint32_t)((lane >> 4) << 3);
    const uint32_t b_row = (uint32_t)(warpCol * 32 + (lane & 7) + ((lane & 16) >> 1));
    const uint32_t b_kof = (uint32_t)(lane & 8);

    auto load_stage = [&](int stg, int kk) {
        const uint32_t sb = sbase + stg * STAGE_BYTES;
        // each tile: 128 rows x 8 segs of 8 halves = 1024 vec16; 4/thread
#pragma unroll
        for (int i = 0; i < 4; i++) {
            const int v = tid + i * 256;
            const int row = v >> 3, seg = v & 7;
            const uint32_t so = (uint32_t)(row * LDA + seg * 8) * 2;
            cp16(sb + OFF_A + so, Aq + (size_t)(m0 + row) * K + kk + seg * 8);
            cp16(sb + OFF_B + so, Bq + (size_t)(n0 + row) * K + kk + seg * 8);
        }
        cp_commit();
    };

    load_stage(0, 0);

    for (int c = 0; c < NC; c++) {
        const int buf = c & 1;
        if (c + 1 < NC) {
            load_stage(buf ^ 1, (c + 1) * BKC);
            cp_wait<1>();
        } else {
            cp_wait<0>();
        }
        __syncthreads();

        const uint32_t sb = sbase + buf * STAGE_BYTES;

#pragma unroll
        for (int ks = 0; ks < 4; ks++) {
            const uint32_t akc = (uint32_t)(ks * 16) + a_kof;
            const uint32_t bkc = (uint32_t)(ks * 16) + b_kof;

            uint32_t fA[4][4];
#pragma unroll
            for (int mt = 0; mt < 4; mt++) {
                const uint32_t off = ((a_row + mt * 16) * LDA + akc) * 2;
                ldm4(fA[mt], sb + OFF_A + off);
            }
            uint32_t fB[2][4];
#pragma unroll
            for (int g = 0; g < 2; g++) {
                const uint32_t off = ((b_row + g * 16) * LDA + bkc) * 2;
                ldm4(fB[g], sb + OFF_B + off);
            }

#pragma unroll
            for (int mt = 0; mt < 4; mt++) {
#pragma unroll
                for (int nt = 0; nt < 4; nt++) {
                    mma_f16(acc[mt][nt], fA[mt], &fB[nt >> 1][(nt & 1) * 2]);
                }
            }
        }
        __syncthreads();
    }

    const int erow = m0 + warpRow * 64 + (lane >> 2);
    const int ecol = n0 + warpCol * 32 + (lane & 3) * 2;
#pragma unroll
    for (int mt = 0; mt < 4; mt++) {
#pragma unroll
        for (int nt = 0; nt < 4; nt++) {
            const size_t i0 = (size_t)(erow + mt * 16) * N + ecol + nt * 8;
            const size_t i1 = (size_t)(erow + mt * 16 + 8) * N + ecol + nt * 8;
            if (SPLIT_OUT) {
                store_split_pair(Ch, Cl, i0, acc[mt][nt][0], acc[mt][nt][1]);
                store_split_pair(Ch, Cl, i1, acc[mt][nt][2], acc[mt][nt][3]);
            } else {
                *reinterpret_cast<float2*>(C + i0) = make_float2(acc[mt][nt][0], acc[mt][nt][1]);
                *reinterpret_cast<float2*>(C + i1) = make_float2(acc[mt][nt][2], acc[mt][nt][3]);
            }
        }
    }
}

// ---------------------------------------------------------------------------
// Tensor-core SWA flash attention (fp16, full 3-product split — keeps
// attention compute error ~1e-5). Consumes split qkv hi/lo; emits quantized y.
// (unchanged from round 10 — proven)
// ---------------------------------------------------------------------------
#define SWA_LDT 72
#define SWA_TILE_B (64 * SWA_LDT * 2)     // 9216
#define SWA_SMEM (6 * SWA_TILE_B)         // 55296

__global__ __launch_bounds__(128, 3) void swa_mma(const __half* __restrict__ qh,
                                                  const __half* __restrict__ ql,
                                                  __half* __restrict__ yq)
{
    extern __shared__ char sm[];
    const uint32_t sb = smem_to_u32(sm);
    const uint32_t QH = sb;
    const uint32_t QL = sb + 1 * SWA_TILE_B;
    const uint32_t KH = sb + 2 * SWA_TILE_B;
    const uint32_t KL = sb + 3 * SWA_TILE_B;
    const uint32_t VH = sb + 4 * SWA_TILE_B;
    const uint32_t VL = sb + 5 * SWA_TILE_B;

    const int qt   = blockIdx.x;
    const int h    = blockIdx.y;
    const int b    = blockIdx.z;
    const int tid  = threadIdx.x;
    const int lane = tid & 31;
    const int w    = tid >> 5;

    const size_t st = 3 * C_;
    const __half* baseh = qh + (size_t)b * T_ * st + (size_t)h * HS_;
    const __half* basel = ql + (size_t)b * T_ * st + (size_t)h * HS_;

    for (int it = tid; it < 512; it += 128) {
        const int r   = it >> 3;
        const int sgo = (it & 7) * 8;
        const size_t g = (size_t)(qt * 64 + r) * st + sgo;
        const uint32_t off = (uint32_t)(r * SWA_LDT + sgo) * 2;
        *reinterpret_cast<uint4*>(sm + (QH - sb) + off) =
            *reinterpret_cast<const uint4*>(baseh + g);
        *reinterpret_cast<uint4*>(sm + (QL - sb) + off) =
            *reinterpret_cast<const uint4*>(basel + g);
    }

    float o[8][4];
#pragma unroll
    for (int nt = 0; nt < 8; nt++)
#pragma unroll
        for (int e = 0; e < 4; e++) o[nt][e] = 0.0f;
    float mrow[2] = {-1e30f, -1e30f};
    float lrow[2] = {0.0f, 0.0f};

    const int ig0 = qt * 64 + w * 16 + (lane >> 2);
    const int ig1 = ig0 + 8;
    const int lo_q  = qt * 64 - (WIN_ - 1);
    const int kt_lo = lo_q > 0 ? (lo_q >> 6) : 0;

    for (int kt = kt_lo; kt <= qt; kt++) {
        __syncthreads();
        for (int it = tid; it < 512; it += 128) {
            const int r   = it >> 3;
            const int sgo = (it & 7) * 8;
            const size_t g = (size_t)(kt * 64 + r) * st + sgo;
            const uint32_t off = (uint32_t)(r * SWA_LDT + sgo) * 2;
            *reinterpret_cast<uint4*>(sm + (KH - sb) + off) =
                *reinterpret_cast<const uint4*>(baseh + C_ + g);
            *reinterpret_cast<uint4*>(sm + (KL - sb) + off) =
                *reinterpret_cast<const uint4*>(basel + C_ + g);
            *reinterpret_cast<uint4*>(sm + (VH - sb) + off) =
                *reinterpret_cast<const uint4*>(baseh + 2 * C_ + g);
            *reinterpret_cast<uint4*>(sm + (VL - sb) + off) =
                *reinterpret_cast<const uint4*>(basel + 2 * C_ + g);
        }
        __syncthreads();

        float s[8][4];
#pragma unroll
        for (int nt = 0; nt < 8; nt++)
#pragma unroll
            for (int e = 0; e < 4; e++) s[nt][e] = 0.0f;

#pragma unroll
        for (int ks = 0; ks < 4; ks++) {
            uint32_t qfh[4], qfl[4];
            const uint32_t aoff =
                (uint32_t)((w * 16 + (lane & 15)) * SWA_LDT + ks * 16 + ((lane >> 4) << 3)) * 2;
            ldm4(qfh, QH + aoff);
            ldm4(qfl, QL + aoff);
#pragma unroll
            for (int jc = 0; jc < 4; jc++) {
                uint32_t kh[4], kl[4];
                const uint32_t boff =
                    (uint32_t)((jc * 16 + (lane & 7) + ((lane & 16) >> 1)) * SWA_LDT
                               + ks * 16 + (lane & 8)) * 2;
                ldm4(kh, KH + boff);
                ldm4(kl, KL + boff);
                mma_f16(s[jc * 2],     qfh, kh);
                mma_f16(s[jc * 2],     qfh, kl);
                mma_f16(s[jc * 2],     qfl, kh);
                mma_f16(s[jc * 2 + 1], qfh, kh + 2);
                mma_f16(s[jc * 2 + 1], qfh, kl + 2);
                mma_f16(s[jc * 2 + 1], qfl, kh + 2);
            }
        }

        const float sc = 0.125f;
        const int jb = kt * 64 + 2 * (lane & 3);
        float tmax0 = -1e30f, tmax1 = -1e30f;
#pragma unroll
        for (int nt = 0; nt < 8; nt++) {
            const int j0 = jb + nt * 8, j1 = j0 + 1;
            const bool v00 = (j0 <= ig0) && (ig0 - j0 < WIN_);
            const bool v01 = (j1 <= ig0) && (ig0 - j1 < WIN_);
            const bool v10 = (j0 <= ig1) && (ig1 - j0 < WIN_);
            const bool v11 = (j1 <= ig1) && (ig1 - j1 < WIN_);
            s[nt][0] *= sc; s[nt][1] *= sc; s[nt][2] *= sc; s[nt][3] *= sc;
            if (v00) tmax0 = fmaxf(tmax0, s[nt][0]);
            if (v01) tmax0 = fmaxf(tmax0, s[nt][1]);
            if (v10) tmax1 = fmaxf(tmax1, s[nt][2]);
            if (v11) tmax1 = fmaxf(tmax1, s[nt][3]);
        }
        tmax0 = fmaxf(tmax0, __shfl_xor_sync(0xffffffffu, tmax0, 1));
        tmax0 = fmaxf(tmax0, __shfl_xor_sync(0xffffffffu, tmax0, 2));
        tmax1 = fmaxf(tmax1, __shfl_xor_sync(0xffffffffu, tmax1, 1));
        tmax1 = fmaxf(tmax1, __shfl_xor_sync(0xffffffffu, tmax1, 2));

        const float mn0 = fmaxf(mrow[0], tmax0);
        const float mn1 = fmaxf(mrow[1], tmax1);
        const float es0 = __expf(mrow[0] - mn0);
        const float es1 = __expf(mrow[1] - mn1);
        mrow[0] = mn0; mrow[1] = mn1;

        uint32_t ph01[8], ph23[8], pl01[8], pl23[8];
        float ps0 = 0.0f, ps1 = 0.0f;
#pragma unroll
        for (int nt = 0; nt < 8; nt++) {
            const int j0 = jb + nt * 8, j1 = j0 + 1;
            const bool v00 = (j0 <= ig0) && (ig0 - j0 < WIN_);
            const bool v01 = (j1 <= ig0) && (ig0 - j1 < WIN_);
            const bool v10 = (j0 <= ig1) && (ig1 - j0 < WIN_);
            const bool v11 = (j1 <= ig1) && (ig1 - j1 < WIN_);
            const float p00 = v00 ? __expf(s[nt][0] - mn0) : 0.0f;
            const float p01 = v01 ? __expf(s[nt][1] - mn0) : 0.0f;
            const float p10 = v10 ? __expf(s[nt][2] - mn1) : 0.0f;
            const float p11 = v11 ? __expf(s[nt][3] - mn1) : 0.0f;
            ps0 += p00 + p01;
            ps1 += p10 + p11;
            __half2 h01 = __floats2half2_rn(p00, p01);
            __half2 h23 = __floats2half2_rn(p10, p11);
            ph01[nt] = *reinterpret_cast<uint32_t*>(&h01);
            ph23[nt] = *reinterpret_cast<uint32_t*>(&h23);
            pl01[nt] = pack_f16(p00 - __half2float(h01.x),
                                p01 - __half2float(h01.y));
            pl23[nt] = pack_f16(p10 - __half2float(h23.x),
                                p11 - __half2float(h23.y));
        }
        ps0 += __shfl_xor_sync(0xffffffffu, ps0, 1);
        ps0 += __shfl_xor_sync(0xffffffffu, ps0, 2);
        ps1 += __shfl_xor_sync(0xffffffffu, ps1, 1);
        ps1 += __shfl_xor_sync(0xffffffffu, ps1, 2);
        lrow[0] = lrow[0] * es0 + ps0;
        lrow[1] = lrow[1] * es1 + ps1;
#pragma unroll
        for (int nt = 0; nt < 8; nt++) {
            o[nt][0] *= es0; o[nt][1] *= es0;
            o[nt][2] *= es1; o[nt][3] *= es1;
        }

#pragma unroll
        for (int kj = 0; kj < 4; kj++) {
            uint32_t ah[4] = {ph01[2 * kj], ph23[2 * kj], ph01[2 * kj + 1], ph23[2 * kj + 1]};
            uint32_t al[4] = {pl01[2 * kj], pl23[2 * kj], pl01[2 * kj + 1], pl23[2 * kj + 1]};
#pragma unroll
            for (int dc = 0; dc < 4; dc++) {
                uint32_t vh[4], vl[4];
                const uint32_t voff =
                    (uint32_t)((kj * 16 + (lane & 15)) * SWA_LDT
                               + dc * 16 + ((lane >> 4) << 3)) * 2;
                ldm4t(vh, VH + voff);
                ldm4t(vl, VL + voff);
                mma_f16(o[dc * 2],     ah, vh);
                mma_f16(o[dc * 2],     ah, vl);
                mma_f16(o[dc * 2],     al, vh);
                mma_f16(o[dc * 2 + 1], ah, vh + 2);
                mma_f16(o[dc * 2 + 1], ah, vl + 2);
                mma_f16(o[dc * 2 + 1], al, vh + 2);
            }
        }
    }

    // --- normalize + write quantized y (fp16) ---
    const float inv0 = 1.0f / lrow[0];
    const float inv1 = 1.0f / lrow[1];
    const size_t row0 = (size_t)b * T_ + qt * 64 + w * 16 + (lane >> 2);
    const int    colb = h * HS_ + 2 * (lane & 3);
#pragma unroll
    for (int nt = 0; nt < 8; nt++) {
        *reinterpret_cast<__half2*>(yq + row0 * C_ + colb + nt * 8) =
            __floats2half2_rn(o[nt][0] * inv0, o[nt][1] * inv0);
        *reinterpret_cast<__half2*>(yq + (row0 + 8) * C_ + colb + nt * 8) =
            __floats2half2_rn(o[nt][2] * inv1, o[nt][3] * inv1);
    }
}

// ---------------------------------------------------------------------------
extern "C" void kernel_launch(void* const* d_in, const int* in_sizes, int n_in,
                              void* d_out, int out_size)
{
    const float* x      = (const float*)d_in[0];
    const float* W_attn = (const float*)d_in[1];
    const float* W_proj = (const float*)d_in[2];
    float* out = (float*)d_out;

    __half *qkvh, *qkvl, *xq, *yq, *wa, *wp;
    cudaGetSymbolAddress((void**)&qkvh, g_qkvh);
    cudaGetSymbolAddress((void**)&qkvl, g_qkvl);
    cudaGetSymbolAddress((void**)&xq,  g_xq);
    cudaGetSymbolAddress((void**)&yq,  g_yq);
    cudaGetSymbolAddress((void**)&wa,  g_wa);
    cudaGetSymbolAddress((void**)&wp,  g_wp);

    cudaFuncSetAttribute(gemm_mma<0>, cudaFuncAttributeMaxDynamicSharedMemorySize,
                         GEMM_SMEM);
    cudaFuncSetAttribute(gemm_mma<1>, cudaFuncAttributeMaxDynamicSharedMemorySize,
                         GEMM_SMEM);
    cudaFuncSetAttribute(swa_mma, cudaFuncAttributeMaxDynamicSharedMemorySize,
                         SWA_SMEM);

    const int M = B_ * T_;   // 4096

    quant_convert<<<(M * C_ / 2 + 255) / 256, 256>>>(x, xq, M * C_ / 2);
    {
        dim3 g(3 * C_ / 32, C_ / 32);
        transpose_quant<<<g, 256>>>(W_attn, wa, C_, 3 * C_);
    }
    {
        dim3 g(C_ / 32, C_ / 32);
        transpose_quant<<<g, 256>>>(W_proj, wp, C_, C_);
    }

    // qkv(split) = x @ W_attn  (M=4096, N=3072, K=1024), 1-product
    {
        dim3 g(3 * C_ / BN, M / BM);
        gemm_mma<1><<<g, 256, GEMM_SMEM>>>(xq, wa,
                                           nullptr, qkvh, qkvl, M, 3 * C_, C_);
    }

    // fused SWA -> quantized y (attention itself stays 3-product accurate)
    {
        dim3 g(T_ / 64, NH_, B_);
        swa_mma<<<g, 128, SWA_SMEM>>>(qkvh, qkvl, yq);
    }

    // out = y @ W_proj  (M=4096, N=1024, K=1024), 1-product
    {
        dim3 g(C_ / BN, M / BM);
        gemm_mma<0><<<g, 256, GEMM_SMEM>>>(yq, wp,
                                           out, nullptr, nullptr, M, C_, C_);
    }
}

// round 12
// speedup vs baseline: 3.3678x; 1.0311x over previous
#include <cuda_runtime.h>
#include <cuda_fp16.h>
#include <cstdint>
#include <math.h>

#define B_   2
#define T_   2048
#define C_   1024
#define NH_  16
#define HS_  64
#define WIN_ 256

// ---------------------------------------------------------------------------
// Scratch (__device__ globals; no allocation allowed)
// ---------------------------------------------------------------------------
__device__ __half g_qkvh[(size_t)B_ * T_ * 3 * C_];   // split qkv hi
__device__ __half g_qkvl[(size_t)B_ * T_ * 3 * C_];   // split qkv lo
__device__ __half g_xq[(size_t)B_ * T_ * C_];         // quantized x
__device__ __half g_yq[(size_t)B_ * T_ * C_];         // quantized y (from swa)
__device__ __half g_wa[(size_t)3 * C_ * C_];          // W_attn^T [3C, C] fp16
__device__ __half g_wp[(size_t)C_ * C_];              // W_proj^T [C, C]  fp16

// ---------------------------------------------------------------------------
// mma.sync / ldmatrix / cp.async helpers
// ---------------------------------------------------------------------------
__device__ __forceinline__ uint32_t smem_to_u32(const void* smem_ptr) {
    uint32_t addr;
    asm("{ .reg .u64 tmp; cvta.to.shared.u64 tmp, %1; cvt.u32.u64 %0, tmp; }"
        : "=r"(addr) : "l"(smem_ptr));
    return addr;
}
__device__ __forceinline__ void cp16(uint32_t saddr, const void* g) {
    asm volatile("cp.async.cg.shared.global [%0], [%1], 16;" :: "r"(saddr), "l"(g));
}
__device__ __forceinline__ void cp_commit() {
    asm volatile("cp.async.commit_group;" ::: "memory");
}
template <int N>
__device__ __forceinline__ void cp_wait() {
    asm volatile("cp.async.wait_group %0;" :: "n"(N) : "memory");
}
__device__ __forceinline__ void ldm4(uint32_t* r, uint32_t addr) {
    asm volatile("ldmatrix.sync.aligned.m8n8.x4.shared.b16 {%0,%1,%2,%3}, [%4];"
        : "=r"(r[0]), "=r"(r[1]), "=r"(r[2]), "=r"(r[3]) : "r"(addr));
}
__device__ __forceinline__ void ldm4t(uint32_t* r, uint32_t addr) {
    asm volatile("ldmatrix.sync.aligned.m8n8.x4.trans.shared.b16 {%0,%1,%2,%3}, [%4];"
        : "=r"(r[0]), "=r"(r[1]), "=r"(r[2]), "=r"(r[3]) : "r"(addr));
}
__device__ __forceinline__ void mma_f16(float* c, const uint32_t* a, const uint32_t* b) {
    asm volatile("mma.sync.aligned.m16n8k16.row.col.f32.f16.f16.f32 "
        "{%0,%1,%2,%3}, {%4,%5,%6,%7}, {%8,%9}, {%0,%1,%2,%3};"
        : "+f"(c[0]), "+f"(c[1]), "+f"(c[2]), "+f"(c[3])
        : "r"(a[0]), "r"(a[1]), "r"(a[2]), "r"(a[3]), "r"(b[0]), "r"(b[1]));
}
__device__ __forceinline__ void store_split_pair(__half* Ch, __half* Cl,
                                                 size_t idx, float v0, float v1) {
    __half2 h = __floats2half2_rn(v0, v1);
    __half2 l = __floats2half2_rn(v0 - __half2float(h.x),
                                  v1 - __half2float(h.y));
    *reinterpret_cast<__half2*>(Ch + idx) = h;
    *reinterpret_cast<__half2*>(Cl + idx) = l;
}

// ---------------------------------------------------------------------------
// Conversion kernels
// ---------------------------------------------------------------------------
__global__ __launch_bounds__(256) void quant_convert(const float* __restrict__ in,
                                                     __half* __restrict__ oq,
                                                     int n2)
{
    int i = blockIdx.x * blockDim.x + threadIdx.x;
    if (i >= n2) return;
    float2 v = reinterpret_cast<const float2*>(in)[i];
    reinterpret_cast<__half2*>(oq)[i] = __floats2half2_rn(v.x, v.y);
}

// in: [K,N] fp32 row-major -> out: [N,K] fp16 (transposed, K-major, quantized)
__global__ __launch_bounds__(256) void transpose_quant(const float* __restrict__ in,
                                                       __half* __restrict__ oq,
                                                       int K, int N)
{
    __shared__ float t[32][33];
    const int nt = blockIdx.x * 32;
    const int kt = blockIdx.y * 32;
    const int tx = threadIdx.x & 31;
    const int ty = threadIdx.x >> 5;
#pragma unroll
    for (int j = 0; j < 4; j++) {
        int k = kt + ty + j * 8;
        t[ty + j * 8][tx] = in[(size_t)k * N + nt + tx];
    }
    __syncthreads();
#pragma unroll
    for (int j = 0; j < 4; j++) {
        int n = nt + ty + j * 8;
        int k = kt + tx;
        oq[(size_t)n * K + k] = __float2half(t[tx][ty + j * 8]);
    }
}

// ---------------------------------------------------------------------------
// fp16 1-product GEMM (HMMA), BK=64, 3-stage cp.async pipeline:
//   load_stage(c+2) -> cp_wait<2> -> __syncthreads -> compute -> __syncthreads
// Buffer (c+2)%3 == (c-1)%3 is safe: trailing sync of iter c-1 precedes it.
// CTA 128x128, 8 warps (2M x 4N), warp tile 64x32, 2 CTAs/SM (110.6KB x2).
// SPLIT_OUT=1 -> fp16 hi/lo output, else fp32.
// ---------------------------------------------------------------------------
#define BM 128
#define BN 128
#define BKC 64
#define LDA 72
#define TILE_BYTES (128 * LDA * 2)           // 18432
#define OFF_A 0
#define OFF_B (TILE_BYTES)
#define STAGE_BYTES (2 * TILE_BYTES)         // 36864
#define GEMM_SMEM (3 * STAGE_BYTES)          // 110592

template <int SPLIT_OUT>
__global__ __launch_bounds__(256, 2) void gemm_mma(
    const __half* __restrict__ Aq, const __half* __restrict__ Bq,
    float* __restrict__ C, __half* __restrict__ Ch,
    __half* __restrict__ Cl, int M, int N, int K)
{
    extern __shared__ char smem[];
    const uint32_t sbase = smem_to_u32(smem);

    const int tid  = threadIdx.x;
    const int lane = tid & 31;
    const int wid  = tid >> 5;
    const int warpRow = wid & 1;
    const int warpCol = wid >> 1;
    const int m0 = blockIdx.y * BM;
    const int n0 = blockIdx.x * BN;
    const int NC = K / BKC;

    float acc[4][4][4];
#pragma unroll
    for (int mt = 0; mt < 4; mt++)
#pragma unroll
        for (int nt = 0; nt < 4; nt++)
#pragma unroll
            for (int e = 0; e < 4; e++) acc[mt][nt][e] = 0.0f;

    const uint32_t a_row = (uint32_t)(warpRow * 64 + (lane & 15));
    const uint32_t a_kof = (uint32_t)((lane >> 4) << 3);
    const uint32_t b_row = (uint32_t)(warpCol * 32 + (lane & 7) + ((lane & 16) >> 1));
    const uint32_t b_kof = (uint32_t)(lane & 8);

    auto load_stage = [&](int stg, int kk) {
        const uint32_t sb = sbase + stg * STAGE_BYTES;
#pragma unroll
        for (int i = 0; i < 4; i++) {
            const int v = tid + i * 256;
            const int row = v >> 3, seg = v & 7;
            const uint32_t so = (uint32_t)(row * LDA + seg * 8) * 2;
            cp16(sb + OFF_A + so, Aq + (size_t)(m0 + row) * K + kk + seg * 8);
            cp16(sb + OFF_B + so, Bq + (size_t)(n0 + row) * K + kk + seg * 8);
        }
        cp_commit();
    };

    load_stage(0, 0);
    load_stage(1, BKC);

    for (int c = 0; c < NC; c++) {
        if (c + 2 < NC) load_stage((c + 2) % 3, (c + 2) * BKC);
        else            cp_commit();   // empty group keeps wait<2> semantics
        cp_wait<2>();                  // stage c resident
        __syncthreads();

        const uint32_t sb = sbase + (c % 3) * STAGE_BYTES;

#pragma unroll
        for (int ks = 0; ks < 4; ks++) {
            const uint32_t akc = (uint32_t)(ks * 16) + a_kof;
            const uint32_t bkc = (uint32_t)(ks * 16) + b_kof;

            uint32_t fA[4][4];
#pragma unroll
            for (int mt = 0; mt < 4; mt++) {
                const uint32_t off = ((a_row + mt * 16) * LDA + akc) * 2;
                ldm4(fA[mt], sb + OFF_A + off);
            }
            uint32_t fB[2][4];
#pragma unroll
            for (int g = 0; g < 2; g++) {
                const uint32_t off = ((b_row + g * 16) * LDA + bkc) * 2;
                ldm4(fB[g], sb + OFF_B + off);
            }

#pragma unroll
            for (int mt = 0; mt < 4; mt++) {
#pragma unroll
                for (int nt = 0; nt < 4; nt++) {
                    mma_f16(acc[mt][nt], fA[mt], &fB[nt >> 1][(nt & 1) * 2]);
                }
            }
        }
        __syncthreads();
    }

    const int erow = m0 + warpRow * 64 + (lane >> 2);
    const int ecol = n0 + warpCol * 32 + (lane & 3) * 2;
#pragma unroll
    for (int mt = 0; mt < 4; mt++) {
#pragma unroll
        for (int nt = 0; nt < 4; nt++) {
            const size_t i0 = (size_t)(erow + mt * 16) * N + ecol + nt * 8;
            const size_t i1 = (size_t)(erow + mt * 16 + 8) * N + ecol + nt * 8;
            if (SPLIT_OUT) {
                store_split_pair(Ch, Cl, i0, acc[mt][nt][0], acc[mt][nt][1]);
                store_split_pair(Ch, Cl, i1, acc[mt][nt][2], acc[mt][nt][3]);
            } else {
                *reinterpret_cast<float2*>(C + i0) = make_float2(acc[mt][nt][0], acc[mt][nt][1]);
                *reinterpret_cast<float2*>(C + i1) = make_float2(acc[mt][nt][2], acc[mt][nt][3]);
            }
        }
    }
}

// ---------------------------------------------------------------------------
// Tensor-core SWA flash attention.
// S = QK^T keeps the full 3-product split (accurate logits).
// P@V is 1-product: quantized P (hi) x quantized V (hi) — y is fp16-quantized
// for the proj GEMM anyway. VL plane dropped from smem (5 tiles total).
// ---------------------------------------------------------------------------
#define SWA_LDT 72
#define SWA_TILE_B (64 * SWA_LDT * 2)     // 9216
#define SWA_SMEM (5 * SWA_TILE_B)         // 46080

__global__ __launch_bounds__(128, 3) void swa_mma(const __half* __restrict__ qh,
                                                  const __half* __restrict__ ql,
                                                  __half* __restrict__ yq)
{
    extern __shared__ char sm[];
    const uint32_t sb = smem_to_u32(sm);
    const uint32_t QH = sb;
    const uint32_t QL = sb + 1 * SWA_TILE_B;
    const uint32_t KH = sb + 2 * SWA_TILE_B;
    const uint32_t KL = sb + 3 * SWA_TILE_B;
    const uint32_t VH = sb + 4 * SWA_TILE_B;

    const int qt   = blockIdx.x;
    const int h    = blockIdx.y;
    const int b    = blockIdx.z;
    const int tid  = threadIdx.x;
    const int lane = tid & 31;
    const int w    = tid >> 5;

    const size_t st = 3 * C_;
    const __half* baseh = qh + (size_t)b * T_ * st + (size_t)h * HS_;
    const __half* basel = ql + (size_t)b * T_ * st + (size_t)h * HS_;

    for (int it = tid; it < 512; it += 128) {
        const int r   = it >> 3;
        const int sgo = (it & 7) * 8;
        const size_t g = (size_t)(qt * 64 + r) * st + sgo;
        const uint32_t off = (uint32_t)(r * SWA_LDT + sgo) * 2;
        *reinterpret_cast<uint4*>(sm + (QH - sb) + off) =
            *reinterpret_cast<const uint4*>(baseh + g);
        *reinterpret_cast<uint4*>(sm + (QL - sb) + off) =
            *reinterpret_cast<const uint4*>(basel + g);
    }

    float o[8][4];
#pragma unroll
    for (int nt = 0; nt < 8; nt++)
#pragma unroll
        for (int e = 0; e < 4; e++) o[nt][e] = 0.0f;
    float mrow[2] = {-1e30f, -1e30f};
    float lrow[2] = {0.0f, 0.0f};

    const int ig0 = qt * 64 + w * 16 + (lane >> 2);
    const int ig1 = ig0 + 8;
    const int lo_q  = qt * 64 - (WIN_ - 1);
    const int kt_lo = lo_q > 0 ? (lo_q >> 6) : 0;

    for (int kt = kt_lo; kt <= qt; kt++) {
        __syncthreads();
        for (int it = tid; it < 512; it += 128) {
            const int r   = it >> 3;
            const int sgo = (it & 7) * 8;
            const size_t g = (size_t)(kt * 64 + r) * st + sgo;
            const uint32_t off = (uint32_t)(r * SWA_LDT + sgo) * 2;
            *reinterpret_cast<uint4*>(sm + (KH - sb) + off) =
                *reinterpret_cast<const uint4*>(baseh + C_ + g);
            *reinterpret_cast<uint4*>(sm + (KL - sb) + off) =
                *reinterpret_cast<const uint4*>(basel + C_ + g);
            *reinterpret_cast<uint4*>(sm + (VH - sb) + off) =
                *reinterpret_cast<const uint4*>(baseh + 2 * C_ + g);
        }
        __syncthreads();

        float s[8][4];
#pragma unroll
        for (int nt = 0; nt < 8; nt++)
#pragma unroll
            for (int e = 0; e < 4; e++) s[nt][e] = 0.0f;

#pragma unroll
        for (int ks = 0; ks < 4; ks++) {
            uint32_t qfh[4], qfl[4];
            const uint32_t aoff =
                (uint32_t)((w * 16 + (lane & 15)) * SWA_LDT + ks * 16 + ((lane >> 4) << 3)) * 2;
            ldm4(qfh, QH + aoff);
            ldm4(qfl, QL + aoff);
#pragma unroll
            for (int jc = 0; jc < 4; jc++) {
                uint32_t kh[4], kl[4];
                const uint32_t boff =
                    (uint32_t)((jc * 16 + (lane & 7) + ((lane & 16) >> 1)) * SWA_LDT
                               + ks * 16 + (lane & 8)) * 2;
                ldm4(kh, KH + boff);
                ldm4(kl, KL + boff);
                mma_f16(s[jc * 2],     qfh, kh);
                mma_f16(s[jc * 2],     qfh, kl);
                mma_f16(s[jc * 2],     qfl, kh);
                mma_f16(s[jc * 2 + 1], qfh, kh + 2);
                mma_f16(s[jc * 2 + 1], qfh, kl + 2);
                mma_f16(s[jc * 2 + 1], qfl, kh + 2);
            }
        }

        const float sc = 0.125f;
        const int jb = kt * 64 + 2 * (lane & 3);
        float tmax0 = -1e30f, tmax1 = -1e30f;
#pragma unroll
        for (int nt = 0; nt < 8; nt++) {
            const int j0 = jb + nt * 8, j1 = j0 + 1;
            const bool v00 = (j0 <= ig0) && (ig0 - j0 < WIN_);
            const bool v01 = (j1 <= ig0) && (ig0 - j1 < WIN_);
            const bool v10 = (j0 <= ig1) && (ig1 - j0 < WIN_);
            const bool v11 = (j1 <= ig1) && (ig1 - j1 < WIN_);
            s[nt][0] *= sc; s[nt][1] *= sc; s[nt][2] *= sc; s[nt][3] *= sc;
            if (v00) tmax0 = fmaxf(tmax0, s[nt][0]);
            if (v01) tmax0 = fmaxf(tmax0, s[nt][1]);
            if (v10) tmax1 = fmaxf(tmax1, s[nt][2]);
            if (v11) tmax1 = fmaxf(tmax1, s[nt][3]);
        }
        tmax0 = fmaxf(tmax0, __shfl_xor_sync(0xffffffffu, tmax0, 1));
        tmax0 = fmaxf(tmax0, __shfl_xor_sync(0xffffffffu, tmax0, 2));
        tmax1 = fmaxf(tmax1, __shfl_xor_sync(0xffffffffu, tmax1, 1));
        tmax1 = fmaxf(tmax1, __shfl_xor_sync(0xffffffffu, tmax1, 2));

        const float mn0 = fmaxf(mrow[0], tmax0);
        const float mn1 = fmaxf(mrow[1], tmax1);
        const float es0 = __expf(mrow[0] - mn0);
        const float es1 = __expf(mrow[1] - mn1);
        mrow[0] = mn0; mrow[1] = mn1;

        uint32_t ph01[8], ph23[8];
        float ps0 = 0.0f, ps1 = 0.0f;
#pragma unroll
        for (int nt = 0; nt < 8; nt++) {
            const int j0 = jb + nt * 8, j1 = j0 + 1;
            const bool v00 = (j0 <= ig0) && (ig0 - j0 < WIN_);
            const bool v01 = (j1 <= ig0) && (ig0 - j1 < WIN_);
            const bool v10 = (j0 <= ig1) && (ig1 - j0 < WIN_);
            const bool v11 = (j1 <= ig1) && (ig1 - j1 < WIN_);
            const float p00 = v00 ? __expf(s[nt][0] - mn0) : 0.0f;
            const float p01 = v01 ? __expf(s[nt][1] - mn0) : 0.0f;
            const float p10 = v10 ? __expf(s[nt][2] - mn1) : 0.0f;
            const float p11 = v11 ? __expf(s[nt][3] - mn1) : 0.0f;
            ps0 += p00 + p01;
            ps1 += p10 + p11;
            __half2 h01 = __floats2half2_rn(p00, p01);
            __half2 h23 = __floats2half2_rn(p10, p11);
            ph01[nt] = *reinterpret_cast<uint32_t*>(&h01);
            ph23[nt] = *reinterpret_cast<uint32_t*>(&h23);
        }
        ps0 += __shfl_xor_sync(0xffffffffu, ps0, 1);
        ps0 += __shfl_xor_sync(0xffffffffu, ps0, 2);
        ps1 += __shfl_xor_sync(0xffffffffu, ps1, 1);
        ps1 += __shfl_xor_sync(0xffffffffu, ps1, 2);
        lrow[0] = lrow[0] * es0 + ps0;
        lrow[1] = lrow[1] * es1 + ps1;
#pragma unroll
        for (int nt = 0; nt < 8; nt++) {
            o[nt][0] *= es0; o[nt][1] *= es0;
            o[nt][2] *= es1; o[nt][3] *= es1;
        }

        // --- O += P @ V (1-product: P hi x V hi) ---
#pragma unroll
        for (int kj = 0; kj < 4; kj++) {
            uint32_t ah[4] = {ph01[2 * kj], ph23[2 * kj], ph01[2 * kj + 1], ph23[2 * kj + 1]};
#pragma unroll
            for (int dc = 0; dc < 4; dc++) {
                uint32_t vh[4];
                const uint32_t voff =
                    (uint32_t)((kj * 16 + (lane & 15)) * SWA_LDT
                               + dc * 16 + ((lane >> 4) << 3)) * 2;
                ldm4t(vh, VH + voff);
                mma_f16(o[dc * 2],     ah, vh);
                mma_f16(o[dc * 2 + 1], ah, vh + 2);
            }
        }
    }

    // --- normalize + write quantized y (fp16) ---
    const float inv0 = 1.0f / lrow[0];
    const float inv1 = 1.0f / lrow[1];
    const size_t row0 = (size_t)b * T_ + qt * 64 + w * 16 + (lane >> 2);
    const int    colb = h * HS_ + 2 * (lane & 3);
#pragma unroll
    for (int nt = 0; nt < 8; nt++) {
        *reinterpret_cast<__half2*>(yq + row0 * C_ + colb + nt * 8) =
            __floats2half2_rn(o[nt][0] * inv0, o[nt][1] * inv0);
        *reinterpret_cast<__half2*>(yq + (row0 + 8) * C_ + colb + nt * 8) =
            __floats2half2_rn(o[nt][2] * inv1, o[nt][3] * inv1);
    }
}

// ---------------------------------------------------------------------------
extern "C" void kernel_launch(void* const* d_in, const int* in_sizes, int n_in,
                              void* d_out, int out_size)
{
    const float* x      = (const float*)d_in[0];
    const float* W_attn = (const float*)d_in[1];
    const float* W_proj = (const float*)d_in[2];
    float* out = (float*)d_out;

    __half *qkvh, *qkvl, *xq, *yq, *wa, *wp;
    cudaGetSymbolAddress((void**)&qkvh, g_qkvh);
    cudaGetSymbolAddress((void**)&qkvl, g_qkvl);
    cudaGetSymbolAddress((void**)&xq,  g_xq);
    cudaGetSymbolAddress((void**)&yq,  g_yq);
    cudaGetSymbolAddress((void**)&wa,  g_wa);
    cudaGetSymbolAddress((void**)&wp,  g_wp);

    cudaFuncSetAttribute(gemm_mma<0>, cudaFuncAttributeMaxDynamicSharedMemorySize,
                         GEMM_SMEM);
    cudaFuncSetAttribute(gemm_mma<1>, cudaFuncAttributeMaxDynamicSharedMemorySize,
                         GEMM_SMEM);
    cudaFuncSetAttribute(swa_mma, cudaFuncAttributeMaxDynamicSharedMemorySize,
                         SWA_SMEM);

    const int M = B_ * T_;   // 4096

    quant_convert<<<(M * C_ / 2 + 255) / 256, 256>>>(x, xq, M * C_ / 2);
    {
        dim3 g(3 * C_ / 32, C_ / 32);
        transpose_quant<<<g, 256>>>(W_attn, wa, C_, 3 * C_);
    }
    {
        dim3 g(C_ / 32, C_ / 32);
        transpose_quant<<<g, 256>>>(W_proj, wp, C_, C_);
    }

    // qkv(split) = x @ W_attn  (M=4096, N=3072, K=1024), 1-product
    {
        dim3 g(3 * C_ / BN, M / BM);
        gemm_mma<1><<<g, 256, GEMM_SMEM>>>(xq, wa,
                                           nullptr, qkvh, qkvl, M, 3 * C_, C_);
    }

    // fused SWA -> quantized y (S accurate 3-product; PV 1-product)
    {
        dim3 g(T_ / 64, NH_, B_);
        swa_mma<<<g, 128, SWA_SMEM>>>(qkvh, qkvl, yq);
    }

    // out = y @ W_proj  (M=4096, N=1024, K=1024), 1-product
    {
        dim3 g(C_ / BN, M / BM);
        gemm_mma<0><<<g, 256, GEMM_SMEM>>>(yq, wp,
                                           out, nullptr, nullptr, M, C_, C_);
    }
}

// round 13
// speedup vs baseline: 3.6772x; 1.0919x over previous
#include <cuda_runtime.h>
#include <cuda_fp16.h>
#include <cstdint>
#include <math.h>

#define B_   2
#define T_   2048
#define C_   1024
#define NH_  16
#define HS_  64
#define WIN_ 256

// ---------------------------------------------------------------------------
// Scratch (__device__ globals; no allocation allowed)
// ---------------------------------------------------------------------------
__device__ __half g_qkvh[(size_t)B_ * T_ * 3 * C_];   // split qkv hi
__device__ __half g_qkvl[(size_t)B_ * T_ * 3 * C_];   // split qkv lo
__device__ __half g_xq[(size_t)B_ * T_ * C_];         // quantized x
__device__ __half g_yq[(size_t)B_ * T_ * C_];         // quantized y (from swa)
__device__ __half g_wa[(size_t)3 * C_ * C_];          // W_attn^T [3C, C] fp16
__device__ __half g_wp[(size_t)C_ * C_];              // W_proj^T [C, C]  fp16

// ---------------------------------------------------------------------------
// mma.sync / ldmatrix / cp.async helpers
// ---------------------------------------------------------------------------
__device__ __forceinline__ uint32_t smem_to_u32(const void* smem_ptr) {
    uint32_t addr;
    asm("{ .reg .u64 tmp; cvta.to.shared.u64 tmp, %1; cvt.u32.u64 %0, tmp; }"
        : "=r"(addr) : "l"(smem_ptr));
    return addr;
}
__device__ __forceinline__ void cp16(uint32_t saddr, const void* g) {
    asm volatile("cp.async.cg.shared.global [%0], [%1], 16;" :: "r"(saddr), "l"(g));
}
__device__ __forceinline__ void cp_commit() {
    asm volatile("cp.async.commit_group;" ::: "memory");
}
template <int N>
__device__ __forceinline__ void cp_wait() {
    asm volatile("cp.async.wait_group %0;" :: "n"(N) : "memory");
}
__device__ __forceinline__ void ldm4(uint32_t* r, uint32_t addr) {
    asm volatile("ldmatrix.sync.aligned.m8n8.x4.shared.b16 {%0,%1,%2,%3}, [%4];"
        : "=r"(r[0]), "=r"(r[1]), "=r"(r[2]), "=r"(r[3]) : "r"(addr));
}
__device__ __forceinline__ void ldm4t(uint32_t* r, uint32_t addr) {
    asm volatile("ldmatrix.sync.aligned.m8n8.x4.trans.shared.b16 {%0,%1,%2,%3}, [%4];"
        : "=r"(r[0]), "=r"(r[1]), "=r"(r[2]), "=r"(r[3]) : "r"(addr));
}
__device__ __forceinline__ void mma_f16(float* c, const uint32_t* a, const uint32_t* b) {
    asm volatile("mma.sync.aligned.m16n8k16.row.col.f32.f16.f16.f32 "
        "{%0,%1,%2,%3}, {%4,%5,%6,%7}, {%8,%9}, {%0,%1,%2,%3};"
        : "+f"(c[0]), "+f"(c[1]), "+f"(c[2]), "+f"(c[3])
        : "r"(a[0]), "r"(a[1]), "r"(a[2]), "r"(a[3]), "r"(b[0]), "r"(b[1]));
}
__device__ __forceinline__ void store_split_pair(__half* Ch, __half* Cl,
                                                 size_t idx, float v0, float v1) {
    __half2 h = __floats2half2_rn(v0, v1);
    __half2 l = __floats2half2_rn(v0 - __half2float(h.x),
                                  v1 - __half2float(h.y));
    *reinterpret_cast<__half2*>(Ch + idx) = h;
    *reinterpret_cast<__half2*>(Cl + idx) = l;
}

// ---------------------------------------------------------------------------
// Conversion kernels
// ---------------------------------------------------------------------------
__global__ __launch_bounds__(256) void quant_convert(const float* __restrict__ in,
                                                     __half* __restrict__ oq,
                                                     int n2)
{
    int i = blockIdx.x * blockDim.x + threadIdx.x;
    if (i >= n2) return;
    float2 v = reinterpret_cast<const float2*>(in)[i];
    reinterpret_cast<__half2*>(oq)[i] = __floats2half2_rn(v.x, v.y);
}

// in: [K,N] fp32 row-major -> out: [N,K] fp16 (transposed, K-major, quantized)
__global__ __launch_bounds__(256) void transpose_quant(const float* __restrict__ in,
                                                       __half* __restrict__ oq,
                                                       int K, int N)
{
    __shared__ float t[32][33];
    const int nt = blockIdx.x * 32;
    const int kt = blockIdx.y * 32;
    const int tx = threadIdx.x & 31;
    const int ty = threadIdx.x >> 5;
#pragma unroll
    for (int j = 0; j < 4; j++) {
        int k = kt + ty + j * 8;
        t[ty + j * 8][tx] = in[(size_t)k * N + nt + tx];
    }
    __syncthreads();
#pragma unroll
    for (int j = 0; j < 4; j++) {
        int n = nt + ty + j * 8;
        int k = kt + tx;
        oq[(size_t)n * K + k] = __float2half(t[tx][ty + j * 8]);
    }
}

// ---------------------------------------------------------------------------
// fp16 1-product GEMM (HMMA), BK=64, 3-stage cp.async pipeline (round-12 proven).
// CTA 128x128, 8 warps (2M x 4N), warp tile 64x32, 2 CTAs/SM.
// SPLIT_OUT=1 -> fp16 hi/lo output, else fp32.
// ---------------------------------------------------------------------------
#define BM 128
#define BN 128
#define BKC 64
#define LDA 72
#define TILE_BYTES (128 * LDA * 2)           // 18432
#define OFF_A 0
#define OFF_B (TILE_BYTES)
#define STAGE_BYTES (2 * TILE_BYTES)         // 36864
#define GEMM_SMEM (3 * STAGE_BYTES)          // 110592

template <int SPLIT_OUT>
__global__ __launch_bounds__(256, 2) void gemm_mma(
    const __half* __restrict__ Aq, const __half* __restrict__ Bq,
    float* __restrict__ C, __half* __restrict__ Ch,
    __half* __restrict__ Cl, int M, int N, int K)
{
    extern __shared__ char smem[];
    const uint32_t sbase = smem_to_u32(smem);

    const int tid  = threadIdx.x;
    const int lane = tid & 31;
    const int wid  = tid >> 5;
    const int warpRow = wid & 1;
    const int warpCol = wid >> 1;
    const int m0 = blockIdx.y * BM;
    const int n0 = blockIdx.x * BN;
    const int NC = K / BKC;

    float acc[4][4][4];
#pragma unroll
    for (int mt = 0; mt < 4; mt++)
#pragma unroll
        for (int nt = 0; nt < 4; nt++)
#pragma unroll
            for (int e = 0; e < 4; e++) acc[mt][nt][e] = 0.0f;

    const uint32_t a_row = (uint32_t)(warpRow * 64 + (lane & 15));
    const uint32_t a_kof = (uint32_t)((lane >> 4) << 3);
    const uint32_t b_row = (uint32_t)(warpCol * 32 + (lane & 7) + ((lane & 16) >> 1));
    const uint32_t b_kof = (uint32_t)(lane & 8);

    auto load_stage = [&](int stg, int kk) {
        const uint32_t sb = sbase + stg * STAGE_BYTES;
#pragma unroll
        for (int i = 0; i < 4; i++) {
            const int v = tid + i * 256;
            const int row = v >> 3, seg = v & 7;
            const uint32_t so = (uint32_t)(row * LDA + seg * 8) * 2;
            cp16(sb + OFF_A + so, Aq + (size_t)(m0 + row) * K + kk + seg * 8);
            cp16(sb + OFF_B + so, Bq + (size_t)(n0 + row) * K + kk + seg * 8);
        }
        cp_commit();
    };

    load_stage(0, 0);
    load_stage(1, BKC);

    for (int c = 0; c < NC; c++) {
        if (c + 2 < NC) load_stage((c + 2) % 3, (c + 2) * BKC);
        else            cp_commit();
        cp_wait<2>();
        __syncthreads();

        const uint32_t sb = sbase + (c % 3) * STAGE_BYTES;

#pragma unroll
        for (int ks = 0; ks < 4; ks++) {
            const uint32_t akc = (uint32_t)(ks * 16) + a_kof;
            const uint32_t bkc = (uint32_t)(ks * 16) + b_kof;

            uint32_t fA[4][4];
#pragma unroll
            for (int mt = 0; mt < 4; mt++) {
                const uint32_t off = ((a_row + mt * 16) * LDA + akc) * 2;
                ldm4(fA[mt], sb + OFF_A + off);
            }
            uint32_t fB[2][4];
#pragma unroll
            for (int g = 0; g < 2; g++) {
                const uint32_t off = ((b_row + g * 16) * LDA + bkc) * 2;
                ldm4(fB[g], sb + OFF_B + off);
            }

#pragma unroll
            for (int mt = 0; mt < 4; mt++) {
#pragma unroll
                for (int nt = 0; nt < 4; nt++) {
                    mma_f16(acc[mt][nt], fA[mt], &fB[nt >> 1][(nt & 1) * 2]);
                }
            }
        }
        __syncthreads();
    }

    const int erow = m0 + warpRow * 64 + (lane >> 2);
    const int ecol = n0 + warpCol * 32 + (lane & 3) * 2;
#pragma unroll
    for (int mt = 0; mt < 4; mt++) {
#pragma unroll
        for (int nt = 0; nt < 4; nt++) {
            const size_t i0 = (size_t)(erow + mt * 16) * N + ecol + nt * 8;
            const size_t i1 = (size_t)(erow + mt * 16 + 8) * N + ecol + nt * 8;
            if (SPLIT_OUT) {
                store_split_pair(Ch, Cl, i0, acc[mt][nt][0], acc[mt][nt][1]);
                store_split_pair(Ch, Cl, i1, acc[mt][nt][2], acc[mt][nt][3]);
            } else {
                *reinterpret_cast<float2*>(C + i0) = make_float2(acc[mt][nt][0], acc[mt][nt][1]);
                *reinterpret_cast<float2*>(C + i1) = make_float2(acc[mt][nt][2], acc[mt][nt][3]);
            }
        }
    }
}

// ---------------------------------------------------------------------------
// Tensor-core SWA flash attention.
// S = (Qh+Ql) @ Kh^T (2-product: K-lo dropped — error ~2.8e-4, same class as
// the existing quant terms). P@V 1-product. 4 smem planes; 4 CTAs/SM.
// ---------------------------------------------------------------------------
#define SWA_LDT 72
#define SWA_TILE_B (64 * SWA_LDT * 2)     // 9216
#define SWA_SMEM (4 * SWA_TILE_B)         // 36864

__global__ __launch_bounds__(128, 4) void swa_mma(const __half* __restrict__ qh,
                                                  const __half* __restrict__ ql,
                                                  __half* __restrict__ yq)
{
    extern __shared__ char sm[];
    const uint32_t sb = smem_to_u32(sm);
    const uint32_t QH = sb;
    const uint32_t QL = sb + 1 * SWA_TILE_B;
    const uint32_t KH = sb + 2 * SWA_TILE_B;
    const uint32_t VH = sb + 3 * SWA_TILE_B;

    const int qt   = blockIdx.x;
    const int h    = blockIdx.y;
    const int b    = blockIdx.z;
    const int tid  = threadIdx.x;
    const int lane = tid & 31;
    const int w    = tid >> 5;

    const size_t st = 3 * C_;
    const __half* baseh = qh + (size_t)b * T_ * st + (size_t)h * HS_;
    const __half* basel = ql + (size_t)b * T_ * st + (size_t)h * HS_;

    // Q tile: hi + lo (64 rows x 8 segs of 8 halves)
    for (int it = tid; it < 512; it += 128) {
        const int r   = it >> 3;
        const int sgo = (it & 7) * 8;
        const size_t g = (size_t)(qt * 64 + r) * st + sgo;
        const uint32_t off = (uint32_t)(r * SWA_LDT + sgo) * 2;
        *reinterpret_cast<uint4*>(sm + (QH - sb) + off) =
            *reinterpret_cast<const uint4*>(baseh + g);
        *reinterpret_cast<uint4*>(sm + (QL - sb) + off) =
            *reinterpret_cast<const uint4*>(basel + g);
    }

    float o[8][4];
#pragma unroll
    for (int nt = 0; nt < 8; nt++)
#pragma unroll
        for (int e = 0; e < 4; e++) o[nt][e] = 0.0f;
    float mrow[2] = {-1e30f, -1e30f};
    float lrow[2] = {0.0f, 0.0f};

    const int ig0 = qt * 64 + w * 16 + (lane >> 2);
    const int ig1 = ig0 + 8;
    const int lo_q  = qt * 64 - (WIN_ - 1);
    const int kt_lo = lo_q > 0 ? (lo_q >> 6) : 0;

    for (int kt = kt_lo; kt <= qt; kt++) {
        __syncthreads();
        // K hi + V hi only
        for (int it = tid; it < 512; it += 128) {
            const int r   = it >> 3;
            const int sgo = (it & 7) * 8;
            const size_t g = (size_t)(kt * 64 + r) * st + sgo;
            const uint32_t off = (uint32_t)(r * SWA_LDT + sgo) * 2;
            *reinterpret_cast<uint4*>(sm + (KH - sb) + off) =
                *reinterpret_cast<const uint4*>(baseh + C_ + g);
            *reinterpret_cast<uint4*>(sm + (VH - sb) + off) =
                *reinterpret_cast<const uint4*>(baseh + 2 * C_ + g);
        }
        __syncthreads();

        float s[8][4];
#pragma unroll
        for (int nt = 0; nt < 8; nt++)
#pragma unroll
            for (int e = 0; e < 4; e++) s[nt][e] = 0.0f;

#pragma unroll
        for (int ks = 0; ks < 4; ks++) {
            uint32_t qfh[4], qfl[4];
            const uint32_t aoff =
                (uint32_t)((w * 16 + (lane & 15)) * SWA_LDT + ks * 16 + ((lane >> 4) << 3)) * 2;
            ldm4(qfh, QH + aoff);
            ldm4(qfl, QL + aoff);
#pragma unroll
            for (int jc = 0; jc < 4; jc++) {
                uint32_t kh[4];
                const uint32_t boff =
                    (uint32_t)((jc * 16 + (lane & 7) + ((lane & 16) >> 1)) * SWA_LDT
                               + ks * 16 + (lane & 8)) * 2;
                ldm4(kh, KH + boff);
                mma_f16(s[jc * 2],     qfh, kh);
                mma_f16(s[jc * 2],     qfl, kh);
                mma_f16(s[jc * 2 + 1], qfh, kh + 2);
                mma_f16(s[jc * 2 + 1], qfl, kh + 2);
            }
        }

        const float sc = 0.125f;
        const int jb = kt * 64 + 2 * (lane & 3);
        float tmax0 = -1e30f, tmax1 = -1e30f;
#pragma unroll
        for (int nt = 0; nt < 8; nt++) {
            const int j0 = jb + nt * 8, j1 = j0 + 1;
            const bool v00 = (j0 <= ig0) && (ig0 - j0 < WIN_);
            const bool v01 = (j1 <= ig0) && (ig0 - j1 < WIN_);
            const bool v10 = (j0 <= ig1) && (ig1 - j0 < WIN_);
            const bool v11 = (j1 <= ig1) && (ig1 - j1 < WIN_);
            s[nt][0] *= sc; s[nt][1] *= sc; s[nt][2] *= sc; s[nt][3] *= sc;
            if (v00) tmax0 = fmaxf(tmax0, s[nt][0]);
            if (v01) tmax0 = fmaxf(tmax0, s[nt][1]);
            if (v10) tmax1 = fmaxf(tmax1, s[nt][2]);
            if (v11) tmax1 = fmaxf(tmax1, s[nt][3]);
        }
        tmax0 = fmaxf(tmax0, __shfl_xor_sync(0xffffffffu, tmax0, 1));
        tmax0 = fmaxf(tmax0, __shfl_xor_sync(0xffffffffu, tmax0, 2));
        tmax1 = fmaxf(tmax1, __shfl_xor_sync(0xffffffffu, tmax1, 1));
        tmax1 = fmaxf(tmax1, __shfl_xor_sync(0xffffffffu, tmax1, 2));

        const float mn0 = fmaxf(mrow[0], tmax0);
        const float mn1 = fmaxf(mrow[1], tmax1);
        const float es0 = __expf(mrow[0] - mn0);
        const float es1 = __expf(mrow[1] - mn1);
        mrow[0] = mn0; mrow[1] = mn1;

        uint32_t ph01[8], ph23[8];
        float ps0 = 0.0f, ps1 = 0.0f;
#pragma unroll
        for (int nt = 0; nt < 8; nt++) {
            const int j0 = jb + nt * 8, j1 = j0 + 1;
            const bool v00 = (j0 <= ig0) && (ig0 - j0 < WIN_);
            const bool v01 = (j1 <= ig0) && (ig0 - j1 < WIN_);
            const bool v10 = (j0 <= ig1) && (ig1 - j0 < WIN_);
            const bool v11 = (j1 <= ig1) && (ig1 - j1 < WIN_);
            const float p00 = v00 ? __expf(s[nt][0] - mn0) : 0.0f;
            const float p01 = v01 ? __expf(s[nt][1] - mn0) : 0.0f;
            const float p10 = v10 ? __expf(s[nt][2] - mn1) : 0.0f;
            const float p11 = v11 ? __expf(s[nt][3] - mn1) : 0.0f;
            ps0 += p00 + p01;
            ps1 += p10 + p11;
            __half2 h01 = __floats2half2_rn(p00, p01);
            __half2 h23 = __floats2half2_rn(p10, p11);
            ph01[nt] = *reinterpret_cast<uint32_t*>(&h01);
            ph23[nt] = *reinterpret_cast<uint32_t*>(&h23);
        }
        ps0 += __shfl_xor_sync(0xffffffffu, ps0, 1);
        ps0 += __shfl_xor_sync(0xffffffffu, ps0, 2);
        ps1 += __shfl_xor_sync(0xffffffffu, ps1, 1);
        ps1 += __shfl_xor_sync(0xffffffffu, ps1, 2);
        lrow[0] = lrow[0] * es0 + ps0;
        lrow[1] = lrow[1] * es1 + ps1;
#pragma unroll
        for (int nt = 0; nt < 8; nt++) {
            o[nt][0] *= es0; o[nt][1] *= es0;
            o[nt][2] *= es1; o[nt][3] *= es1;
        }

        // O += P @ V (1-product)
#pragma unroll
        for (int kj = 0; kj < 4; kj++) {
            uint32_t ah[4] = {ph01[2 * kj], ph23[2 * kj], ph01[2 * kj + 1], ph23[2 * kj + 1]};
#pragma unroll
            for (int dc = 0; dc < 4; dc++) {
                uint32_t vh[4];
                const uint32_t voff =
                    (uint32_t)((kj * 16 + (lane & 15)) * SWA_LDT
                               + dc * 16 + ((lane >> 4) << 3)) * 2;
                ldm4t(vh, VH + voff);
                mma_f16(o[dc * 2],     ah, vh);
                mma_f16(o[dc * 2 + 1], ah, vh + 2);
            }
        }
    }

    // normalize + write quantized y (fp16)
    const float inv0 = 1.0f / lrow[0];
    const float inv1 = 1.0f / lrow[1];
    const size_t row0 = (size_t)b * T_ + qt * 64 + w * 16 + (lane >> 2);
    const int    colb = h * HS_ + 2 * (lane & 3);
#pragma unroll
    for (int nt = 0; nt < 8; nt++) {
        *reinterpret_cast<__half2*>(yq + row0 * C_ + colb + nt * 8) =
            __floats2half2_rn(o[nt][0] * inv0, o[nt][1] * inv0);
        *reinterpret_cast<__half2*>(yq + (row0 + 8) * C_ + colb + nt * 8) =
            __floats2half2_rn(o[nt][2] * inv1, o[nt][3] * inv1);
    }
}

// ---------------------------------------------------------------------------
extern "C" void kernel_launch(void* const* d_in, const int* in_sizes, int n_in,
                              void* d_out, int out_size)
{
    const float* x      = (const float*)d_in[0];
    const float* W_attn = (const float*)d_in[1];
    const float* W_proj = (const float*)d_in[2];
    float* out = (float*)d_out;

    __half *qkvh, *qkvl, *xq, *yq, *wa, *wp;
    cudaGetSymbolAddress((void**)&qkvh, g_qkvh);
    cudaGetSymbolAddress((void**)&qkvl, g_qkvl);
    cudaGetSymbolAddress((void**)&xq,  g_xq);
    cudaGetSymbolAddress((void**)&yq,  g_yq);
    cudaGetSymbolAddress((void**)&wa,  g_wa);
    cudaGetSymbolAddress((void**)&wp,  g_wp);

    cudaFuncSetAttribute(gemm_mma<0>, cudaFuncAttributeMaxDynamicSharedMemorySize,
                         GEMM_SMEM);
    cudaFuncSetAttribute(gemm_mma<1>, cudaFuncAttributeMaxDynamicSharedMemorySize,
                         GEMM_SMEM);
    cudaFuncSetAttribute(swa_mma, cudaFuncAttributeMaxDynamicSharedMemorySize,
                         SWA_SMEM);

    const int M = B_ * T_;   // 4096

    quant_convert<<<(M * C_ / 2 + 255) / 256, 256>>>(x, xq, M * C_ / 2);
    {
        dim3 g(3 * C_ / 32, C_ / 32);
        transpose_quant<<<g, 256>>>(W_attn, wa, C_, 3 * C_);
    }
    {
        dim3 g(C_ / 32, C_ / 32);
        transpose_quant<<<g, 256>>>(W_proj, wp, C_, C_);
    }

    // qkv(split) = x @ W_attn  (M=4096, N=3072, K=1024), 1-product
    {
        dim3 g(3 * C_ / BN, M / BM);
        gemm_mma<1><<<g, 256, GEMM_SMEM>>>(xq, wa,
                                           nullptr, qkvh, qkvl, M, 3 * C_, C_);
    }

    // fused SWA -> quantized y (S 2-product; PV 1-product)
    {
        dim3 g(T_ / 64, NH_, B_);
        swa_mma<<<g, 128, SWA_SMEM>>>(qkvh, qkvl, yq);
    }

    // out = y @ W_proj  (M=4096, N=1024, K=1024), 1-product
    {
        dim3 g(C_ / BN, M / BM);
        gemm_mma<0><<<g, 256, GEMM_SMEM>>>(yq, wp,
                                           out, nullptr, nullptr, M, C_, C_);
    }
}

// round 14
// speedup vs baseline: 4.0100x; 1.0905x over previous
#include <cuda_runtime.h>
#include <cuda_fp16.h>
#include <cstdint>
#include <math.h>

#define B_   2
#define T_   2048
#define C_   1024
#define NH_  16
#define HS_  64
#define WIN_ 256

// ---------------------------------------------------------------------------
// Scratch (__device__ globals; no allocation allowed)
// ---------------------------------------------------------------------------
__device__ __half g_qkv[(size_t)B_ * T_ * 3 * C_];    // quantized qkv
__device__ __half g_xq[(size_t)B_ * T_ * C_];         // quantized x
__device__ __half g_yq[(size_t)B_ * T_ * C_];         // quantized y (from swa)
__device__ __half g_wa[(size_t)3 * C_ * C_];          // W_attn^T [3C, C] fp16
__device__ __half g_wp[(size_t)C_ * C_];              // W_proj^T [C, C]  fp16

// ---------------------------------------------------------------------------
// mma.sync / ldmatrix / cp.async helpers
// ---------------------------------------------------------------------------
__device__ __forceinline__ uint32_t smem_to_u32(const void* smem_ptr) {
    uint32_t addr;
    asm("{ .reg .u64 tmp; cvta.to.shared.u64 tmp, %1; cvt.u32.u64 %0, tmp; }"
        : "=r"(addr) : "l"(smem_ptr));
    return addr;
}
__device__ __forceinline__ void cp16(uint32_t saddr, const void* g) {
    asm volatile("cp.async.cg.shared.global [%0], [%1], 16;" :: "r"(saddr), "l"(g));
}
__device__ __forceinline__ void cp_commit() {
    asm volatile("cp.async.commit_group;" ::: "memory");
}
template <int N>
__device__ __forceinline__ void cp_wait() {
    asm volatile("cp.async.wait_group %0;" :: "n"(N) : "memory");
}
__device__ __forceinline__ void ldm4(uint32_t* r, uint32_t addr) {
    asm volatile("ldmatrix.sync.aligned.m8n8.x4.shared.b16 {%0,%1,%2,%3}, [%4];"
        : "=r"(r[0]), "=r"(r[1]), "=r"(r[2]), "=r"(r[3]) : "r"(addr));
}
__device__ __forceinline__ void ldm4t(uint32_t* r, uint32_t addr) {
    asm volatile("ldmatrix.sync.aligned.m8n8.x4.trans.shared.b16 {%0,%1,%2,%3}, [%4];"
        : "=r"(r[0]), "=r"(r[1]), "=r"(r[2]), "=r"(r[3]) : "r"(addr));
}
__device__ __forceinline__ void mma_f16(float* c, const uint32_t* a, const uint32_t* b) {
    asm volatile("mma.sync.aligned.m16n8k16.row.col.f32.f16.f16.f32 "
        "{%0,%1,%2,%3}, {%4,%5,%6,%7}, {%8,%9}, {%0,%1,%2,%3};"
        : "+f"(c[0]), "+f"(c[1]), "+f"(c[2]), "+f"(c[3])
        : "r"(a[0]), "r"(a[1]), "r"(a[2]), "r"(a[3]), "r"(b[0]), "r"(b[1]));
}

// ---------------------------------------------------------------------------
// Conversion kernels
// ---------------------------------------------------------------------------
__global__ __launch_bounds__(256) void quant_convert(const float* __restrict__ in,
                                                     __half* __restrict__ oq,
                                                     int n2)
{
    int i = blockIdx.x * blockDim.x + threadIdx.x;
    if (i >= n2) return;
    float2 v = reinterpret_cast<const float2*>(in)[i];
    reinterpret_cast<__half2*>(oq)[i] = __floats2half2_rn(v.x, v.y);
}

// in: [K,N] fp32 row-major -> out: [N,K] fp16 (transposed, K-major, quantized)
__global__ __launch_bounds__(256) void transpose_quant(const float* __restrict__ in,
                                                       __half* __restrict__ oq,
                                                       int K, int N)
{
    __shared__ float t[32][33];
    const int nt = blockIdx.x * 32;
    const int kt = blockIdx.y * 32;
    const int tx = threadIdx.x & 31;
    const int ty = threadIdx.x >> 5;
#pragma unroll
    for (int j = 0; j < 4; j++) {
        int k = kt + ty + j * 8;
        t[ty + j * 8][tx] = in[(size_t)k * N + nt + tx];
    }
    __syncthreads();
#pragma unroll
    for (int j = 0; j < 4; j++) {
        int n = nt + ty + j * 8;
        int k = kt + tx;
        oq[(size_t)n * K + k] = __float2half(t[tx][ty + j * 8]);
    }
}

// ---------------------------------------------------------------------------
// fp16 1-product GEMM (HMMA), BK=64, 3-stage cp.async (round-12/13 proven).
// CTA 128x128, 8 warps (2M x 4N), warp tile 64x32, 2 CTAs/SM.
// OUT_F16=1 -> quantized fp16 output; else fp32.
// ---------------------------------------------------------------------------
#define BM 128
#define BN 128
#define BKC 64
#define LDA 72
#define TILE_BYTES (128 * LDA * 2)           // 18432
#define OFF_A 0
#define OFF_B (TILE_BYTES)
#define STAGE_BYTES (2 * TILE_BYTES)         // 36864
#define GEMM_SMEM (3 * STAGE_BYTES)          // 110592

template <int OUT_F16>
__global__ __launch_bounds__(256, 2) void gemm_mma(
    const __half* __restrict__ Aq, const __half* __restrict__ Bq,
    float* __restrict__ C, __half* __restrict__ Cq,
    int M, int N, int K)
{
    extern __shared__ char smem[];
    const uint32_t sbase = smem_to_u32(smem);

    const int tid  = threadIdx.x;
    const int lane = tid & 31;
    const int wid  = tid >> 5;
    const int warpRow = wid & 1;
    const int warpCol = wid >> 1;
    const int m0 = blockIdx.y * BM;
    const int n0 = blockIdx.x * BN;
    const int NC = K / BKC;

    float acc[4][4][4];
#pragma unroll
    for (int mt = 0; mt < 4; mt++)
#pragma unroll
        for (int nt = 0; nt < 4; nt++)
#pragma unroll
            for (int e = 0; e < 4; e++) acc[mt][nt][e] = 0.0f;

    const uint32_t a_row = (uint32_t)(warpRow * 64 + (lane & 15));
    const uint32_t a_kof = (uint32_t)((lane >> 4) << 3);
    const uint32_t b_row = (uint32_t)(warpCol * 32 + (lane & 7) + ((lane & 16) >> 1));
    const uint32_t b_kof = (uint32_t)(lane & 8);

    auto load_stage = [&](int stg, int kk) {
        const uint32_t sb = sbase + stg * STAGE_BYTES;
#pragma unroll
        for (int i = 0; i < 4; i++) {
            const int v = tid + i * 256;
            const int row = v >> 3, seg = v & 7;
            const uint32_t so = (uint32_t)(row * LDA + seg * 8) * 2;
            cp16(sb + OFF_A + so, Aq + (size_t)(m0 + row) * K + kk + seg * 8);
            cp16(sb + OFF_B + so, Bq + (size_t)(n0 + row) * K + kk + seg * 8);
        }
        cp_commit();
    };

    load_stage(0, 0);
    load_stage(1, BKC);

    for (int c = 0; c < NC; c++) {
        if (c + 2 < NC) load_stage((c + 2) % 3, (c + 2) * BKC);
        else            cp_commit();
        cp_wait<2>();
        __syncthreads();

        const uint32_t sb = sbase + (c % 3) * STAGE_BYTES;

#pragma unroll
        for (int ks = 0; ks < 4; ks++) {
            const uint32_t akc = (uint32_t)(ks * 16) + a_kof;
            const uint32_t bkc = (uint32_t)(ks * 16) + b_kof;

            uint32_t fA[4][4];
#pragma unroll
            for (int mt = 0; mt < 4; mt++) {
                const uint32_t off = ((a_row + mt * 16) * LDA + akc) * 2;
                ldm4(fA[mt], sb + OFF_A + off);
            }
            uint32_t fB[2][4];
#pragma unroll
            for (int g = 0; g < 2; g++) {
                const uint32_t off = ((b_row + g * 16) * LDA + bkc) * 2;
                ldm4(fB[g], sb + OFF_B + off);
            }

#pragma unroll
            for (int mt = 0; mt < 4; mt++) {
#pragma unroll
                for (int nt = 0; nt < 4; nt++) {
                    mma_f16(acc[mt][nt], fA[mt], &fB[nt >> 1][(nt & 1) * 2]);
                }
            }
        }
        __syncthreads();
    }

    const int erow = m0 + warpRow * 64 + (lane >> 2);
    const int ecol = n0 + warpCol * 32 + (lane & 3) * 2;
#pragma unroll
    for (int mt = 0; mt < 4; mt++) {
#pragma unroll
        for (int nt = 0; nt < 4; nt++) {
            const size_t i0 = (size_t)(erow + mt * 16) * N + ecol + nt * 8;
            const size_t i1 = (size_t)(erow + mt * 16 + 8) * N + ecol + nt * 8;
            if (OUT_F16) {
                *reinterpret_cast<__half2*>(Cq + i0) =
                    __floats2half2_rn(acc[mt][nt][0], acc[mt][nt][1]);
                *reinterpret_cast<__half2*>(Cq + i1) =
                    __floats2half2_rn(acc[mt][nt][2], acc[mt][nt][3]);
            } else {
                *reinterpret_cast<float2*>(C + i0) = make_float2(acc[mt][nt][0], acc[mt][nt][1]);
                *reinterpret_cast<float2*>(C + i1) = make_float2(acc[mt][nt][2], acc[mt][nt][3]);
            }
        }
    }
}

// ---------------------------------------------------------------------------
// Tensor-core SWA flash attention — pure 1-product fp16.
// S = Q̂ @ K̂^T; P@V 1-product. 3 smem planes (Q/K/V hi); 4 CTAs/SM.
// ---------------------------------------------------------------------------
#define SWA_LDT 72
#define SWA_TILE_B (64 * SWA_LDT * 2)     // 9216
#define SWA_SMEM (3 * SWA_TILE_B)         // 27648

__global__ __launch_bounds__(128, 4) void swa_mma(const __half* __restrict__ qkv,
                                                  __half* __restrict__ yq)
{
    extern __shared__ char sm[];
    const uint32_t sb = smem_to_u32(sm);
    const uint32_t QH = sb;
    const uint32_t KH = sb + 1 * SWA_TILE_B;
    const uint32_t VH = sb + 2 * SWA_TILE_B;

    const int qt   = blockIdx.x;
    const int h    = blockIdx.y;
    const int b    = blockIdx.z;
    const int tid  = threadIdx.x;
    const int lane = tid & 31;
    const int w    = tid >> 5;

    const size_t st = 3 * C_;
    const __half* baseh = qkv + (size_t)b * T_ * st + (size_t)h * HS_;

    // Q tile (64 rows x 8 segs of 8 halves)
    for (int it = tid; it < 512; it += 128) {
        const int r   = it >> 3;
        const int sgo = (it & 7) * 8;
        const uint32_t off = (uint32_t)(r * SWA_LDT + sgo) * 2;
        *reinterpret_cast<uint4*>(sm + (QH - sb) + off) =
            *reinterpret_cast<const uint4*>(baseh + (size_t)(qt * 64 + r) * st + sgo);
    }

    float o[8][4];
#pragma unroll
    for (int nt = 0; nt < 8; nt++)
#pragma unroll
        for (int e = 0; e < 4; e++) o[nt][e] = 0.0f;
    float mrow[2] = {-1e30f, -1e30f};
    float lrow[2] = {0.0f, 0.0f};

    const int ig0 = qt * 64 + w * 16 + (lane >> 2);
    const int ig1 = ig0 + 8;
    const int lo_q  = qt * 64 - (WIN_ - 1);
    const int kt_lo = lo_q > 0 ? (lo_q >> 6) : 0;

    for (int kt = kt_lo; kt <= qt; kt++) {
        __syncthreads();
        for (int it = tid; it < 512; it += 128) {
            const int r   = it >> 3;
            const int sgo = (it & 7) * 8;
            const size_t g = (size_t)(kt * 64 + r) * st + sgo;
            const uint32_t off = (uint32_t)(r * SWA_LDT + sgo) * 2;
            *reinterpret_cast<uint4*>(sm + (KH - sb) + off) =
                *reinterpret_cast<const uint4*>(baseh + C_ + g);
            *reinterpret_cast<uint4*>(sm + (VH - sb) + off) =
                *reinterpret_cast<const uint4*>(baseh + 2 * C_ + g);
        }
        __syncthreads();

        float s[8][4];
#pragma unroll
        for (int nt = 0; nt < 8; nt++)
#pragma unroll
            for (int e = 0; e < 4; e++) s[nt][e] = 0.0f;

#pragma unroll
        for (int ks = 0; ks < 4; ks++) {
            uint32_t qf[4];
            const uint32_t aoff =
                (uint32_t)((w * 16 + (lane & 15)) * SWA_LDT + ks * 16 + ((lane >> 4) << 3)) * 2;
            ldm4(qf, QH + aoff);
#pragma unroll
            for (int jc = 0; jc < 4; jc++) {
                uint32_t kh[4];
                const uint32_t boff =
                    (uint32_t)((jc * 16 + (lane & 7) + ((lane & 16) >> 1)) * SWA_LDT
                               + ks * 16 + (lane & 8)) * 2;
                ldm4(kh, KH + boff);
                mma_f16(s[jc * 2],     qf, kh);
                mma_f16(s[jc * 2 + 1], qf, kh + 2);
            }
        }

        const float sc = 0.125f;
        const int jb = kt * 64 + 2 * (lane & 3);
        float tmax0 = -1e30f, tmax1 = -1e30f;
#pragma unroll
        for (int nt = 0; nt < 8; nt++) {
            const int j0 = jb + nt * 8, j1 = j0 + 1;
            const bool v00 = (j0 <= ig0) && (ig0 - j0 < WIN_);
            const bool v01 = (j1 <= ig0) && (ig0 - j1 < WIN_);
            const bool v10 = (j0 <= ig1) && (ig1 - j0 < WIN_);
            const bool v11 = (j1 <= ig1) && (ig1 - j1 < WIN_);
            s[nt][0] *= sc; s[nt][1] *= sc; s[nt][2] *= sc; s[nt][3] *= sc;
            if (v00) tmax0 = fmaxf(tmax0, s[nt][0]);
            if (v01) tmax0 = fmaxf(tmax0, s[nt][1]);
            if (v10) tmax1 = fmaxf(tmax1, s[nt][2]);
            if (v11) tmax1 = fmaxf(tmax1, s[nt][3]);
        }
        tmax0 = fmaxf(tmax0, __shfl_xor_sync(0xffffffffu, tmax0, 1));
        tmax0 = fmaxf(tmax0, __shfl_xor_sync(0xffffffffu, tmax0, 2));
        tmax1 = fmaxf(tmax1, __shfl_xor_sync(0xffffffffu, tmax1, 1));
        tmax1 = fmaxf(tmax1, __shfl_xor_sync(0xffffffffu, tmax1, 2));

        const float mn0 = fmaxf(mrow[0], tmax0);
        const float mn1 = fmaxf(mrow[1], tmax1);
        const float es0 = __expf(mrow[0] - mn0);
        const float es1 = __expf(mrow[1] - mn1);
        mrow[0] = mn0; mrow[1] = mn1;

        uint32_t ph01[8], ph23[8];
        float ps0 = 0.0f, ps1 = 0.0f;
#pragma unroll
        for (int nt = 0; nt < 8; nt++) {
            const int j0 = jb + nt * 8, j1 = j0 + 1;
            const bool v00 = (j0 <= ig0) && (ig0 - j0 < WIN_);
            const bool v01 = (j1 <= ig0) && (ig0 - j1 < WIN_);
            const bool v10 = (j0 <= ig1) && (ig1 - j0 < WIN_);
            const bool v11 = (j1 <= ig1) && (ig1 - j1 < WIN_);
            const float p00 = v00 ? __expf(s[nt][0] - mn0) : 0.0f;
            const float p01 = v01 ? __expf(s[nt][1] - mn0) : 0.0f;
            const float p10 = v10 ? __expf(s[nt][2] - mn1) : 0.0f;
            const float p11 = v11 ? __expf(s[nt][3] - mn1) : 0.0f;
            ps0 += p00 + p01;
            ps1 += p10 + p11;
            __half2 h01 = __floats2half2_rn(p00, p01);
            __half2 h23 = __floats2half2_rn(p10, p11);
            ph01[nt] = *reinterpret_cast<uint32_t*>(&h01);
            ph23[nt] = *reinterpret_cast<uint32_t*>(&h23);
        }
        ps0 += __shfl_xor_sync(0xffffffffu, ps0, 1);
        ps0 += __shfl_xor_sync(0xffffffffu, ps0, 2);
        ps1 += __shfl_xor_sync(0xffffffffu, ps1, 1);
        ps1 += __shfl_xor_sync(0xffffffffu, ps1, 2);
        lrow[0] = lrow[0] * es0 + ps0;
        lrow[1] = lrow[1] * es1 + ps1;
#pragma unroll
        for (int nt = 0; nt < 8; nt++) {
            o[nt][0] *= es0; o[nt][1] *= es0;
            o[nt][2] *= es1; o[nt][3] *= es1;
        }

        // O += P @ V (1-product)
#pragma unroll
        for (int kj = 0; kj < 4; kj++) {
            uint32_t ah[4] = {ph01[2 * kj], ph23[2 * kj], ph01[2 * kj + 1], ph23[2 * kj + 1]};
#pragma unroll
            for (int dc = 0; dc < 4; dc++) {
                uint32_t vh[4];
                const uint32_t voff =
                    (uint32_t)((kj * 16 + (lane & 15)) * SWA_LDT
                               + dc * 16 + ((lane >> 4) << 3)) * 2;
                ldm4t(vh, VH + voff);
                mma_f16(o[dc * 2],     ah, vh);
                mma_f16(o[dc * 2 + 1], ah, vh + 2);
            }
        }
    }

    // normalize + write quantized y (fp16)
    const float inv0 = 1.0f / lrow[0];
    const float inv1 = 1.0f / lrow[1];
    const size_t row0 = (size_t)b * T_ + qt * 64 + w * 16 + (lane >> 2);
    const int    colb = h * HS_ + 2 * (lane & 3);
#pragma unroll
    for (int nt = 0; nt < 8; nt++) {
        *reinterpret_cast<__half2*>(yq + row0 * C_ + colb + nt * 8) =
            __floats2half2_rn(o[nt][0] * inv0, o[nt][1] * inv0);
        *reinterpret_cast<__half2*>(yq + (row0 + 8) * C_ + colb + nt * 8) =
            __floats2half2_rn(o[nt][2] * inv1, o[nt][3] * inv1);
    }
}

// ---------------------------------------------------------------------------
extern "C" void kernel_launch(void* const* d_in, const int* in_sizes, int n_in,
                              void* d_out, int out_size)
{
    const float* x      = (const float*)d_in[0];
    const float* W_attn = (const float*)d_in[1];
    const float* W_proj = (const float*)d_in[2];
    float* out = (float*)d_out;

    __half *qkv, *xq, *yq, *wa, *wp;
    cudaGetSymbolAddress((void**)&qkv, g_qkv);
    cudaGetSymbolAddress((void**)&xq,  g_xq);
    cudaGetSymbolAddress((void**)&yq,  g_yq);
    cudaGetSymbolAddress((void**)&wa,  g_wa);
    cudaGetSymbolAddress((void**)&wp,  g_wp);

    cudaFuncSetAttribute(gemm_mma<0>, cudaFuncAttributeMaxDynamicSharedMemorySize,
                         GEMM_SMEM);
    cudaFuncSetAttribute(gemm_mma<1>, cudaFuncAttributeMaxDynamicSharedMemorySize,
                         GEMM_SMEM);
    cudaFuncSetAttribute(swa_mma, cudaFuncAttributeMaxDynamicSharedMemorySize,
                         SWA_SMEM);

    const int M = B_ * T_;   // 4096

    quant_convert<<<(M * C_ / 2 + 255) / 256, 256>>>(x, xq, M * C_ / 2);
    {
        dim3 g(3 * C_ / 32, C_ / 32);
        transpose_quant<<<g, 256>>>(W_attn, wa, C_, 3 * C_);
    }
    {
        dim3 g(C_ / 32, C_ / 32);
        transpose_quant<<<g, 256>>>(W_proj, wp, C_, C_);
    }

    // qkv(q) = x @ W_attn  (M=4096, N=3072, K=1024), 1-product, fp16 out
    {
        dim3 g(3 * C_ / BN, M / BM);
        gemm_mma<1><<<g, 256, GEMM_SMEM>>>(xq, wa, nullptr, qkv, M, 3 * C_, C_);
    }

    // fused SWA -> quantized y (pure 1-product)
    {
        dim3 g(T_ / 64, NH_, B_);
        swa_mma<<<g, 128, SWA_SMEM>>>(qkv, yq);
    }

    // out = y @ W_proj  (M=4096, N=1024, K=1024), 1-product, fp32 out
    {
        dim3 g(C_ / BN, M / BM);
        gemm_mma<0><<<g, 256, GEMM_SMEM>>>(yq, wp, out, nullptr, M, C_, C_);
    }
}

// round 15
// speedup vs baseline: 4.1480x; 1.0344x over previous
#include <cuda_runtime.h>
#include <cuda_fp16.h>
#include <cstdint>
#include <math.h>

#define B_   2
#define T_   2048
#define C_   1024
#define NH_  16
#define HS_  64
#define WIN_ 256

// ---------------------------------------------------------------------------
// Scratch (__device__ globals; no allocation allowed)
// ---------------------------------------------------------------------------
__device__ __half g_qkv[(size_t)B_ * T_ * 3 * C_];    // quantized qkv
__device__ __half g_xq[(size_t)B_ * T_ * C_];         // quantized x
__device__ __half g_yq[(size_t)B_ * T_ * C_];         // quantized y (from swa)
__device__ __half g_wa[(size_t)3 * C_ * C_];          // W_attn^T [3C, C] fp16
__device__ __half g_wp[(size_t)C_ * C_];              // W_proj^T [C, C]  fp16

// ---------------------------------------------------------------------------
// mma.sync / ldmatrix / cp.async helpers
// ---------------------------------------------------------------------------
__device__ __forceinline__ uint32_t smem_to_u32(const void* smem_ptr) {
    uint32_t addr;
    asm("{ .reg .u64 tmp; cvta.to.shared.u64 tmp, %1; cvt.u32.u64 %0, tmp; }"
        : "=r"(addr) : "l"(smem_ptr));
    return addr;
}
__device__ __forceinline__ void cp16(uint32_t saddr, const void* g) {
    asm volatile("cp.async.cg.shared.global [%0], [%1], 16;" :: "r"(saddr), "l"(g));
}
__device__ __forceinline__ void cp_commit() {
    asm volatile("cp.async.commit_group;" ::: "memory");
}
template <int N>
__device__ __forceinline__ void cp_wait() {
    asm volatile("cp.async.wait_group %0;" :: "n"(N) : "memory");
}
__device__ __forceinline__ void ldm4(uint32_t* r, uint32_t addr) {
    asm volatile("ldmatrix.sync.aligned.m8n8.x4.shared.b16 {%0,%1,%2,%3}, [%4];"
        : "=r"(r[0]), "=r"(r[1]), "=r"(r[2]), "=r"(r[3]) : "r"(addr));
}
__device__ __forceinline__ void ldm4t(uint32_t* r, uint32_t addr) {
    asm volatile("ldmatrix.sync.aligned.m8n8.x4.trans.shared.b16 {%0,%1,%2,%3}, [%4];"
        : "=r"(r[0]), "=r"(r[1]), "=r"(r[2]), "=r"(r[3]) : "r"(addr));
}
__device__ __forceinline__ void mma_f16(float* c, const uint32_t* a, const uint32_t* b) {
    asm volatile("mma.sync.aligned.m16n8k16.row.col.f32.f16.f16.f32 "
        "{%0,%1,%2,%3}, {%4,%5,%6,%7}, {%8,%9}, {%0,%1,%2,%3};"
        : "+f"(c[0]), "+f"(c[1]), "+f"(c[2]), "+f"(c[3])
        : "r"(a[0]), "r"(a[1]), "r"(a[2]), "r"(a[3]), "r"(b[0]), "r"(b[1]));
}

// ---------------------------------------------------------------------------
// Fused prep: x quant + W_attn transpose-quant + W_proj transpose-quant,
// dispatched by block-id range (one launch instead of three).
// ---------------------------------------------------------------------------
#define QB_BLOCKS 8192                     // (4096*1024/2)/256
#define WA_BLOCKS (96 * 32)                // (3072/32)*(1024/32)
#define WP_BLOCKS (32 * 32)
#define PREP_BLOCKS (QB_BLOCKS + WA_BLOCKS + WP_BLOCKS)

__device__ __forceinline__ void transpose_tile(const float* __restrict__ in,
                                               __half* __restrict__ oq,
                                               int K, int N, int ntile, int ktile,
                                               int tid, float* t /*[32*33]*/)
{
    const int nt = ntile * 32;
    const int kt = ktile * 32;
    const int tx = tid & 31;
    const int ty = tid >> 5;
#pragma unroll
    for (int j = 0; j < 4; j++) {
        int k = kt + ty + j * 8;
        t[(ty + j * 8) * 33 + tx] = in[(size_t)k * N + nt + tx];
    }
    __syncthreads();
#pragma unroll
    for (int j = 0; j < 4; j++) {
        int n = nt + ty + j * 8;
        int k = kt + tx;
        oq[(size_t)n * K + k] = __float2half(t[tx * 33 + ty + j * 8]);
    }
}

__global__ __launch_bounds__(256) void prep_all(const float* __restrict__ x,
                                                const float* __restrict__ W_attn,
                                                const float* __restrict__ W_proj,
                                                __half* __restrict__ xq,
                                                __half* __restrict__ wa,
                                                __half* __restrict__ wp)
{
    __shared__ float t[32 * 33];
    const int bid = blockIdx.x;
    const int tid = threadIdx.x;
    if (bid < QB_BLOCKS) {
        const int i = bid * 256 + tid;
        float2 v = reinterpret_cast<const float2*>(x)[i];
        reinterpret_cast<__half2*>(xq)[i] = __floats2half2_rn(v.x, v.y);
    } else if (bid < QB_BLOCKS + WA_BLOCKS) {
        const int idx = bid - QB_BLOCKS;
        transpose_tile(W_attn, wa, C_, 3 * C_, idx % 96, idx / 96, tid, t);
    } else {
        const int idx = bid - (QB_BLOCKS + WA_BLOCKS);
        transpose_tile(W_proj, wp, C_, C_, idx % 32, idx / 32, tid, t);
    }
}

// ---------------------------------------------------------------------------
// fp16 1-product GEMM (HMMA), BK=64, 3-stage cp.async.
// CTA 128x128, 128 threads, 4 warps (2M x 2N), warp tile 64x64 (4:1 ldm:MMA),
// 2 CTAs/SM. OUT_F16=1 -> quantized fp16 output; else fp32.
// ---------------------------------------------------------------------------
#define BM 128
#define BN 128
#define BKC 64
#define LDA 72
#define TILE_BYTES (128 * LDA * 2)           // 18432
#define OFF_A 0
#define OFF_B (TILE_BYTES)
#define STAGE_BYTES (2 * TILE_BYTES)         // 36864
#define GEMM_SMEM (3 * STAGE_BYTES)          // 110592

template <int OUT_F16>
__global__ __launch_bounds__(128, 2) void gemm_mma(
    const __half* __restrict__ Aq, const __half* __restrict__ Bq,
    float* __restrict__ C, __half* __restrict__ Cq,
    int M, int N, int K)
{
    extern __shared__ char smem[];
    const uint32_t sbase = smem_to_u32(smem);

    const int tid  = threadIdx.x;
    const int lane = tid & 31;
    const int wid  = tid >> 5;
    const int warpRow = wid & 1;     // 2 in M
    const int warpCol = wid >> 1;    // 2 in N
    const int m0 = blockIdx.y * BM;
    const int n0 = blockIdx.x * BN;
    const int NC = K / BKC;

    float acc[4][8][4];
#pragma unroll
    for (int mt = 0; mt < 4; mt++)
#pragma unroll
        for (int nt = 0; nt < 8; nt++)
#pragma unroll
            for (int e = 0; e < 4; e++) acc[mt][nt][e] = 0.0f;

    const uint32_t a_row  = (uint32_t)(warpRow * 64 + (lane & 15));
    const uint32_t a_kof  = (uint32_t)((lane >> 4) << 3);
    const uint32_t b_rbase = (uint32_t)(warpCol * 64 + (lane & 7) + ((lane & 16) >> 1));
    const uint32_t b_kof  = (uint32_t)(lane & 8);

    auto load_stage = [&](int stg, int kk) {
        const uint32_t sb = sbase + stg * STAGE_BYTES;
#pragma unroll
        for (int i = 0; i < 8; i++) {
            const int v = tid + i * 128;
            const int row = v >> 3, seg = v & 7;
            const uint32_t so = (uint32_t)(row * LDA + seg * 8) * 2;
            cp16(sb + OFF_A + so, Aq + (size_t)(m0 + row) * K + kk + seg * 8);
            cp16(sb + OFF_B + so, Bq + (size_t)(n0 + row) * K + kk + seg * 8);
        }
        cp_commit();
    };

    load_stage(0, 0);
    load_stage(1, BKC);

    for (int c = 0; c < NC; c++) {
        if (c + 2 < NC) load_stage((c + 2) % 3, (c + 2) * BKC);
        else            cp_commit();
        cp_wait<2>();
        __syncthreads();

        const uint32_t sb = sbase + (c % 3) * STAGE_BYTES;

#pragma unroll
        for (int ks = 0; ks < 4; ks++) {
            const uint32_t akc = (uint32_t)(ks * 16) + a_kof;
            const uint32_t bkc = (uint32_t)(ks * 16) + b_kof;

            uint32_t fA[4][4];
#pragma unroll
            for (int mt = 0; mt < 4; mt++) {
                const uint32_t off = ((a_row + mt * 16) * LDA + akc) * 2;
                ldm4(fA[mt], sb + OFF_A + off);
            }
            uint32_t fB[4][4];
#pragma unroll
            for (int g = 0; g < 4; g++) {
                const uint32_t off = ((b_rbase + g * 16) * LDA + bkc) * 2;
                ldm4(fB[g], sb + OFF_B + off);
            }

#pragma unroll
            for (int mt = 0; mt < 4; mt++) {
#pragma unroll
                for (int nt = 0; nt < 8; nt++) {
                    mma_f16(acc[mt][nt], fA[mt], &fB[nt >> 1][(nt & 1) * 2]);
                }
            }
        }
        __syncthreads();
    }

    const int erow = m0 + warpRow * 64 + (lane >> 2);
    const int ecol = n0 + warpCol * 64 + (lane & 3) * 2;
#pragma unroll
    for (int mt = 0; mt < 4; mt++) {
#pragma unroll
        for (int nt = 0; nt < 8; nt++) {
            const size_t i0 = (size_t)(erow + mt * 16) * N + ecol + nt * 8;
            const size_t i1 = (size_t)(erow + mt * 16 + 8) * N + ecol + nt * 8;
            if (OUT_F16) {
                *reinterpret_cast<__half2*>(Cq + i0) =
                    __floats2half2_rn(acc[mt][nt][0], acc[mt][nt][1]);
                *reinterpret_cast<__half2*>(Cq + i1) =
                    __floats2half2_rn(acc[mt][nt][2], acc[mt][nt][3]);
            } else {
                *reinterpret_cast<float2*>(C + i0) = make_float2(acc[mt][nt][0], acc[mt][nt][1]);
                *reinterpret_cast<float2*>(C + i1) = make_float2(acc[mt][nt][2], acc[mt][nt][3]);
            }
        }
    }
}

// ---------------------------------------------------------------------------
// Tensor-core SWA flash attention — pure 1-product fp16 (round-14 proven).
// ---------------------------------------------------------------------------
#define SWA_LDT 72
#define SWA_TILE_B (64 * SWA_LDT * 2)     // 9216
#define SWA_SMEM (3 * SWA_TILE_B)         // 27648

__global__ __launch_bounds__(128, 4) void swa_mma(const __half* __restrict__ qkv,
                                                  __half* __restrict__ yq)
{
    extern __shared__ char sm[];
    const uint32_t sb = smem_to_u32(sm);
    const uint32_t QH = sb;
    const uint32_t KH = sb + 1 * SWA_TILE_B;
    const uint32_t VH = sb + 2 * SWA_TILE_B;

    const int qt   = blockIdx.x;
    const int h    = blockIdx.y;
    const int b    = blockIdx.z;
    const int tid  = threadIdx.x;
    const int lane = tid & 31;
    const int w    = tid >> 5;

    const size_t st = 3 * C_;
    const __half* baseh = qkv + (size_t)b * T_ * st + (size_t)h * HS_;

    for (int it = tid; it < 512; it += 128) {
        const int r   = it >> 3;
        const int sgo = (it & 7) * 8;
        const uint32_t off = (uint32_t)(r * SWA_LDT + sgo) * 2;
        *reinterpret_cast<uint4*>(sm + (QH - sb) + off) =
            *reinterpret_cast<const uint4*>(baseh + (size_t)(qt * 64 + r) * st + sgo);
    }

    float o[8][4];
#pragma unroll
    for (int nt = 0; nt < 8; nt++)
#pragma unroll
        for (int e = 0; e < 4; e++) o[nt][e] = 0.0f;
    float mrow[2] = {-1e30f, -1e30f};
    float lrow[2] = {0.0f, 0.0f};

    const int ig0 = qt * 64 + w * 16 + (lane >> 2);
    const int ig1 = ig0 + 8;
    const int lo_q  = qt * 64 - (WIN_ - 1);
    const int kt_lo = lo_q > 0 ? (lo_q >> 6) : 0;

    for (int kt = kt_lo; kt <= qt; kt++) {
        __syncthreads();
        for (int it = tid; it < 512; it += 128) {
            const int r   = it >> 3;
            const int sgo = (it & 7) * 8;
            const size_t g = (size_t)(kt * 64 + r) * st + sgo;
            const uint32_t off = (uint32_t)(r * SWA_LDT + sgo) * 2;
            *reinterpret_cast<uint4*>(sm + (KH - sb) + off) =
                *reinterpret_cast<const uint4*>(baseh + C_ + g);
            *reinterpret_cast<uint4*>(sm + (VH - sb) + off) =
                *reinterpret_cast<const uint4*>(baseh + 2 * C_ + g);
        }
        __syncthreads();

        float s[8][4];
#pragma unroll
        for (int nt = 0; nt < 8; nt++)
#pragma unroll
            for (int e = 0; e < 4; e++) s[nt][e] = 0.0f;

#pragma unroll
        for (int ks = 0; ks < 4; ks++) {
            uint32_t qf[4];
            const uint32_t aoff =
                (uint32_t)((w * 16 + (lane & 15)) * SWA_LDT + ks * 16 + ((lane >> 4) << 3)) * 2;
            ldm4(qf, QH + aoff);
#pragma unroll
            for (int jc = 0; jc < 4; jc++) {
                uint32_t kh[4];
                const uint32_t boff =
                    (uint32_t)((jc * 16 + (lane & 7) + ((lane & 16) >> 1)) * SWA_LDT
                               + ks * 16 + (lane & 8)) * 2;
                ldm4(kh, KH + boff);
                mma_f16(s[jc * 2],     qf, kh);
                mma_f16(s[jc * 2 + 1], qf, kh + 2);
            }
        }

        const float sc = 0.125f;
        const int jb = kt * 64 + 2 * (lane & 3);
        float tmax0 = -1e30f, tmax1 = -1e30f;
#pragma unroll
        for (int nt = 0; nt < 8; nt++) {
            const int j0 = jb + nt * 8, j1 = j0 + 1;
            const bool v00 = (j0 <= ig0) && (ig0 - j0 < WIN_);
            const bool v01 = (j1 <= ig0) && (ig0 - j1 < WIN_);
            const bool v10 = (j0 <= ig1) && (ig1 - j0 < WIN_);
            const bool v11 = (j1 <= ig1) && (ig1 - j1 < WIN_);
            s[nt][0] *= sc; s[nt][1] *= sc; s[nt][2] *= sc; s[nt][3] *= sc;
            if (v00) tmax0 = fmaxf(tmax0, s[nt][0]);
            if (v01) tmax0 = fmaxf(tmax0, s[nt][1]);
            if (v10) tmax1 = fmaxf(tmax1, s[nt][2]);
            if (v11) tmax1 = fmaxf(tmax1, s[nt][3]);
        }
        tmax0 = fmaxf(tmax0, __shfl_xor_sync(0xffffffffu, tmax0, 1));
        tmax0 = fmaxf(tmax0, __shfl_xor_sync(0xffffffffu, tmax0, 2));
        tmax1 = fmaxf(tmax1, __shfl_xor_sync(0xffffffffu, tmax1, 1));
        tmax1 = fmaxf(tmax1, __shfl_xor_sync(0xffffffffu, tmax1, 2));

        const float mn0 = fmaxf(mrow[0], tmax0);
        const float mn1 = fmaxf(mrow[1], tmax1);
        const float es0 = __expf(mrow[0] - mn0);
        const float es1 = __expf(mrow[1] - mn1);
        mrow[0] = mn0; mrow[1] = mn1;

        uint32_t ph01[8], ph23[8];
        float ps0 = 0.0f, ps1 = 0.0f;
#pragma unroll
        for (int nt = 0; nt < 8; nt++) {
            const int j0 = jb + nt * 8, j1 = j0 + 1;
            const bool v00 = (j0 <= ig0) && (ig0 - j0 < WIN_);
            const bool v01 = (j1 <= ig0) && (ig0 - j1 < WIN_);
            const bool v10 = (j0 <= ig1) && (ig1 - j0 < WIN_);
            const bool v11 = (j1 <= ig1) && (ig1 - j1 < WIN_);
            const float p00 = v00 ? __expf(s[nt][0] - mn0) : 0.0f;
            const float p01 = v01 ? __expf(s[nt][1] - mn0) : 0.0f;
            const float p10 = v10 ? __expf(s[nt][2] - mn1) : 0.0f;
            const float p11 = v11 ? __expf(s[nt][3] - mn1) : 0.0f;
            ps0 += p00 + p01;
            ps1 += p10 + p11;
            __half2 h01 = __floats2half2_rn(p00, p01);
            __half2 h23 = __floats2half2_rn(p10, p11);
            ph01[nt] = *reinterpret_cast<uint32_t*>(&h01);
            ph23[nt] = *reinterpret_cast<uint32_t*>(&h23);
        }
        ps0 += __shfl_xor_sync(0xffffffffu, ps0, 1);
        ps0 += __shfl_xor_sync(0xffffffffu, ps0, 2);
        ps1 += __shfl_xor_sync(0xffffffffu, ps1, 1);
        ps1 += __shfl_xor_sync(0xffffffffu, ps1, 2);
        lrow[0] = lrow[0] * es0 + ps0;
        lrow[1] = lrow[1] * es1 + ps1;
#pragma unroll
        for (int nt = 0; nt < 8; nt++) {
            o[nt][0] *= es0; o[nt][1] *= es0;
            o[nt][2] *= es1; o[nt][3] *= es1;
        }

#pragma unroll
        for (int kj = 0; kj < 4; kj++) {
            uint32_t ah[4] = {ph01[2 * kj], ph23[2 * kj], ph01[2 * kj + 1], ph23[2 * kj + 1]};
#pragma unroll
            for (int dc = 0; dc < 4; dc++) {
                uint32_t vh[4];
                const uint32_t voff =
                    (uint32_t)((kj * 16 + (lane & 15)) * SWA_LDT
                               + dc * 16 + ((lane >> 4) << 3)) * 2;
                ldm4t(vh, VH + voff);
                mma_f16(o[dc * 2],     ah, vh);
                mma_f16(o[dc * 2 + 1], ah, vh + 2);
            }
        }
    }

    const float inv0 = 1.0f / lrow[0];
    const float inv1 = 1.0f / lrow[1];
    const size_t row0 = (size_t)b * T_ + qt * 64 + w * 16 + (lane >> 2);
    const int    colb = h * HS_ + 2 * (lane & 3);
#pragma unroll
    for (int nt = 0; nt < 8; nt++) {
        *reinterpret_cast<__half2*>(yq + row0 * C_ + colb + nt * 8) =
            __floats2half2_rn(o[nt][0] * inv0, o[nt][1] * inv0);
        *reinterpret_cast<__half2*>(yq + (row0 + 8) * C_ + colb + nt * 8) =
            __floats2half2_rn(o[nt][2] * inv1, o[nt][3] * inv1);
    }
}

// ---------------------------------------------------------------------------
extern "C" void kernel_launch(void* const* d_in, const int* in_sizes, int n_in,
                              void* d_out, int out_size)
{
    const float* x      = (const float*)d_in[0];
    const float* W_attn = (const float*)d_in[1];
    const float* W_proj = (const float*)d_in[2];
    float* out = (float*)d_out;

    __half *qkv, *xq, *yq, *wa, *wp;
    cudaGetSymbolAddress((void**)&qkv, g_qkv);
    cudaGetSymbolAddress((void**)&xq,  g_xq);
    cudaGetSymbolAddress((void**)&yq,  g_yq);
    cudaGetSymbolAddress((void**)&wa,  g_wa);
    cudaGetSymbolAddress((void**)&wp,  g_wp);

    cudaFuncSetAttribute(gemm_mma<0>, cudaFuncAttributeMaxDynamicSharedMemorySize,
                         GEMM_SMEM);
    cudaFuncSetAttribute(gemm_mma<1>, cudaFuncAttributeMaxDynamicSharedMemorySize,
                         GEMM_SMEM);
    cudaFuncSetAttribute(swa_mma, cudaFuncAttributeMaxDynamicSharedMemorySize,
                         SWA_SMEM);

    const int M = B_ * T_;   // 4096

    // fused prep: x quant + both weight transposes, one launch
    prep_all<<<PREP_BLOCKS, 256>>>(x, W_attn, W_proj, xq, wa, wp);

    // qkv(q) = x @ W_attn  (M=4096, N=3072, K=1024), 1-product, fp16 out
    {
        dim3 g(3 * C_ / BN, M / BM);
        gemm_mma<1><<<g, 128, GEMM_SMEM>>>(xq, wa, nullptr, qkv, M, 3 * C_, C_);
    }

    // fused SWA -> quantized y (pure 1-product)
    {
        dim3 g(T_ / 64, NH_, B_);
        swa_mma<<<g, 128, SWA_SMEM>>>(qkv, yq);
    }

    // out = y @ W_proj  (M=4096, N=1024, K=1024), 1-product, fp32 out
    {
        dim3 g(C_ / BN, M / BM);
        gemm_mma<0><<<g, 128, GEMM_SMEM>>>(yq, wp, out, nullptr, M, C_, C_);
    }
}

// round 16
// speedup vs baseline: 4.1573x; 1.0022x over previous
#include <cuda_runtime.h>
#include <cuda_fp16.h>
#include <cstdint>
#include <math.h>

#define B_   2
#define T_   2048
#define C_   1024
#define NH_  16
#define HS_  64
#define WIN_ 256

// ---------------------------------------------------------------------------
// Scratch (__device__ globals; no allocation allowed)
// ---------------------------------------------------------------------------
__device__ __half g_qkv[(size_t)B_ * T_ * 3 * C_];    // quantized qkv
__device__ __half g_xq[(size_t)B_ * T_ * C_];         // quantized x
__device__ __half g_yq[(size_t)B_ * T_ * C_];         // quantized y (from swa)
__device__ __half g_wa[(size_t)3 * C_ * C_];          // W_attn^T [3C, C] fp16
__device__ __half g_wp[(size_t)C_ * C_];              // W_proj^T [C, C]  fp16

// ---------------------------------------------------------------------------
// mma.sync / ldmatrix / cp.async helpers
// ---------------------------------------------------------------------------
__device__ __forceinline__ uint32_t smem_to_u32(const void* smem_ptr) {
    uint32_t addr;
    asm("{ .reg .u64 tmp; cvta.to.shared.u64 tmp, %1; cvt.u32.u64 %0, tmp; }"
        : "=r"(addr) : "l"(smem_ptr));
    return addr;
}
__device__ __forceinline__ void cp16(uint32_t saddr, const void* g) {
    asm volatile("cp.async.cg.shared.global [%0], [%1], 16;" :: "r"(saddr), "l"(g));
}
__device__ __forceinline__ void cp_commit() {
    asm volatile("cp.async.commit_group;" ::: "memory");
}
template <int N>
__device__ __forceinline__ void cp_wait() {
    asm volatile("cp.async.wait_group %0;" :: "n"(N) : "memory");
}
__device__ __forceinline__ void ldm4(uint32_t* r, uint32_t addr) {
    asm volatile("ldmatrix.sync.aligned.m8n8.x4.shared.b16 {%0,%1,%2,%3}, [%4];"
        : "=r"(r[0]), "=r"(r[1]), "=r"(r[2]), "=r"(r[3]) : "r"(addr));
}
__device__ __forceinline__ void ldm4t(uint32_t* r, uint32_t addr) {
    asm volatile("ldmatrix.sync.aligned.m8n8.x4.trans.shared.b16 {%0,%1,%2,%3}, [%4];"
        : "=r"(r[0]), "=r"(r[1]), "=r"(r[2]), "=r"(r[3]) : "r"(addr));
}
__device__ __forceinline__ void mma_f16(float* c, const uint32_t* a, const uint32_t* b) {
    asm volatile("mma.sync.aligned.m16n8k16.row.col.f32.f16.f16.f32 "
        "{%0,%1,%2,%3}, {%4,%5,%6,%7}, {%8,%9}, {%0,%1,%2,%3};"
        : "+f"(c[0]), "+f"(c[1]), "+f"(c[2]), "+f"(c[3])
        : "r"(a[0]), "r"(a[1]), "r"(a[2]), "r"(a[3]), "r"(b[0]), "r"(b[1]));
}

// ---------------------------------------------------------------------------
// Fused prep: x quant + W_attn transpose-quant + W_proj transpose-quant.
// ---------------------------------------------------------------------------
#define QB_BLOCKS 8192
#define WA_BLOCKS (96 * 32)
#define WP_BLOCKS (32 * 32)
#define PREP_BLOCKS (QB_BLOCKS + WA_BLOCKS + WP_BLOCKS)

__device__ __forceinline__ void transpose_tile(const float* __restrict__ in,
                                               __half* __restrict__ oq,
                                               int K, int N, int ntile, int ktile,
                                               int tid, float* t /*[32*33]*/)
{
    const int nt = ntile * 32;
    const int kt = ktile * 32;
    const int tx = tid & 31;
    const int ty = tid >> 5;
#pragma unroll
    for (int j = 0; j < 4; j++) {
        int k = kt + ty + j * 8;
        t[(ty + j * 8) * 33 + tx] = in[(size_t)k * N + nt + tx];
    }
    __syncthreads();
#pragma unroll
    for (int j = 0; j < 4; j++) {
        int n = nt + ty + j * 8;
        int k = kt + tx;
        oq[(size_t)n * K + k] = __float2half(t[tx * 33 + ty + j * 8]);
    }
}

__global__ __launch_bounds__(256) void prep_all(const float* __restrict__ x,
                                                const float* __restrict__ W_attn,
                                                const float* __restrict__ W_proj,
                                                __half* __restrict__ xq,
                                                __half* __restrict__ wa,
                                                __half* __restrict__ wp)
{
    __shared__ float t[32 * 33];
    const int bid = blockIdx.x;
    const int tid = threadIdx.x;
    if (bid < QB_BLOCKS) {
        const int i = bid * 256 + tid;
        float2 v = reinterpret_cast<const float2*>(x)[i];
        reinterpret_cast<__half2*>(xq)[i] = __floats2half2_rn(v.x, v.y);
    } else if (bid < QB_BLOCKS + WA_BLOCKS) {
        const int idx = bid - QB_BLOCKS;
        transpose_tile(W_attn, wa, C_, 3 * C_, idx % 96, idx / 96, tid, t);
    } else {
        const int idx = bid - (QB_BLOCKS + WA_BLOCKS);
        transpose_tile(W_proj, wp, C_, C_, idx % 32, idx / 32, tid, t);
    }
}

// ---------------------------------------------------------------------------
// Shared gemm geometry constants
// ---------------------------------------------------------------------------
#define BM 128
#define BN 128
#define BKC 64
#define LDA 72
#define TILE_BYTES (128 * LDA * 2)           // 18432
#define OFF_A 0
#define OFF_B (TILE_BYTES)
#define STAGE_BYTES (2 * TILE_BYTES)         // 36864
#define GEMM_SMEM (3 * STAGE_BYTES)          // 110592

// ---------------------------------------------------------------------------
// GEMM variant A (for QKV, big grid): 128 threads, 4 warps (2Mx2N),
// warp tile 64x64 (4:1 ldm:MMA). fp16 quantized output.
// ---------------------------------------------------------------------------
__global__ __launch_bounds__(128, 2) void gemm_w64(
    const __half* __restrict__ Aq, const __half* __restrict__ Bq,
    __half* __restrict__ Cq, int M, int N, int K)
{
    extern __shared__ char smem[];
    const uint32_t sbase = smem_to_u32(smem);

    const int tid  = threadIdx.x;
    const int lane = tid & 31;
    const int wid  = tid >> 5;
    const int warpRow = wid & 1;
    const int warpCol = wid >> 1;
    const int m0 = blockIdx.y * BM;
    const int n0 = blockIdx.x * BN;
    const int NC = K / BKC;

    float acc[4][8][4];
#pragma unroll
    for (int mt = 0; mt < 4; mt++)
#pragma unroll
        for (int nt = 0; nt < 8; nt++)
#pragma unroll
            for (int e = 0; e < 4; e++) acc[mt][nt][e] = 0.0f;

    const uint32_t a_row   = (uint32_t)(warpRow * 64 + (lane & 15));
    const uint32_t a_kof   = (uint32_t)((lane >> 4) << 3);
    const uint32_t b_rbase = (uint32_t)(warpCol * 64 + (lane & 7) + ((lane & 16) >> 1));
    const uint32_t b_kof   = (uint32_t)(lane & 8);

    auto load_stage = [&](int stg, int kk) {
        const uint32_t sb = sbase + stg * STAGE_BYTES;
#pragma unroll
        for (int i = 0; i < 8; i++) {
            const int v = tid + i * 128;
            const int row = v >> 3, seg = v & 7;
            const uint32_t so = (uint32_t)(row * LDA + seg * 8) * 2;
            cp16(sb + OFF_A + so, Aq + (size_t)(m0 + row) * K + kk + seg * 8);
            cp16(sb + OFF_B + so, Bq + (size_t)(n0 + row) * K + kk + seg * 8);
        }
        cp_commit();
    };

    load_stage(0, 0);
    load_stage(1, BKC);

    for (int c = 0; c < NC; c++) {
        if (c + 2 < NC) load_stage((c + 2) % 3, (c + 2) * BKC);
        else            cp_commit();
        cp_wait<2>();
        __syncthreads();

        const uint32_t sb = sbase + (c % 3) * STAGE_BYTES;

#pragma unroll
        for (int ks = 0; ks < 4; ks++) {
            const uint32_t akc = (uint32_t)(ks * 16) + a_kof;
            const uint32_t bkc = (uint32_t)(ks * 16) + b_kof;

            uint32_t fA[4][4];
#pragma unroll
            for (int mt = 0; mt < 4; mt++) {
                const uint32_t off = ((a_row + mt * 16) * LDA + akc) * 2;
                ldm4(fA[mt], sb + OFF_A + off);
            }
            uint32_t fB[4][4];
#pragma unroll
            for (int g = 0; g < 4; g++) {
                const uint32_t off = ((b_rbase + g * 16) * LDA + bkc) * 2;
                ldm4(fB[g], sb + OFF_B + off);
            }

#pragma unroll
            for (int mt = 0; mt < 4; mt++) {
#pragma unroll
                for (int nt = 0; nt < 8; nt++) {
                    mma_f16(acc[mt][nt], fA[mt], &fB[nt >> 1][(nt & 1) * 2]);
                }
            }
        }
        __syncthreads();
    }

    const int erow = m0 + warpRow * 64 + (lane >> 2);
    const int ecol = n0 + warpCol * 64 + (lane & 3) * 2;
#pragma unroll
    for (int mt = 0; mt < 4; mt++) {
#pragma unroll
        for (int nt = 0; nt < 8; nt++) {
            const size_t i0 = (size_t)(erow + mt * 16) * N + ecol + nt * 8;
            const size_t i1 = (size_t)(erow + mt * 16 + 8) * N + ecol + nt * 8;
            *reinterpret_cast<__half2*>(Cq + i0) =
                __floats2half2_rn(acc[mt][nt][0], acc[mt][nt][1]);
            *reinterpret_cast<__half2*>(Cq + i1) =
                __floats2half2_rn(acc[mt][nt][2], acc[mt][nt][3]);
        }
    }
}

// ---------------------------------------------------------------------------
// GEMM variant B (for proj, small grid): 256 threads, 8 warps (2Mx4N),
// warp tile 64x32, 16 warps/SM (round-14 proven). fp32 output.
// ---------------------------------------------------------------------------
__global__ __launch_bounds__(256, 2) void gemm_w32(
    const __half* __restrict__ Aq, const __half* __restrict__ Bq,
    float* __restrict__ C, int M, int N, int K)
{
    extern __shared__ char smem[];
    const uint32_t sbase = smem_to_u32(smem);

    const int tid  = threadIdx.x;
    const int lane = tid & 31;
    const int wid  = tid >> 5;
    const int warpRow = wid & 1;
    const int warpCol = wid >> 1;
    const int m0 = blockIdx.y * BM;
    const int n0 = blockIdx.x * BN;
    const int NC = K / BKC;

    float acc[4][4][4];
#pragma unroll
    for (int mt = 0; mt < 4; mt++)
#pragma unroll
        for (int nt = 0; nt < 4; nt++)
#pragma unroll
            for (int e = 0; e < 4; e++) acc[mt][nt][e] = 0.0f;

    const uint32_t a_row = (uint32_t)(warpRow * 64 + (lane & 15));
    const uint32_t a_kof = (uint32_t)((lane >> 4) << 3);
    const uint32_t b_row = (uint32_t)(warpCol * 32 + (lane & 7) + ((lane & 16) >> 1));
    const uint32_t b_kof = (uint32_t)(lane & 8);

    auto load_stage = [&](int stg, int kk) {
        const uint32_t sb = sbase + stg * STAGE_BYTES;
#pragma unroll
        for (int i = 0; i < 4; i++) {
            const int v = tid + i * 256;
            const int row = v >> 3, seg = v & 7;
            const uint32_t so = (uint32_t)(row * LDA + seg * 8) * 2;
            cp16(sb + OFF_A + so, Aq + (size_t)(m0 + row) * K + kk + seg * 8);
            cp16(sb + OFF_B + so, Bq + (size_t)(n0 + row) * K + kk + seg * 8);
        }
        cp_commit();
    };

    load_stage(0, 0);
    load_stage(1, BKC);

    for (int c = 0; c < NC; c++) {
        if (c + 2 < NC) load_stage((c + 2) % 3, (c + 2) * BKC);
        else            cp_commit();
        cp_wait<2>();
        __syncthreads();

        const uint32_t sb = sbase + (c % 3) * STAGE_BYTES;

#pragma unroll
        for (int ks = 0; ks < 4; ks++) {
            const uint32_t akc = (uint32_t)(ks * 16) + a_kof;
            const uint32_t bkc = (uint32_t)(ks * 16) + b_kof;

            uint32_t fA[4][4];
#pragma unroll
            for (int mt = 0; mt < 4; mt++) {
                const uint32_t off = ((a_row + mt * 16) * LDA + akc) * 2;
                ldm4(fA[mt], sb + OFF_A + off);
            }
            uint32_t fB[2][4];
#pragma unroll
            for (int g = 0; g < 2; g++) {
                const uint32_t off = ((b_row + g * 16) * LDA + bkc) * 2;
                ldm4(fB[g], sb + OFF_B + off);
            }

#pragma unroll
            for (int mt = 0; mt < 4; mt++) {
#pragma unroll
                for (int nt = 0; nt < 4; nt++) {
                    mma_f16(acc[mt][nt], fA[mt], &fB[nt >> 1][(nt & 1) * 2]);
                }
            }
        }
        __syncthreads();
    }

    const int erow = m0 + warpRow * 64 + (lane >> 2);
    const int ecol = n0 + warpCol * 32 + (lane & 3) * 2;
#pragma unroll
    for (int mt = 0; mt < 4; mt++) {
#pragma unroll
        for (int nt = 0; nt < 4; nt++) {
            const size_t i0 = (size_t)(erow + mt * 16) * N + ecol + nt * 8;
            const size_t i1 = (size_t)(erow + mt * 16 + 8) * N + ecol + nt * 8;
            *reinterpret_cast<float2*>(C + i0) = make_float2(acc[mt][nt][0], acc[mt][nt][1]);
            *reinterpret_cast<float2*>(C + i1) = make_float2(acc[mt][nt][2], acc[mt][nt][3]);
        }
    }
}

// ---------------------------------------------------------------------------
// Tensor-core SWA flash attention — pure 1-product fp16 (round-14/15 proven).
// ---------------------------------------------------------------------------
#define SWA_LDT 72
#define SWA_TILE_B (64 * SWA_LDT * 2)     // 9216
#define SWA_SMEM (3 * SWA_TILE_B)         // 27648

__global__ __launch_bounds__(128, 4) void swa_mma(const __half* __restrict__ qkv,
                                                  __half* __restrict__ yq)
{
    extern __shared__ char sm[];
    const uint32_t sb = smem_to_u32(sm);
    const uint32_t QH = sb;
    const uint32_t KH = sb + 1 * SWA_TILE_B;
    const uint32_t VH = sb + 2 * SWA_TILE_B;

    const int qt   = blockIdx.x;
    const int h    = blockIdx.y;
    const int b    = blockIdx.z;
    const int tid  = threadIdx.x;
    const int lane = tid & 31;
    const int w    = tid >> 5;

    const size_t st = 3 * C_;
    const __half* baseh = qkv + (size_t)b * T_ * st + (size_t)h * HS_;

    for (int it = tid; it < 512; it += 128) {
        const int r   = it >> 3;
        const int sgo = (it & 7) * 8;
        const uint32_t off = (uint32_t)(r * SWA_LDT + sgo) * 2;
        *reinterpret_cast<uint4*>(sm + (QH - sb) + off) =
            *reinterpret_cast<const uint4*>(baseh + (size_t)(qt * 64 + r) * st + sgo);
    }

    float o[8][4];
#pragma unroll
    for (int nt = 0; nt < 8; nt++)
#pragma unroll
        for (int e = 0; e < 4; e++) o[nt][e] = 0.0f;
    float mrow[2] = {-1e30f, -1e30f};
    float lrow[2] = {0.0f, 0.0f};

    const int ig0 = qt * 64 + w * 16 + (lane >> 2);
    const int ig1 = ig0 + 8;
    const int lo_q  = qt * 64 - (WIN_ - 1);
    const int kt_lo = lo_q > 0 ? (lo_q >> 6) : 0;

    for (int kt = kt_lo; kt <= qt; kt++) {
        __syncthreads();
        for (int it = tid; it < 512; it += 128) {
            const int r   = it >> 3;
            const int sgo = (it & 7) * 8;
            const size_t g = (size_t)(kt * 64 + r) * st + sgo;
            const uint32_t off = (uint32_t)(r * SWA_LDT + sgo) * 2;
            *reinterpret_cast<uint4*>(sm + (KH - sb) + off) =
                *reinterpret_cast<const uint4*>(baseh + C_ + g);
            *reinterpret_cast<uint4*>(sm + (VH - sb) + off) =
                *reinterpret_cast<const uint4*>(baseh + 2 * C_ + g);
        }
        __syncthreads();

        float s[8][4];
#pragma unroll
        for (int nt = 0; nt < 8; nt++)
#pragma unroll
            for (int e = 0; e < 4; e++) s[nt][e] = 0.0f;

#pragma unroll
        for (int ks = 0; ks < 4; ks++) {
            uint32_t qf[4];
            const uint32_t aoff =
                (uint32_t)((w * 16 + (lane & 15)) * SWA_LDT + ks * 16 + ((lane >> 4) << 3)) * 2;
            ldm4(qf, QH + aoff);
#pragma unroll
            for (int jc = 0; jc < 4; jc++) {
                uint32_t kh[4];
                const uint32_t boff =
                    (uint32_t)((jc * 16 + (lane & 7) + ((lane & 16) >> 1)) * SWA_LDT
                               + ks * 16 + (lane & 8)) * 2;
                ldm4(kh, KH + boff);
                mma_f16(s[jc * 2],     qf, kh);
                mma_f16(s[jc * 2 + 1], qf, kh + 2);
            }
        }

        const float sc = 0.125f;
        const int jb = kt * 64 + 2 * (lane & 3);
        float tmax0 = -1e30f, tmax1 = -1e30f;
#pragma unroll
        for (int nt = 0; nt < 8; nt++) {
            const int j0 = jb + nt * 8, j1 = j0 + 1;
            const bool v00 = (j0 <= ig0) && (ig0 - j0 < WIN_);
            const bool v01 = (j1 <= ig0) && (ig0 - j1 < WIN_);
            const bool v10 = (j0 <= ig1) && (ig1 - j0 < WIN_);
            const bool v11 = (j1 <= ig1) && (ig1 - j1 < WIN_);
            s[nt][0] *= sc; s[nt][1] *= sc; s[nt][2] *= sc; s[nt][3] *= sc;
            if (v00) tmax0 = fmaxf(tmax0, s[nt][0]);
            if (v01) tmax0 = fmaxf(tmax0, s[nt][1]);
            if (v10) tmax1 = fmaxf(tmax1, s[nt][2]);
            if (v11) tmax1 = fmaxf(tmax1, s[nt][3]);
        }
        tmax0 = fmaxf(tmax0, __shfl_xor_sync(0xffffffffu, tmax0, 1));
        tmax0 = fmaxf(tmax0, __shfl_xor_sync(0xffffffffu, tmax0, 2));
        tmax1 = fmaxf(tmax1, __shfl_xor_sync(0xffffffffu, tmax1, 1));
        tmax1 = fmaxf(tmax1, __shfl_xor_sync(0xffffffffu, tmax1, 2));

        const float mn0 = fmaxf(mrow[0], tmax0);
        const float mn1 = fmaxf(mrow[1], tmax1);
        const float es0 = __expf(mrow[0] - mn0);
        const float es1 = __expf(mrow[1] - mn1);
        mrow[0] = mn0; mrow[1] = mn1;

        uint32_t ph01[8], ph23[8];
        float ps0 = 0.0f, ps1 = 0.0f;
#pragma unroll
        for (int nt = 0; nt < 8; nt++) {
            const int j0 = jb + nt * 8, j1 = j0 + 1;
            const bool v00 = (j0 <= ig0) && (ig0 - j0 < WIN_);
            const bool v01 = (j1 <= ig0) && (ig0 - j1 < WIN_);
            const bool v10 = (j0 <= ig1) && (ig1 - j0 < WIN_);
            const bool v11 = (j1 <= ig1) && (ig1 - j1 < WIN_);
            const float p00 = v00 ? __expf(s[nt][0] - mn0) : 0.0f;
            const float p01 = v01 ? __expf(s[nt][1] - mn0) : 0.0f;
            const float p10 = v10 ? __expf(s[nt][2] - mn1) : 0.0f;
            const float p11 = v11 ? __expf(s[nt][3] - mn1) : 0.0f;
            ps0 += p00 + p01;
            ps1 += p10 + p11;
            __half2 h01 = __floats2half2_rn(p00, p01);
            __half2 h23 = __floats2half2_rn(p10, p11);
            ph01[nt] = *reinterpret_cast<uint32_t*>(&h01);
            ph23[nt] = *reinterpret_cast<uint32_t*>(&h23);
        }
        ps0 += __shfl_xor_sync(0xffffffffu, ps0, 1);
        ps0 += __shfl_xor_sync(0xffffffffu, ps0, 2);
        ps1 += __shfl_xor_sync(0xffffffffu, ps1, 1);
        ps1 += __shfl_xor_sync(0xffffffffu, ps1, 2);
        lrow[0] = lrow[0] * es0 + ps0;
        lrow[1] = lrow[1] * es1 + ps1;
#pragma unroll
        for (int nt = 0; nt < 8; nt++) {
            o[nt][0] *= es0; o[nt][1] *= es0;
            o[nt][2] *= es1; o[nt][3] *= es1;
        }

#pragma unroll
        for (int kj = 0; kj < 4; kj++) {
            uint32_t ah[4] = {ph01[2 * kj], ph23[2 * kj], ph01[2 * kj + 1], ph23[2 * kj + 1]};
#pragma unroll
            for (int dc = 0; dc < 4; dc++) {
                uint32_t vh[4];
                const uint32_t voff =
                    (uint32_t)((kj * 16 + (lane & 15)) * SWA_LDT
                               + dc * 16 + ((lane >> 4) << 3)) * 2;
                ldm4t(vh, VH + voff);
                mma_f16(o[dc * 2],     ah, vh);
                mma_f16(o[dc * 2 + 1], ah, vh + 2);
            }
        }
    }

    const float inv0 = 1.0f / lrow[0];
    const float inv1 = 1.0f / lrow[1];
    const size_t row0 = (size_t)b * T_ + qt * 64 + w * 16 + (lane >> 2);
    const int    colb = h * HS_ + 2 * (lane & 3);
#pragma unroll
    for (int nt = 0; nt < 8; nt++) {
        *reinterpret_cast<__half2*>(yq + row0 * C_ + colb + nt * 8) =
            __floats2half2_rn(o[nt][0] * inv0, o[nt][1] * inv0);
        *reinterpret_cast<__half2*>(yq + (row0 + 8) * C_ + colb + nt * 8) =
            __floats2half2_rn(o[nt][2] * inv1, o[nt][3] * inv1);
    }
}

// ---------------------------------------------------------------------------
extern "C" void kernel_launch(void* const* d_in, const int* in_sizes, int n_in,
                              void* d_out, int out_size)
{
    const float* x      = (const float*)d_in[0];
    const float* W_attn = (const float*)d_in[1];
    const float* W_proj = (const float*)d_in[2];
    float* out = (float*)d_out;

    __half *qkv, *xq, *yq, *wa, *wp;
    cudaGetSymbolAddress((void**)&qkv, g_qkv);
    cudaGetSymbolAddress((void**)&xq,  g_xq);
    cudaGetSymbolAddress((void**)&yq,  g_yq);
    cudaGetSymbolAddress((void**)&wa,  g_wa);
    cudaGetSymbolAddress((void**)&wp,  g_wp);

    cudaFuncSetAttribute(gemm_w64, cudaFuncAttributeMaxDynamicSharedMemorySize,
                         GEMM_SMEM);
    cudaFuncSetAttribute(gemm_w32, cudaFuncAttributeMaxDynamicSharedMemorySize,
                         GEMM_SMEM);
    cudaFuncSetAttribute(swa_mma, cudaFuncAttributeMaxDynamicSharedMemorySize,
                         SWA_SMEM);

    const int M = B_ * T_;   // 4096

    // fused prep: x quant + both weight transposes, one launch
    prep_all<<<PREP_BLOCKS, 256>>>(x, W_attn, W_proj, xq, wa, wp);

    // qkv(q) = x @ W_attn  (M=4096, N=3072, K=1024): 64x64-tile variant (big grid)
    {
        dim3 g(3 * C_ / BN, M / BM);
        gemm_w64<<<g, 128, GEMM_SMEM>>>(xq, wa, qkv, M, 3 * C_, C_);
    }

    // fused SWA -> quantized y (pure 1-product)
    {
        dim3 g(T_ / 64, NH_, B_);
        swa_mma<<<g, 128, SWA_SMEM>>>(qkv, yq);
    }

    // out = y @ W_proj  (M=4096, N=1024, K=1024): 64x32-tile variant (small grid)
    {
        dim3 g(C_ / BN, M / BM);
        gemm_w32<<<g, 256, GEMM_SMEM>>>(yq, wp, out, M, C_, C_);
    }
}